// round 11
// baseline (speedup 1.0000x reference)
#include <cuda_runtime.h>
#include <cuda_fp16.h>
#include <stdint.h>
#include <math.h>

#define NEGF (-1e9f)
typedef unsigned short ushort_t;

// ---------- scratch ----------
__device__ float    g_x [4194304];
__device__ float    g_t [4194304];
__device__ float    g_s [16777216];
__device__ float    g_vt[16777216];
__device__ ushort_t g_xh[4194304],  g_xl[4194304];
__device__ unsigned char g_x8h[4194304], g_x8l[4194304];
__device__ ushort_t g_qh[4194304],  g_ql[4194304];
__device__ ushort_t g_kh[4194304],  g_kl[4194304];
__device__ ushort_t g_vh[4194304],  g_vl[4194304];
__device__ ushort_t g_oh[4194304],  g_ol[4194304];
__device__ ushort_t g_sh[16777216], g_sl[16777216];
__device__ ushort_t g_hh[16777216];
__device__ unsigned char g_h8h[16777216], g_h8l[16777216];
__device__ ushort_t g_w1h[9437184];                        // [L][9][1024][256] fp16 hi
__device__ unsigned char g_w18h[9437184], g_w18l[9437184]; // fp8 planes
__device__ ushort_t g_w2h[9437184];                        // [L][9][256][1024]
__device__ unsigned char g_w28h[9437184], g_w28l[9437184];
__device__ unsigned g_wqh[131072], g_wql[131072], g_wkh[131072], g_wkl[131072];
__device__ unsigned g_wvh[131072], g_wvl[131072], g_woh[131072], g_wol[131072];
__device__ unsigned g_dir[524288];
__device__ int      g_idx[32768];

// ---------- fp16 split helpers ----------
__device__ __forceinline__ void split1(float v, ushort_t& h, ushort_t& l) {
    __half hh = __float2half_rn(v);
    __half ll = __float2half_rn(v - __half2float(hh));
    h = __half_as_ushort(hh); l = __half_as_ushort(ll);
}
__device__ __forceinline__ void wsplit2(ushort_t* Ph, ushort_t* Pl, size_t off,
                                        float v0, float v1) {
    ushort_t h0, l0, h1, l1;
    split1(v0, h0, l0); split1(v1, h1, l1);
    *(unsigned*)&Ph[off] = (unsigned)h0 | ((unsigned)h1 << 16);
    *(unsigned*)&Pl[off] = (unsigned)l0 | ((unsigned)l1 << 16);
}
// pack two floats into two e4m3 bytes: low byte = b0, high byte = b1
__device__ __forceinline__ ushort_t fp8x2(float b0, float b1) {
    ushort_t r;
    asm("cvt.rn.satfinite.e4m3x2.f32 %0, %2, %1;" : "=h"(r) : "f"(b0), "f"(b1));
    return r;
}
__device__ __forceinline__ unsigned smem_u32(const void* p) {
    unsigned a;
    asm("{ .reg .u64 t; cvta.to.shared.u64 t, %1; cvt.u32.u64 %0, t; }" : "=r"(a) : "l"(p));
    return a;
}

// ---------- mma cores ----------
__device__ __forceinline__ void mma16(float c[4], const unsigned a[4], const unsigned b[2]) {
    asm volatile(
        "mma.sync.aligned.m16n8k16.row.col.f32.f16.f16.f32 "
        "{%0,%1,%2,%3},{%4,%5,%6,%7},{%8,%9},{%0,%1,%2,%3};\n"
        : "+f"(c[0]), "+f"(c[1]), "+f"(c[2]), "+f"(c[3])
        : "r"(a[0]), "r"(a[1]), "r"(a[2]), "r"(a[3]), "r"(b[0]), "r"(b[1]));
}
__device__ __forceinline__ void mmaf8(float c[4], const unsigned a[4], const unsigned b[2]) {
    asm volatile(
        "mma.sync.aligned.m16n8k32.row.col.f32.e4m3.e4m3.f32 "
        "{%0,%1,%2,%3},{%4,%5,%6,%7},{%8,%9},{%0,%1,%2,%3};\n"
        : "+f"(c[0]), "+f"(c[1]), "+f"(c[2]), "+f"(c[3])
        : "r"(a[0]), "r"(a[1]), "r"(a[2]), "r"(a[3]), "r"(b[0]), "r"(b[1]));
}

#define CPA(d, s, n) \
    asm volatile("cp.async.cg.shared.global [%0],[%1],16,%2;" :: "r"(d), "l"(s), "r"(n) : "memory")

// ================= conv as implicit im2col GEMM (fp16 hi·hi + fp8 cross) =================
// Block 128x128, K-chunk 32. smem per buffer: As16 10240 | As8h 6144 | As8l 6144 |
// Bs16 10240 | Bs8h 6144 | Bs8l 6144 = 45056 bytes; two buffers = 90112.
__global__ void __launch_bounds__(256)
k_conv(const ushort_t* __restrict__ Ah, const unsigned char* __restrict__ A8h,
       const unsigned char* __restrict__ A8l,
       const ushort_t* __restrict__ Wh, const unsigned char* __restrict__ W8h,
       const unsigned char* __restrict__ W8l,
       const float* __restrict__ bias, int Cin, int nsh, int relu_split,
       ushort_t* __restrict__ OHh, unsigned char* __restrict__ OH8h,
       unsigned char* __restrict__ OH8l, float* __restrict__ Of, int outld) {
    extern __shared__ __align__(16) char smem[];
    unsigned sbase = smem_u32(smem);
    int tid = threadIdx.x, wid = tid >> 5, lane = tid & 31;
    int wm = wid & 3, wn = wid >> 2, g = lane >> 2, tig = lane & 3;
    int n0 = blockIdx.x * 128, m0 = blockIdx.y * 128;
    int Coutv = gridDim.x * 128;
    int bbase = m0 & ~511, tb = m0 & 511;
    int ncmask = (1 << nsh) - 1;
    int NIT = 9 << nsh;
    size_t wdk_str = (size_t)Coutv * Cin;
    int lrow = tid >> 1, lhalf = tid & 1;
    float acc[16][4] = {}, accX[16][4] = {};

#define ISSUE(itv, bo) do {                                                    \
        int dk_ = (itv) >> nsh; int kc_ = ((itv) & ncmask) << 5;               \
        int t_ = tb + lrow + dk_ - 4;                                          \
        unsigned okn = ((unsigned)t_ < 512u) ? 16u : 0u;                       \
        size_t arow_ = (size_t)(bbase + t_) * Cin + kc_ + lhalf * 16;          \
        unsigned d_ = sbase + (bo) + (lrow * 20 + lhalf * 8) * 4;              \
        CPA(d_, Ah + arow_, okn); CPA(d_ + 16, Ah + arow_ + 8, okn);           \
        CPA(sbase + (bo) + 10240 + lrow * 48 + lhalf * 16, A8h + arow_, okn);  \
        CPA(sbase + (bo) + 16384 + lrow * 48 + lhalf * 16, A8l + arow_, okn);  \
        size_t wrow_ = (size_t)dk_ * wdk_str + (size_t)(n0 + lrow) * Cin + kc_ + lhalf * 16; \
        unsigned db_ = sbase + (bo) + 22528 + (lrow * 20 + lhalf * 8) * 4;     \
        CPA(db_, Wh + wrow_, 16u); CPA(db_ + 16, Wh + wrow_ + 8, 16u);         \
        CPA(sbase + (bo) + 32768 + lrow * 48 + lhalf * 16, W8h + wrow_, 16u);  \
        CPA(sbase + (bo) + 38912 + lrow * 48 + lhalf * 16, W8l + wrow_, 16u);  \
    } while (0)

    ISSUE(0, 0);
    asm volatile("cp.async.commit_group;" ::: "memory");
    for (int it = 0; it < NIT; ++it) {
        int cbo = (it & 1) * 45056, nbo = 45056 - cbo;
        if (it + 1 < NIT) {
            ISSUE(it + 1, nbo);
            asm volatile("cp.async.commit_group;" ::: "memory");
            asm volatile("cp.async.wait_group 1;" ::: "memory");
        } else {
            asm volatile("cp.async.wait_group 0;" ::: "memory");
        }
        __syncthreads();
        const unsigned* As16 = (const unsigned*)(smem + cbo);
        const unsigned* As8hp = (const unsigned*)(smem + cbo + 10240);
        const unsigned* As8lp = (const unsigned*)(smem + cbo + 16384);
        const unsigned* Bs16 = (const unsigned*)(smem + cbo + 22528);
        const unsigned* Bs8hp = (const unsigned*)(smem + cbo + 32768);
        const unsigned* Bs8lp = (const unsigned*)(smem + cbo + 38912);
        unsigned aH0[2][4], aH1[2][4], a8h[2][4], a8l[2][4];
#pragma unroll
        for (int i = 0; i < 2; ++i) {
            int r = wm * 32 + i * 16 + g;
            aH0[i][0] = As16[r * 20 + tig];      aH0[i][1] = As16[(r + 8) * 20 + tig];
            aH0[i][2] = As16[r * 20 + tig + 4];  aH0[i][3] = As16[(r + 8) * 20 + tig + 4];
            aH1[i][0] = As16[r * 20 + tig + 8];  aH1[i][1] = As16[(r + 8) * 20 + tig + 8];
            aH1[i][2] = As16[r * 20 + tig + 12]; aH1[i][3] = As16[(r + 8) * 20 + tig + 12];
            a8h[i][0] = As8hp[r * 12 + tig];     a8h[i][1] = As8hp[(r + 8) * 12 + tig];
            a8h[i][2] = As8hp[r * 12 + tig + 4]; a8h[i][3] = As8hp[(r + 8) * 12 + tig + 4];
            a8l[i][0] = As8lp[r * 12 + tig];     a8l[i][1] = As8lp[(r + 8) * 12 + tig];
            a8l[i][2] = As8lp[r * 12 + tig + 4]; a8l[i][3] = As8lp[(r + 8) * 12 + tig + 4];
        }
#pragma unroll
        for (int j = 0; j < 8; ++j) {
            int cc = wn * 64 + j * 8 + g;
            unsigned bh0[2] = {Bs16[cc * 20 + tig], Bs16[cc * 20 + tig + 4]};
            unsigned bh1[2] = {Bs16[cc * 20 + tig + 8], Bs16[cc * 20 + tig + 12]};
            unsigned b8h2[2] = {Bs8hp[cc * 12 + tig], Bs8hp[cc * 12 + tig + 4]};
            unsigned b8l2[2] = {Bs8lp[cc * 12 + tig], Bs8lp[cc * 12 + tig + 4]};
#pragma unroll
            for (int i = 0; i < 2; ++i) {
                mma16(acc[i * 8 + j], aH0[i], bh0);
                mma16(acc[i * 8 + j], aH1[i], bh1);
                mmaf8(accX[i * 8 + j], a8l[i], b8h2);
                mmaf8(accX[i * 8 + j], a8h[i], b8l2);
            }
        }
        __syncthreads();
    }
#undef ISSUE
    const float SX = 1.0f / 65536.0f;
#pragma unroll
    for (int i = 0; i < 2; ++i)
#pragma unroll
        for (int j = 0; j < 8; ++j) {
            int m = m0 + wm * 32 + i * 16 + g;
            int n = n0 + wn * 64 + j * 8 + 2 * tig;
            float* a = acc[i * 8 + j];
            float* x = accX[i * 8 + j];
            float b0 = bias[n], b1 = bias[n + 1];
            float v0 = a[0] + x[0] * SX + b0, v1 = a[1] + x[1] * SX + b1;
            float v2 = a[2] + x[2] * SX + b0, v3 = a[3] + x[3] * SX + b1;
            size_t o0 = (size_t)m * outld + n, o1 = (size_t)(m + 8) * outld + n;
            if (relu_split) {
                v0 = fmaxf(v0, 0.f); v1 = fmaxf(v1, 0.f);
                v2 = fmaxf(v2, 0.f); v3 = fmaxf(v3, 0.f);
                __half h0 = __float2half_rn(v0), h1 = __float2half_rn(v1);
                __half h2 = __float2half_rn(v2), h3 = __float2half_rn(v3);
                *(unsigned*)&OHh[o0] = (unsigned)__half_as_ushort(h0) | ((unsigned)__half_as_ushort(h1) << 16);
                *(unsigned*)&OHh[o1] = (unsigned)__half_as_ushort(h2) | ((unsigned)__half_as_ushort(h3) << 16);
                *(ushort_t*)&OH8h[o0] = fp8x2(v0, v1);
                *(ushort_t*)&OH8h[o1] = fp8x2(v2, v3);
                *(ushort_t*)&OH8l[o0] = fp8x2((v0 - __half2float(h0)) * 2048.f,
                                              (v1 - __half2float(h1)) * 2048.f);
                *(ushort_t*)&OH8l[o1] = fp8x2((v2 - __half2float(h2)) * 2048.f,
                                              (v3 - __half2float(h3)) * 2048.f);
            } else {
                *(float2*)&Of[o0] = make_float2(v0, v1);
                *(float2*)&Of[o1] = make_float2(v2, v3);
            }
        }
}

// conv weight prep: src[l][R][C][9] fp32 -> [l][9][R][C]: fp16 hi + fp8(v*32) + fp8(lo*65536)
__global__ void k_wprep(const float* __restrict__ src, ushort_t* __restrict__ Wh,
                        unsigned char* __restrict__ W8h, unsigned char* __restrict__ W8l,
                        int R, int C) {
    size_t idx = ((size_t)blockIdx.x * 256 + threadIdx.x) * 2;
    int c = (int)(idx % C);
    size_t t1 = idx / C;
    int r = (int)(t1 % R);
    size_t t2 = t1 / R;
    int dk = (int)(t2 % 9);
    int l = (int)(t2 / 9);
    size_t sb = (((size_t)l * R + r) * C + c) * 9 + dk;
    float v0 = src[sb], v1 = src[sb + 9];
    __half h0 = __float2half_rn(v0), h1 = __float2half_rn(v1);
    *(unsigned*)&Wh[idx] = (unsigned)__half_as_ushort(h0) | ((unsigned)__half_as_ushort(h1) << 16);
    *(ushort_t*)&W8h[idx] = fp8x2(v0 * 32.f, v1 * 32.f);
    *(ushort_t*)&W8l[idx] = fp8x2((v0 - __half2float(h0)) * 65536.f,
                                  (v1 - __half2float(h1)) * 65536.f);
}

// ================= mma.sync machinery (attention; unchanged) =================
__device__ __forceinline__ void mma_tile16(const unsigned* AsH, const unsigned* AsL,
                                           const unsigned* BsH, const unsigned* BsL,
                                           int wm, int wn, int g, int tig,
                                           float (*acc)[4]) {
    unsigned aH[2][4], aL[2][4];
#pragma unroll
    for (int i = 0; i < 2; ++i) {
        int r = (wm * 32 + i * 16 + g) * 12 + tig;
        aH[i][0] = AsH[r]; aH[i][1] = AsH[r + 96]; aH[i][2] = AsH[r + 4]; aH[i][3] = AsH[r + 100];
        aL[i][0] = AsL[r]; aL[i][1] = AsL[r + 96]; aL[i][2] = AsL[r + 4]; aL[i][3] = AsL[r + 100];
    }
#pragma unroll
    for (int j = 0; j < 8; ++j) {
        int nb = wn * 64 + j * 8 + g;
        unsigned bH[2] = {BsH[tig * 136 + nb], BsH[(tig + 4) * 136 + nb]};
        unsigned bL[2] = {BsL[tig * 136 + nb], BsL[(tig + 4) * 136 + nb]};
#pragma unroll
        for (int i = 0; i < 2; ++i) {
            mma16(acc[i * 8 + j], aH[i], bH);
            mma16(acc[i * 8 + j], aL[i], bH);
            mma16(acc[i * 8 + j], aH[i], bL);
        }
    }
}

__global__ void __launch_bounds__(256, 2)
k_gemm_bias(const ushort_t* __restrict__ Ah, const ushort_t* __restrict__ Al,
            const unsigned* __restrict__ Bph, const unsigned* __restrict__ Bpl,
            const float* __restrict__ bias, float* __restrict__ Cf,
            ushort_t* __restrict__ Ch, ushort_t* __restrict__ Cl) {
    __shared__ unsigned AsH[1536], AsL[1536], BsH[1088], BsL[1088];
    int tid = threadIdx.x, w = tid >> 5, lane = tid & 31;
    int wm = w & 3, wn = w >> 2, g = lane >> 2, tig = lane & 3;
    int n0 = blockIdx.x * 128, m0 = blockIdx.y * 128;
    int arow = tid >> 1, apart = tid & 1;
    int bp = tid >> 5, bc = lane * 4;
    float acc[16][4] = {};
    for (int k0 = 0; k0 < 256; k0 += 16) {
        size_t aoff = (size_t)(m0 + arow) * 256 + k0 + apart * 8;
        uint4 ah = *(const uint4*)(Ah + aoff);
        uint4 al = *(const uint4*)(Al + aoff);
        size_t boff = (size_t)(k0 / 2 + bp) * 256 + n0 + bc;
        uint4 bh = *(const uint4*)(Bph + boff);
        uint4 bl = *(const uint4*)(Bpl + boff);
        __syncthreads();
        *(uint4*)&AsH[arow * 12 + apart * 4] = ah;
        *(uint4*)&AsL[arow * 12 + apart * 4] = al;
        *(uint4*)&BsH[bp * 136 + bc] = bh;
        *(uint4*)&BsL[bp * 136 + bc] = bl;
        __syncthreads();
        mma_tile16(AsH, AsL, BsH, BsL, wm, wn, g, tig, acc);
    }
#pragma unroll
    for (int i = 0; i < 2; ++i)
#pragma unroll
        for (int j = 0; j < 8; ++j) {
            int m = m0 + wm * 32 + i * 16 + g;
            int n = n0 + wn * 64 + j * 8 + 2 * tig;
            float b0 = bias[n], b1 = bias[n + 1];
            float* a = acc[i * 8 + j];
            float v0 = a[0] + b0, v1 = a[1] + b1, v2 = a[2] + b0, v3 = a[3] + b1;
            if (Cf) {
                *(float2*)&Cf[(size_t)m * 256 + n] = make_float2(v0, v1);
                *(float2*)&Cf[(size_t)(m + 8) * 256 + n] = make_float2(v2, v3);
            }
            if (Ch) {
                wsplit2(Ch, Cl, (size_t)m * 256 + n, v0, v1);
                wsplit2(Ch, Cl, (size_t)(m + 8) * 256 + n, v2, v3);
            }
        }
}

__global__ void __launch_bounds__(256, 2)
k_scores(const ushort_t* __restrict__ Qh, const ushort_t* __restrict__ Ql,
         const ushort_t* __restrict__ Kh, const ushort_t* __restrict__ Kl,
         float* __restrict__ S, const int* __restrict__ srcL) {
    __shared__ unsigned AsH[1536], AsL[1536], BsH[1088], BsL[1088];
    int tid = threadIdx.x, w = tid >> 5, lane = tid & 31;
    int wm = w & 3, wn = w >> 2, g = lane >> 2, tig = lane & 3;
    int n0 = blockIdx.x * 128, m0 = blockIdx.y * 128, bh = blockIdx.z;
    int b = bh >> 1, h = bh & 1;
    int arow = tid >> 1, apart = tid & 1;
    int btn = tid & 127, bpb = (tid >> 7) * 4;
    float acc[16][4] = {};
    for (int k0 = 0; k0 < 128; k0 += 16) {
        size_t aoff = (size_t)(b * 512 + m0 + arow) * 256 + h * 128 + k0 + apart * 8;
        uint4 ah = *(const uint4*)(Qh + aoff);
        uint4 al = *(const uint4*)(Ql + aoff);
        size_t koff = (size_t)(b * 512 + n0 + btn) * 256 + h * 128 + k0 + bpb * 2;
        uint4 bh4 = *(const uint4*)(Kh + koff);
        uint4 bl4 = *(const uint4*)(Kl + koff);
        __syncthreads();
        *(uint4*)&AsH[arow * 12 + apart * 4] = ah;
        *(uint4*)&AsL[arow * 12 + apart * 4] = al;
        BsH[(bpb + 0) * 136 + btn] = bh4.x; BsH[(bpb + 1) * 136 + btn] = bh4.y;
        BsH[(bpb + 2) * 136 + btn] = bh4.z; BsH[(bpb + 3) * 136 + btn] = bh4.w;
        BsL[(bpb + 0) * 136 + btn] = bl4.x; BsL[(bpb + 1) * 136 + btn] = bl4.y;
        BsL[(bpb + 2) * 136 + btn] = bl4.z; BsL[(bpb + 3) * 136 + btn] = bl4.w;
        __syncthreads();
        mma_tile16(AsH, AsL, BsH, BsL, wm, wn, g, tig, acc);
    }
    int sl = srcL[b];
    const float scale = 0.08838834764831845f;
#pragma unroll
    for (int i = 0; i < 2; ++i)
#pragma unroll
        for (int j = 0; j < 8; ++j) {
            int m = m0 + wm * 32 + i * 16 + g;
            int n = n0 + wn * 64 + j * 8 + 2 * tig;
            float* a = acc[i * 8 + j];
            bool p0 = (n >= sl), p1 = (n + 1 >= sl);
            float2 r0 = {p0 ? NEGF : a[0] * scale, p1 ? NEGF : a[1] * scale};
            float2 r1 = {p0 ? NEGF : a[2] * scale, p1 ? NEGF : a[3] * scale};
            *(float2*)&S[((size_t)bh * 512 + m) * 512 + n] = r0;
            *(float2*)&S[((size_t)bh * 512 + m + 8) * 512 + n] = r1;
        }
}

__global__ void __launch_bounds__(256, 2)
k_attnout(const ushort_t* __restrict__ Sh, const ushort_t* __restrict__ Sl,
          const ushort_t* __restrict__ Vh, const ushort_t* __restrict__ Vl,
          ushort_t* __restrict__ Oh, ushort_t* __restrict__ Ol) {
    __shared__ unsigned AsH[1536], AsL[1536], BsH[1088], BsL[1088];
    int tid = threadIdx.x, w = tid >> 5, lane = tid & 31;
    int wm = w & 3, wn = w >> 2, g = lane >> 2, tig = lane & 3;
    int m0 = blockIdx.y * 128, bh = blockIdx.z;
    int b = bh >> 1, h = bh & 1;
    int arow = tid >> 1, apart = tid & 1;
    int bp = tid >> 5, bc = lane * 4;
    float acc[16][4] = {};
    for (int k0 = 0; k0 < 512; k0 += 16) {
        size_t aoff = ((size_t)bh * 512 + m0 + arow) * 512 + k0 + apart * 8;
        uint4 ah = *(const uint4*)(Sh + aoff);
        uint4 al = *(const uint4*)(Sl + aoff);
        const ushort_t* r0h = Vh + (size_t)(b * 512 + k0 + 2 * bp) * 256 + h * 128 + bc;
        uint2 uah = *(const uint2*)r0h, ubh = *(const uint2*)(r0h + 256);
        const ushort_t* r0l = Vl + (size_t)(b * 512 + k0 + 2 * bp) * 256 + h * 128 + bc;
        uint2 ual = *(const uint2*)r0l, ubl = *(const uint2*)(r0l + 256);
        __syncthreads();
        *(uint4*)&AsH[arow * 12 + apart * 4] = ah;
        *(uint4*)&AsL[arow * 12 + apart * 4] = al;
        BsH[bp * 136 + bc + 0] = (uah.x & 0xFFFFu) | (ubh.x << 16);
        BsH[bp * 136 + bc + 1] = (uah.x >> 16) | (ubh.x & 0xFFFF0000u);
        BsH[bp * 136 + bc + 2] = (uah.y & 0xFFFFu) | (ubh.y << 16);
        BsH[bp * 136 + bc + 3] = (uah.y >> 16) | (ubh.y & 0xFFFF0000u);
        BsL[bp * 136 + bc + 0] = (ual.x & 0xFFFFu) | (ubl.x << 16);
        BsL[bp * 136 + bc + 1] = (ual.x >> 16) | (ubl.x & 0xFFFF0000u);
        BsL[bp * 136 + bc + 2] = (ual.y & 0xFFFFu) | (ubl.y << 16);
        BsL[bp * 136 + bc + 3] = (ual.y >> 16) | (ubl.y & 0xFFFF0000u);
        __syncthreads();
        mma_tile16(AsH, AsL, BsH, BsL, wm, wn, g, tig, acc);
    }
#pragma unroll
    for (int i = 0; i < 2; ++i)
#pragma unroll
        for (int j = 0; j < 8; ++j) {
            int m = m0 + wm * 32 + i * 16 + g;
            int n = h * 128 + wn * 64 + j * 8 + 2 * tig;
            float* a = acc[i * 8 + j];
            wsplit2(Oh, Ol, (size_t)(b * 512 + m) * 256 + n, a[0], a[1]);
            wsplit2(Oh, Ol, (size_t)(b * 512 + m + 8) * 256 + n, a[2], a[3]);
        }
}

// ================= producers / elementwise =================
__global__ void k_embed(const int* __restrict__ tok, const float* __restrict__ emb,
                        const float* __restrict__ pos, float* __restrict__ x,
                        ushort_t* __restrict__ xh, ushort_t* __restrict__ xl) {
    int row = blockIdx.x, d = threadIdx.x;
    int t = row & 511;
    int id = tok[row];
    size_t off = (size_t)row * 256 + d;
    float v = emb[(size_t)id * 256 + d] + pos[(size_t)t * 256 + d];
    x[off] = v;
    ushort_t h, l; split1(v, h, l);
    xh[off] = h; xl[off] = l;
}

__global__ void k_softmax(const float* __restrict__ S, ushort_t* __restrict__ Sh,
                          ushort_t* __restrict__ Sl) {
    __shared__ float red[4];
    size_t row = blockIdx.x;
    float4 v = ((const float4*)(S + row * 512))[threadIdx.x];
    int lane = threadIdx.x & 31, wid = threadIdx.x >> 5;
    float m = fmaxf(fmaxf(v.x, v.y), fmaxf(v.z, v.w));
#pragma unroll
    for (int o = 16; o > 0; o >>= 1) m = fmaxf(m, __shfl_xor_sync(~0u, m, o));
    if (lane == 0) red[wid] = m;
    __syncthreads();
    m = fmaxf(fmaxf(red[0], red[1]), fmaxf(red[2], red[3]));
    __syncthreads();
    v.x = expf(v.x - m); v.y = expf(v.y - m); v.z = expf(v.z - m); v.w = expf(v.w - m);
    float s = v.x + v.y + v.z + v.w;
#pragma unroll
    for (int o = 16; o > 0; o >>= 1) s += __shfl_xor_sync(~0u, s, o);
    if (lane == 0) red[wid] = s;
    __syncthreads();
    s = red[0] + red[1] + red[2] + red[3];
    float inv = 1.0f / s;
    size_t off = row * 512 + threadIdx.x * 4;
    wsplit2(Sh, Sl, off, v.x * inv, v.y * inv);
    wsplit2(Sh, Sl, off + 2, v.z * inv, v.w * inv);
}

__global__ void k_lnres(const float* __restrict__ t, const float* __restrict__ res,
                        const float* __restrict__ gam, const float* __restrict__ bet,
                        const int* __restrict__ srcL, float* __restrict__ out,
                        ushort_t* __restrict__ oh, ushort_t* __restrict__ ol,
                        unsigned char* __restrict__ o8h, unsigned char* __restrict__ o8l) {
    __shared__ float red[8];
    int row = blockIdx.x, d = threadIdx.x;
    size_t off = (size_t)row * 256 + d;
    float val = t[off] + res[off];
    float s = val;
#pragma unroll
    for (int o = 16; o > 0; o >>= 1) s += __shfl_xor_sync(~0u, s, o);
    if ((d & 31) == 0) red[d >> 5] = s;
    __syncthreads();
    float tot = 0.f;
#pragma unroll
    for (int i = 0; i < 8; ++i) tot += red[i];
    float mean = tot * (1.0f / 256.0f);
    float dv = val - mean;
    __syncthreads();
    float s2 = dv * dv;
#pragma unroll
    for (int o = 16; o > 0; o >>= 1) s2 += __shfl_xor_sync(~0u, s2, o);
    if ((d & 31) == 0) red[d >> 5] = s2;
    __syncthreads();
    float tot2 = 0.f;
#pragma unroll
    for (int i = 0; i < 8; ++i) tot2 += red[i];
    float o = dv * rsqrtf(tot2 * (1.0f / 256.0f) + 1e-5f) * gam[d] + bet[d];
    if ((row & 511) >= srcL[row >> 9]) o = 0.f;
    out[off] = o;
    __half hh = __float2half_rn(o);
    float lo = o - __half2float(hh);
    oh[off] = __half_as_ushort(hh);
    ol[off] = __half_as_ushort(__float2half_rn(lo));
    o8h[off] = (unsigned char)(fp8x2(o, 0.f) & 0xFF);
    o8l[off] = (unsigned char)(fp8x2(lo * 2048.f, 0.f) & 0xFF);
}

__global__ void k_packsplit(const float* __restrict__ src, unsigned* __restrict__ Uh,
                            unsigned* __restrict__ Ul, int nshift) {
    size_t idx = (size_t)blockIdx.x * 256 + threadIdx.x;
    size_t kp = idx >> nshift;
    int n = (int)(idx & ((1u << nshift) - 1));
    size_t N = (size_t)1 << nshift;
    float a = src[(2 * kp) * N + n], b = src[(2 * kp + 1) * N + n];
    ushort_t ha, la, hb, lb;
    split1(a, ha, la); split1(b, hb, lb);
    Uh[idx] = (unsigned)ha | ((unsigned)hb << 16);
    Ul[idx] = (unsigned)la | ((unsigned)lb << 16);
}

// ================= MAS + expand =================
__global__ void k_vtrans(const float* __restrict__ val, float* __restrict__ vt,
                         const int* __restrict__ srcL, const int* __restrict__ melL) {
    __shared__ float s[32][33];
    int b = blockIdx.z;
    int x0 = blockIdx.x * 32, y0 = blockIdx.y * 32;
    int sl = srcL[b], ml = melL[b];
    const float* vp = val + (size_t)b * 512 * 1024;
    float* op = vt + (size_t)b * 1024 * 512;
    for (int i = threadIdx.y; i < 32; i += 8) {
        int x = x0 + i, y = y0 + threadIdx.x;
        float v = vp[(size_t)x * 1024 + y];
        s[i][threadIdx.x] = (x < sl && y < ml) ? v : 0.f;
    }
    __syncthreads();
    for (int j = threadIdx.y; j < 32; j += 8)
        op[(size_t)(y0 + j) * 512 + x0 + threadIdx.x] = s[threadIdx.x][j];
}

__global__ void k_masdp(const float* __restrict__ vt, const int* __restrict__ srcL,
                        const int* __restrict__ melL, unsigned* __restrict__ dir) {
    __shared__ float sv[512];
    int b = blockIdx.x, x = threadIdx.x;
    int sl = srcL[b], ml = melL[b];
    int lane = x & 31, wid = x >> 5;
    float v = 0.f;
    for (int j = 0; j < 1024; ++j) {
        sv[x] = v;
        __syncthreads();
        float v0 = x ? sv[x - 1] : NEGF;
        float val = vt[((size_t)b * 1024 + j) * 512 + x];
        bool d = (v >= v0);
        float vmax = d ? v : v0;
        float vnew = (x <= j) ? (vmax + val) : NEGF;
        bool dm = (x < sl && j < ml) ? d : true;
        unsigned bal = __ballot_sync(0xffffffffu, dm);
        if (lane == 0) dir[((size_t)b * 1024 + j) * 16 + wid] = bal;
        v = vnew;
        __syncthreads();
    }
}

__global__ void k_masbt(const unsigned* __restrict__ dir, const int* __restrict__ srcL,
                        int* __restrict__ idxout) {
    int b = threadIdx.x;
    if (b >= 32) return;
    int idx = srcL[b] - 1;
    for (int y = 1023; y >= 0; --y) {
        idxout[b * 1024 + y] = idx;
        unsigned w = dir[((size_t)b * 1024 + y) * 16 + (idx >> 5)];
        idx += (int)((w >> (idx & 31)) & 1u) - 1;
    }
}

__global__ void k_expand(const float* __restrict__ X, const int* __restrict__ idx,
                         const int* __restrict__ srcL, const int* __restrict__ melL,
                         float* __restrict__ out) {
    int row = blockIdx.x;
    int b = row >> 10, y = row & 1023;
    int d = threadIdx.x;
    float o = 0.f;
    if (y < melL[b]) {
        int ix = idx[row];
        if (ix >= 0 && ix < srcL[b])
            o = X[((size_t)(b << 9) + ix) * 256 + d];
    }
    out[(size_t)row * 256 + d] = o;
}

// ================= launch =================
extern "C" void kernel_launch(void* const* d_in, const int* in_sizes, int n_in,
                              void* d_out, int out_size) {
    const int* tokens = (const int*)d_in[0];
    const int* srcL   = (const int*)d_in[1];
    const int* melL   = (const int*)d_in[2];
    const float* value = (const float*)d_in[3];
    const float* embed = (const float*)d_in[4];
    const float* pos   = (const float*)d_in[5];
    const float* wq = (const float*)d_in[6];  const float* bq = (const float*)d_in[7];
    const float* wk = (const float*)d_in[8];  const float* bk = (const float*)d_in[9];
    const float* wv = (const float*)d_in[10]; const float* bv = (const float*)d_in[11];
    const float* wo = (const float*)d_in[12]; const float* bo = (const float*)d_in[13];
    const float* ln1g = (const float*)d_in[14]; const float* ln1b = (const float*)d_in[15];
    const float* c1w = (const float*)d_in[16]; const float* c1b = (const float*)d_in[17];
    const float* c2w = (const float*)d_in[18]; const float* c2b = (const float*)d_in[19];
    const float* ln2g = (const float*)d_in[20]; const float* ln2b = (const float*)d_in[21];
    float* out = (float*)d_out;

    float *px, *pt, *ps, *pvt;
    ushort_t *pxh, *pxl, *pqh, *pql, *pkh, *pkl, *pvh, *pvl, *poh, *pol;
    ushort_t *psh, *psl, *phh, *pw1h, *pw2h;
    unsigned char *px8h, *px8l, *ph8h, *ph8l;
    unsigned char *pw18h, *pw18l, *pw28h, *pw28l;
    unsigned *pwqh, *pwql, *pwkh, *pwkl, *pwvh, *pwvl, *pwoh, *pwol;
    unsigned* pdir; int* pidx;
    cudaGetSymbolAddress((void**)&px, g_x);   cudaGetSymbolAddress((void**)&pt, g_t);
    cudaGetSymbolAddress((void**)&ps, g_s);   cudaGetSymbolAddress((void**)&pvt, g_vt);
    cudaGetSymbolAddress((void**)&pxh, g_xh); cudaGetSymbolAddress((void**)&pxl, g_xl);
    cudaGetSymbolAddress((void**)&px8h, g_x8h); cudaGetSymbolAddress((void**)&px8l, g_x8l);
    cudaGetSymbolAddress((void**)&pqh, g_qh); cudaGetSymbolAddress((void**)&pql, g_ql);
    cudaGetSymbolAddress((void**)&pkh, g_kh); cudaGetSymbolAddress((void**)&pkl, g_kl);
    cudaGetSymbolAddress((void**)&pvh, g_vh); cudaGetSymbolAddress((void**)&pvl, g_vl);
    cudaGetSymbolAddress((void**)&poh, g_oh); cudaGetSymbolAddress((void**)&pol, g_ol);
    cudaGetSymbolAddress((void**)&psh, g_sh); cudaGetSymbolAddress((void**)&psl, g_sl);
    cudaGetSymbolAddress((void**)&phh, g_hh);
    cudaGetSymbolAddress((void**)&ph8h, g_h8h); cudaGetSymbolAddress((void**)&ph8l, g_h8l);
    cudaGetSymbolAddress((void**)&pw1h, g_w1h);
    cudaGetSymbolAddress((void**)&pw18h, g_w18h); cudaGetSymbolAddress((void**)&pw18l, g_w18l);
    cudaGetSymbolAddress((void**)&pw2h, g_w2h);
    cudaGetSymbolAddress((void**)&pw28h, g_w28h); cudaGetSymbolAddress((void**)&pw28l, g_w28l);
    cudaGetSymbolAddress((void**)&pwqh, g_wqh); cudaGetSymbolAddress((void**)&pwql, g_wql);
    cudaGetSymbolAddress((void**)&pwkh, g_wkh); cudaGetSymbolAddress((void**)&pwkl, g_wkl);
    cudaGetSymbolAddress((void**)&pwvh, g_wvh); cudaGetSymbolAddress((void**)&pwvl, g_wvl);
    cudaGetSymbolAddress((void**)&pwoh, g_woh); cudaGetSymbolAddress((void**)&pwol, g_wol);
    cudaGetSymbolAddress((void**)&pdir, g_dir); cudaGetSymbolAddress((void**)&pidx, g_idx);

    const int SMEMC = 90112;
    cudaFuncSetAttribute(k_conv, cudaFuncAttributeMaxDynamicSharedMemorySize, SMEMC);

    dim3 blk256(256);
    // weight prep
    k_wprep<<<18432, blk256>>>(c1w, pw1h, pw18h, pw18l, 1024, 256);
    k_wprep<<<18432, blk256>>>(c2w, pw2h, pw28h, pw28l, 256, 1024);
    k_packsplit<<<512, blk256>>>(wq, pwqh, pwql, 8);
    k_packsplit<<<512, blk256>>>(wk, pwkh, pwkl, 8);
    k_packsplit<<<512, blk256>>>(wv, pwvh, pwvl, 8);
    k_packsplit<<<512, blk256>>>(wo, pwoh, pwol, 8);
    // inputs
    k_vtrans<<<dim3(16, 32, 32), dim3(32, 8)>>>(value, pvt, srcL, melL);
    k_embed<<<16384, blk256>>>(tokens, embed, pos, px, pxh, pxl);

    for (int l = 0; l < 4; ++l) {
        const unsigned *wqh_l = pwqh + l * 32768, *wql_l = pwql + l * 32768;
        const unsigned *wkh_l = pwkh + l * 32768, *wkl_l = pwkl + l * 32768;
        const unsigned *wvh_l = pwvh + l * 32768, *wvl_l = pwvl + l * 32768;
        const unsigned *woh_l = pwoh + l * 32768, *wol_l = pwol + l * 32768;

        k_gemm_bias<<<dim3(2, 128), blk256>>>(pxh, pxl, wqh_l, wql_l, bq + l * 256, nullptr, pqh, pql);
        k_gemm_bias<<<dim3(2, 128), blk256>>>(pxh, pxl, wkh_l, wkl_l, bk + l * 256, nullptr, pkh, pkl);
        k_gemm_bias<<<dim3(2, 128), blk256>>>(pxh, pxl, wvh_l, wvl_l, bv + l * 256, nullptr, pvh, pvl);
        k_scores<<<dim3(4, 4, 64), blk256>>>(pqh, pql, pkh, pkl, ps, srcL);
        k_softmax<<<32768, 128>>>(ps, psh, psl);
        k_attnout<<<dim3(1, 4, 64), blk256>>>(psh, psl, pvh, pvl, poh, pol);
        k_gemm_bias<<<dim3(2, 128), blk256>>>(poh, pol, woh_l, wol_l, bo + l * 256, pt, nullptr, nullptr);
        k_lnres<<<16384, blk256>>>(pt, px, ln1g + l * 256, ln1b + l * 256, srcL, px,
                                   pxh, pxl, px8h, px8l);

        k_conv<<<dim3(8, 128), blk256, SMEMC>>>(pxh, px8h, px8l,
            pw1h + (size_t)l * 2359296, pw18h + (size_t)l * 2359296, pw18l + (size_t)l * 2359296,
            c1b + l * 1024, 256, 3, 1, phh, ph8h, ph8l, nullptr, 1024);
        k_conv<<<dim3(2, 128), blk256, SMEMC>>>(phh, ph8h, ph8l,
            pw2h + (size_t)l * 2359296, pw28h + (size_t)l * 2359296, pw28l + (size_t)l * 2359296,
            c2b + l * 256, 1024, 5, 0, nullptr, nullptr, nullptr, pt, 256);
        k_lnres<<<16384, blk256>>>(pt, px, ln2g + l * 256, ln2b + l * 256, srcL, px,
                                   pxh, pxl, px8h, px8l);
    }

    k_masdp<<<32, 512>>>(pvt, srcL, melL, pdir);
    k_masbt<<<1, 32>>>(pdir, srcL, pidx);
    k_expand<<<32768, blk256>>>(px, pidx, srcL, melL, out);
}

// round 12
// speedup vs baseline: 1.0648x; 1.0648x over previous
#include <cuda_runtime.h>
#include <cuda_fp16.h>
#include <stdint.h>
#include <math.h>

#define NEGF (-1e9f)
typedef unsigned short ushort_t;

// ---------- scratch ----------
__device__ float    g_x [4194304];
__device__ float    g_t [4194304];
__device__ float    g_s [16777216];
__device__ float    g_vt[16777216];
__device__ ushort_t g_xh[4194304],  g_xl[4194304];
__device__ unsigned char g_x8[8388608];     // [row][16 chunks * 32B] lo|hi interleave
__device__ ushort_t g_qh[4194304],  g_ql[4194304];
__device__ ushort_t g_kh[4194304],  g_kl[4194304];
__device__ ushort_t g_vh[4194304],  g_vl[4194304];
__device__ ushort_t g_oh[4194304],  g_ol[4194304];
__device__ ushort_t g_sh[16777216], g_sl[16777216];
__device__ ushort_t g_hh[16777216];
__device__ unsigned char g_h8[33554432];    // [row][64 chunks * 32B]
__device__ ushort_t g_w1h[9437184];         // [L][9][1024][256] fp16
__device__ unsigned char g_w1i[18874368];   // [L][9][1024][512] hi*32|lo*65536 interleave
__device__ ushort_t g_w2h[9437184];         // [L][9][256][1024]
__device__ unsigned char g_w2i[18874368];
__device__ unsigned g_wqh[131072], g_wql[131072], g_wkh[131072], g_wkl[131072];
__device__ unsigned g_wvh[131072], g_wvl[131072], g_woh[131072], g_wol[131072];
__device__ unsigned g_dir[524288];
__device__ int      g_idx[32768];

// ---------- helpers ----------
__device__ __forceinline__ void split1(float v, ushort_t& h, ushort_t& l) {
    __half hh = __float2half_rn(v);
    __half ll = __float2half_rn(v - __half2float(hh));
    h = __half_as_ushort(hh); l = __half_as_ushort(ll);
}
__device__ __forceinline__ void wsplit2(ushort_t* Ph, ushort_t* Pl, size_t off,
                                        float v0, float v1) {
    ushort_t h0, l0, h1, l1;
    split1(v0, h0, l0); split1(v1, h1, l1);
    *(unsigned*)&Ph[off] = (unsigned)h0 | ((unsigned)h1 << 16);
    *(unsigned*)&Pl[off] = (unsigned)l0 | ((unsigned)l1 << 16);
}
// two e4m3 bytes: low byte = b0, high byte = b1
__device__ __forceinline__ ushort_t fp8x2(float b0, float b1) {
    ushort_t r;
    asm("cvt.rn.satfinite.e4m3x2.f32 %0, %2, %1;" : "=h"(r) : "f"(b0), "f"(b1));
    return r;
}
__device__ __forceinline__ unsigned smem_u32(const void* p) {
    unsigned a;
    asm("{ .reg .u64 t; cvta.to.shared.u64 t, %1; cvt.u32.u64 %0, t; }" : "=r"(a) : "l"(p));
    return a;
}

// ---------- mma cores ----------
__device__ __forceinline__ void mma16(float c[4], const unsigned a[4], const unsigned b[2]) {
    asm volatile(
        "mma.sync.aligned.m16n8k16.row.col.f32.f16.f16.f32 "
        "{%0,%1,%2,%3},{%4,%5,%6,%7},{%8,%9},{%0,%1,%2,%3};\n"
        : "+f"(c[0]), "+f"(c[1]), "+f"(c[2]), "+f"(c[3])
        : "r"(a[0]), "r"(a[1]), "r"(a[2]), "r"(a[3]), "r"(b[0]), "r"(b[1]));
}
// packed cross-term fp8 mma, f16 accumulate
__device__ __forceinline__ void qmma16(unsigned c[2], const unsigned a[4], const unsigned b[2]) {
    asm volatile(
        "mma.sync.aligned.m16n8k32.row.col.f16.e4m3.e4m3.f16 "
        "{%0,%1},{%2,%3,%4,%5},{%6,%7},{%0,%1};\n"
        : "+r"(c[0]), "+r"(c[1])
        : "r"(a[0]), "r"(a[1]), "r"(a[2]), "r"(a[3]), "r"(b[0]), "r"(b[1]));
}

#define CPA(d, s, n) \
    asm volatile("cp.async.cg.shared.global [%0],[%1],16,%2;" :: "r"(d), "l"(s), "r"(n) : "memory")

// ================= conv: hi*hi fp16 + packed fp8 cross, occupancy 2 =================
// Block 128x128, K-chunk 16. Buffer: A16@0 A8@6144 B16@12288 B8@18432 (24576B), x2 = 48KB.
__global__ void __launch_bounds__(256, 2)
k_conv(const ushort_t* __restrict__ Ah, const unsigned char* __restrict__ A8,
       const ushort_t* __restrict__ Wh, const unsigned char* __restrict__ W8,
       const float* __restrict__ bias, int Cin, int nsh, int relu_split,
       ushort_t* __restrict__ OHh, unsigned char* __restrict__ OH8,
       float* __restrict__ Of, int outld) {
    __shared__ __align__(16) char smem[49152];
    unsigned sbase = smem_u32(smem);
    int tid = threadIdx.x, wd = tid >> 5, lane = tid & 31;
    int wm = wd & 3, wn = wd >> 2, g = lane >> 2, tig = lane & 3;
    int n0 = blockIdx.x * 128, m0 = blockIdx.y * 128;
    int Coutv = gridDim.x * 128;
    int bbase = m0 & ~511, tb = m0 & 511;
    int ncmask = (1 << nsh) - 1;
    int NIT = 9 << nsh;
    int lrow = tid >> 1, lhalf = tid & 1;
    size_t wstr = (size_t)Coutv * Cin;
    float acc[16][4] = {};
    unsigned accX[16][2] = {};

#define ISSUE(itv, bo) do {                                                   \
        int dk_ = (itv) >> nsh; int kc_ = ((itv) & ncmask) << 4;              \
        int t_ = tb + lrow + dk_ - 4;                                         \
        unsigned okn = ((unsigned)t_ < 512u) ? 16u : 0u;                      \
        size_t ar_ = (size_t)(bbase + t_) * Cin;                              \
        unsigned d0_ = sbase + (bo) + lrow * 48 + lhalf * 16;                 \
        CPA(d0_, Ah + ar_ + kc_ + lhalf * 8, okn);                            \
        CPA(d0_ + 6144, A8 + ar_ * 2 + kc_ * 2 + lhalf * 16, okn);            \
        size_t wr_ = (size_t)dk_ * wstr + (size_t)(n0 + lrow) * Cin;          \
        CPA(d0_ + 12288, Wh + wr_ + kc_ + lhalf * 8, 16u);                    \
        CPA(d0_ + 18432, W8 + wr_ * 2 + kc_ * 2 + lhalf * 16, 16u);           \
    } while (0)

    ISSUE(0, 0);
    asm volatile("cp.async.commit_group;" ::: "memory");
    for (int it = 0; it < NIT; ++it) {
        int cbo = (it & 1) * 24576, nbo = 24576 - cbo;
        if (it + 1 < NIT) {
            ISSUE(it + 1, nbo);
            asm volatile("cp.async.commit_group;" ::: "memory");
            asm volatile("cp.async.wait_group 1;" ::: "memory");
        } else {
            asm volatile("cp.async.wait_group 0;" ::: "memory");
        }
        __syncthreads();
        const unsigned* A16 = (const unsigned*)(smem + cbo);
        const unsigned* A8s = (const unsigned*)(smem + cbo + 6144);
        const unsigned* B16 = (const unsigned*)(smem + cbo + 12288);
        const unsigned* B8s = (const unsigned*)(smem + cbo + 18432);
        unsigned aF[2][4], aQ[2][4];
#pragma unroll
        for (int i = 0; i < 2; ++i) {
            int r = wm * 32 + i * 16 + g;
            aF[i][0] = A16[r * 12 + tig];     aF[i][1] = A16[(r + 8) * 12 + tig];
            aF[i][2] = A16[r * 12 + 4 + tig]; aF[i][3] = A16[(r + 8) * 12 + 4 + tig];
            aQ[i][0] = A8s[r * 12 + tig];     aQ[i][1] = A8s[(r + 8) * 12 + tig];
            aQ[i][2] = A8s[r * 12 + 4 + tig]; aQ[i][3] = A8s[(r + 8) * 12 + 4 + tig];
        }
#pragma unroll
        for (int j = 0; j < 8; ++j) {
            int c = wn * 64 + j * 8 + g;
            unsigned bF[2] = {B16[c * 12 + tig], B16[c * 12 + 4 + tig]};
            unsigned bQ[2] = {B8s[c * 12 + tig], B8s[c * 12 + 4 + tig]};
#pragma unroll
            for (int i = 0; i < 2; ++i) {
                mma16(acc[i * 8 + j], aF[i], bF);
                qmma16(accX[i * 8 + j], aQ[i], bQ);
            }
        }
        __syncthreads();
    }
#undef ISSUE
    const float SX = 1.0f / 65536.0f;
#pragma unroll
    for (int i = 0; i < 2; ++i)
#pragma unroll
        for (int j = 0; j < 8; ++j) {
            int m = m0 + wm * 32 + i * 16 + g;
            int n = n0 + wn * 64 + j * 8 + 2 * tig;
            float* a = acc[i * 8 + j];
            __half2 x0 = *(__half2*)&accX[i * 8 + j][0];
            __half2 x1 = *(__half2*)&accX[i * 8 + j][1];
            float b0 = bias[n], b1 = bias[n + 1];
            float v0 = a[0] + __low2float(x0) * SX + b0;
            float v1 = a[1] + __high2float(x0) * SX + b1;
            float v2 = a[2] + __low2float(x1) * SX + b0;
            float v3 = a[3] + __high2float(x1) * SX + b1;
            size_t o0 = (size_t)m * outld + n, o1 = (size_t)(m + 8) * outld + n;
            if (relu_split) {
                v0 = fmaxf(v0, 0.f); v1 = fmaxf(v1, 0.f);
                v2 = fmaxf(v2, 0.f); v3 = fmaxf(v3, 0.f);
                __half h0 = __float2half_rn(v0), h1 = __float2half_rn(v1);
                __half h2 = __float2half_rn(v2), h3 = __float2half_rn(v3);
                *(unsigned*)&OHh[o0] = (unsigned)__half_as_ushort(h0) | ((unsigned)__half_as_ushort(h1) << 16);
                *(unsigned*)&OHh[o1] = (unsigned)__half_as_ushort(h2) | ((unsigned)__half_as_ushort(h3) << 16);
                size_t b8a = (size_t)m * (outld * 2) + ((n >> 4) * 32) + (n & 15);
                size_t b8b = (size_t)(m + 8) * (outld * 2) + ((n >> 4) * 32) + (n & 15);
                *(ushort_t*)&OH8[b8a] = fp8x2((v0 - __half2float(h0)) * 2048.f,
                                              (v1 - __half2float(h1)) * 2048.f);
                *(ushort_t*)&OH8[b8a + 16] = fp8x2(v0, v1);
                *(ushort_t*)&OH8[b8b] = fp8x2((v2 - __half2float(h2)) * 2048.f,
                                              (v3 - __half2float(h3)) * 2048.f);
                *(ushort_t*)&OH8[b8b + 16] = fp8x2(v2, v3);
            } else {
                *(float2*)&Of[o0] = make_float2(v0, v1);
                *(float2*)&Of[o1] = make_float2(v2, v3);
            }
        }
}

// conv weight prep: src[l][R][C][9] -> Wh [l][9][R][C] fp16; Wi [l][9][R][C*2]
// interleave: chunk c>>4: bytes 0-15 = hi*32, 16-31 = lo*65536
__global__ void k_wprep(const float* __restrict__ src, ushort_t* __restrict__ Wh,
                        unsigned char* __restrict__ Wi, int R, int C) {
    size_t idx = ((size_t)blockIdx.x * 256 + threadIdx.x) * 2;
    int c = (int)(idx % C);
    size_t t1 = idx / C;
    int r = (int)(t1 % R);
    size_t t2 = t1 / R;
    int dk = (int)(t2 % 9);
    int l = (int)(t2 / 9);
    size_t sb = (((size_t)l * R + r) * C + c) * 9 + dk;
    float v0 = src[sb], v1 = src[sb + 9];
    __half h0 = __float2half_rn(v0), h1 = __float2half_rn(v1);
    *(unsigned*)&Wh[idx] = (unsigned)__half_as_ushort(h0) | ((unsigned)__half_as_ushort(h1) << 16);
    size_t rowb = (idx - c) * 2;
    size_t p = rowb + ((c >> 4) * 32) + (c & 15);
    *(ushort_t*)&Wi[p] = fp8x2(v0 * 32.f, v1 * 32.f);
    *(ushort_t*)&Wi[p + 16] = fp8x2((v0 - __half2float(h0)) * 65536.f,
                                    (v1 - __half2float(h1)) * 65536.f);
}

// ================= mma.sync attention (unchanged from R8) =================
__device__ __forceinline__ void mma_tile16(const unsigned* AsH, const unsigned* AsL,
                                           const unsigned* BsH, const unsigned* BsL,
                                           int wm, int wn, int g, int tig,
                                           float (*acc)[4]) {
    unsigned aH[2][4], aL[2][4];
#pragma unroll
    for (int i = 0; i < 2; ++i) {
        int r = (wm * 32 + i * 16 + g) * 12 + tig;
        aH[i][0] = AsH[r]; aH[i][1] = AsH[r + 96]; aH[i][2] = AsH[r + 4]; aH[i][3] = AsH[r + 100];
        aL[i][0] = AsL[r]; aL[i][1] = AsL[r + 96]; aL[i][2] = AsL[r + 4]; aL[i][3] = AsL[r + 100];
    }
#pragma unroll
    for (int j = 0; j < 8; ++j) {
        int nb = wn * 64 + j * 8 + g;
        unsigned bH[2] = {BsH[tig * 136 + nb], BsH[(tig + 4) * 136 + nb]};
        unsigned bL[2] = {BsL[tig * 136 + nb], BsL[(tig + 4) * 136 + nb]};
#pragma unroll
        for (int i = 0; i < 2; ++i) {
            mma16(acc[i * 8 + j], aH[i], bH);
            mma16(acc[i * 8 + j], aL[i], bH);
            mma16(acc[i * 8 + j], aH[i], bL);
        }
    }
}

__global__ void __launch_bounds__(256, 2)
k_gemm_bias(const ushort_t* __restrict__ Ah, const ushort_t* __restrict__ Al,
            const unsigned* __restrict__ Bph, const unsigned* __restrict__ Bpl,
            const float* __restrict__ bias, float* __restrict__ Cf,
            ushort_t* __restrict__ Ch, ushort_t* __restrict__ Cl) {
    __shared__ unsigned AsH[1536], AsL[1536], BsH[1088], BsL[1088];
    int tid = threadIdx.x, w = tid >> 5, lane = tid & 31;
    int wm = w & 3, wn = w >> 2, g = lane >> 2, tig = lane & 3;
    int n0 = blockIdx.x * 128, m0 = blockIdx.y * 128;
    int arow = tid >> 1, apart = tid & 1;
    int bp = tid >> 5, bc = lane * 4;
    float acc[16][4] = {};
    for (int k0 = 0; k0 < 256; k0 += 16) {
        size_t aoff = (size_t)(m0 + arow) * 256 + k0 + apart * 8;
        uint4 ah = *(const uint4*)(Ah + aoff);
        uint4 al = *(const uint4*)(Al + aoff);
        size_t boff = (size_t)(k0 / 2 + bp) * 256 + n0 + bc;
        uint4 bh = *(const uint4*)(Bph + boff);
        uint4 bl = *(const uint4*)(Bpl + boff);
        __syncthreads();
        *(uint4*)&AsH[arow * 12 + apart * 4] = ah;
        *(uint4*)&AsL[arow * 12 + apart * 4] = al;
        *(uint4*)&BsH[bp * 136 + bc] = bh;
        *(uint4*)&BsL[bp * 136 + bc] = bl;
        __syncthreads();
        mma_tile16(AsH, AsL, BsH, BsL, wm, wn, g, tig, acc);
    }
#pragma unroll
    for (int i = 0; i < 2; ++i)
#pragma unroll
        for (int j = 0; j < 8; ++j) {
            int m = m0 + wm * 32 + i * 16 + g;
            int n = n0 + wn * 64 + j * 8 + 2 * tig;
            float b0 = bias[n], b1 = bias[n + 1];
            float* a = acc[i * 8 + j];
            float v0 = a[0] + b0, v1 = a[1] + b1, v2 = a[2] + b0, v3 = a[3] + b1;
            if (Cf) {
                *(float2*)&Cf[(size_t)m * 256 + n] = make_float2(v0, v1);
                *(float2*)&Cf[(size_t)(m + 8) * 256 + n] = make_float2(v2, v3);
            }
            if (Ch) {
                wsplit2(Ch, Cl, (size_t)m * 256 + n, v0, v1);
                wsplit2(Ch, Cl, (size_t)(m + 8) * 256 + n, v2, v3);
            }
        }
}

__global__ void __launch_bounds__(256, 2)
k_scores(const ushort_t* __restrict__ Qh, const ushort_t* __restrict__ Ql,
         const ushort_t* __restrict__ Kh, const ushort_t* __restrict__ Kl,
         float* __restrict__ S, const int* __restrict__ srcL) {
    __shared__ unsigned AsH[1536], AsL[1536], BsH[1088], BsL[1088];
    int tid = threadIdx.x, w = tid >> 5, lane = tid & 31;
    int wm = w & 3, wn = w >> 2, g = lane >> 2, tig = lane & 3;
    int n0 = blockIdx.x * 128, m0 = blockIdx.y * 128, bh = blockIdx.z;
    int b = bh >> 1, h = bh & 1;
    int arow = tid >> 1, apart = tid & 1;
    int btn = tid & 127, bpb = (tid >> 7) * 4;
    float acc[16][4] = {};
    for (int k0 = 0; k0 < 128; k0 += 16) {
        size_t aoff = (size_t)(b * 512 + m0 + arow) * 256 + h * 128 + k0 + apart * 8;
        uint4 ah = *(const uint4*)(Qh + aoff);
        uint4 al = *(const uint4*)(Ql + aoff);
        size_t koff = (size_t)(b * 512 + n0 + btn) * 256 + h * 128 + k0 + bpb * 2;
        uint4 bh4 = *(const uint4*)(Kh + koff);
        uint4 bl4 = *(const uint4*)(Kl + koff);
        __syncthreads();
        *(uint4*)&AsH[arow * 12 + apart * 4] = ah;
        *(uint4*)&AsL[arow * 12 + apart * 4] = al;
        BsH[(bpb + 0) * 136 + btn] = bh4.x; BsH[(bpb + 1) * 136 + btn] = bh4.y;
        BsH[(bpb + 2) * 136 + btn] = bh4.z; BsH[(bpb + 3) * 136 + btn] = bh4.w;
        BsL[(bpb + 0) * 136 + btn] = bl4.x; BsL[(bpb + 1) * 136 + btn] = bl4.y;
        BsL[(bpb + 2) * 136 + btn] = bl4.z; BsL[(bpb + 3) * 136 + btn] = bl4.w;
        __syncthreads();
        mma_tile16(AsH, AsL, BsH, BsL, wm, wn, g, tig, acc);
    }
    int sl = srcL[b];
    const float scale = 0.08838834764831845f;
#pragma unroll
    for (int i = 0; i < 2; ++i)
#pragma unroll
        for (int j = 0; j < 8; ++j) {
            int m = m0 + wm * 32 + i * 16 + g;
            int n = n0 + wn * 64 + j * 8 + 2 * tig;
            float* a = acc[i * 8 + j];
            bool p0 = (n >= sl), p1 = (n + 1 >= sl);
            float2 r0 = {p0 ? NEGF : a[0] * scale, p1 ? NEGF : a[1] * scale};
            float2 r1 = {p0 ? NEGF : a[2] * scale, p1 ? NEGF : a[3] * scale};
            *(float2*)&S[((size_t)bh * 512 + m) * 512 + n] = r0;
            *(float2*)&S[((size_t)bh * 512 + m + 8) * 512 + n] = r1;
        }
}

__global__ void __launch_bounds__(256, 2)
k_attnout(const ushort_t* __restrict__ Sh, const ushort_t* __restrict__ Sl,
          const ushort_t* __restrict__ Vh, const ushort_t* __restrict__ Vl,
          ushort_t* __restrict__ Oh, ushort_t* __restrict__ Ol) {
    __shared__ unsigned AsH[1536], AsL[1536], BsH[1088], BsL[1088];
    int tid = threadIdx.x, w = tid >> 5, lane = tid & 31;
    int wm = w & 3, wn = w >> 2, g = lane >> 2, tig = lane & 3;
    int m0 = blockIdx.y * 128, bh = blockIdx.z;
    int b = bh >> 1, h = bh & 1;
    int arow = tid >> 1, apart = tid & 1;
    int bp = tid >> 5, bc = lane * 4;
    float acc[16][4] = {};
    for (int k0 = 0; k0 < 512; k0 += 16) {
        size_t aoff = ((size_t)bh * 512 + m0 + arow) * 512 + k0 + apart * 8;
        uint4 ah = *(const uint4*)(Sh + aoff);
        uint4 al = *(const uint4*)(Sl + aoff);
        const ushort_t* r0h = Vh + (size_t)(b * 512 + k0 + 2 * bp) * 256 + h * 128 + bc;
        uint2 uah = *(const uint2*)r0h, ubh = *(const uint2*)(r0h + 256);
        const ushort_t* r0l = Vl + (size_t)(b * 512 + k0 + 2 * bp) * 256 + h * 128 + bc;
        uint2 ual = *(const uint2*)r0l, ubl = *(const uint2*)(r0l + 256);
        __syncthreads();
        *(uint4*)&AsH[arow * 12 + apart * 4] = ah;
        *(uint4*)&AsL[arow * 12 + apart * 4] = al;
        BsH[bp * 136 + bc + 0] = (uah.x & 0xFFFFu) | (ubh.x << 16);
        BsH[bp * 136 + bc + 1] = (uah.x >> 16) | (ubh.x & 0xFFFF0000u);
        BsH[bp * 136 + bc + 2] = (uah.y & 0xFFFFu) | (ubh.y << 16);
        BsH[bp * 136 + bc + 3] = (uah.y >> 16) | (ubh.y & 0xFFFF0000u);
        BsL[bp * 136 + bc + 0] = (ual.x & 0xFFFFu) | (ubl.x << 16);
        BsL[bp * 136 + bc + 1] = (ual.x >> 16) | (ubl.x & 0xFFFF0000u);
        BsL[bp * 136 + bc + 2] = (ual.y & 0xFFFFu) | (ubl.y << 16);
        BsL[bp * 136 + bc + 3] = (ual.y >> 16) | (ubl.y & 0xFFFF0000u);
        __syncthreads();
        mma_tile16(AsH, AsL, BsH, BsL, wm, wn, g, tig, acc);
    }
#pragma unroll
    for (int i = 0; i < 2; ++i)
#pragma unroll
        for (int j = 0; j < 8; ++j) {
            int m = m0 + wm * 32 + i * 16 + g;
            int n = h * 128 + wn * 64 + j * 8 + 2 * tig;
            float* a = acc[i * 8 + j];
            wsplit2(Oh, Ol, (size_t)(b * 512 + m) * 256 + n, a[0], a[1]);
            wsplit2(Oh, Ol, (size_t)(b * 512 + m + 8) * 256 + n, a[2], a[3]);
        }
}

// ================= producers / elementwise =================
__global__ void k_embed(const int* __restrict__ tok, const float* __restrict__ emb,
                        const float* __restrict__ pos, float* __restrict__ x,
                        ushort_t* __restrict__ xh, ushort_t* __restrict__ xl) {
    int row = blockIdx.x, d = threadIdx.x;
    int t = row & 511;
    int id = tok[row];
    size_t off = (size_t)row * 256 + d;
    float v = emb[(size_t)id * 256 + d] + pos[(size_t)t * 256 + d];
    x[off] = v;
    ushort_t h, l; split1(v, h, l);
    xh[off] = h; xl[off] = l;
}

__global__ void k_softmax(const float* __restrict__ S, ushort_t* __restrict__ Sh,
                          ushort_t* __restrict__ Sl) {
    __shared__ float red[4];
    size_t row = blockIdx.x;
    float4 v = ((const float4*)(S + row * 512))[threadIdx.x];
    int lane = threadIdx.x & 31, wid = threadIdx.x >> 5;
    float m = fmaxf(fmaxf(v.x, v.y), fmaxf(v.z, v.w));
#pragma unroll
    for (int o = 16; o > 0; o >>= 1) m = fmaxf(m, __shfl_xor_sync(~0u, m, o));
    if (lane == 0) red[wid] = m;
    __syncthreads();
    m = fmaxf(fmaxf(red[0], red[1]), fmaxf(red[2], red[3]));
    __syncthreads();
    v.x = expf(v.x - m); v.y = expf(v.y - m); v.z = expf(v.z - m); v.w = expf(v.w - m);
    float s = v.x + v.y + v.z + v.w;
#pragma unroll
    for (int o = 16; o > 0; o >>= 1) s += __shfl_xor_sync(~0u, s, o);
    if (lane == 0) red[wid] = s;
    __syncthreads();
    s = red[0] + red[1] + red[2] + red[3];
    float inv = 1.0f / s;
    size_t off = row * 512 + threadIdx.x * 4;
    wsplit2(Sh, Sl, off, v.x * inv, v.y * inv);
    wsplit2(Sh, Sl, off + 2, v.z * inv, v.w * inv);
}

__global__ void k_lnres(const float* __restrict__ t, const float* __restrict__ res,
                        const float* __restrict__ gam, const float* __restrict__ bet,
                        const int* __restrict__ srcL, float* __restrict__ out,
                        ushort_t* __restrict__ oh, ushort_t* __restrict__ ol,
                        unsigned char* __restrict__ o8) {
    __shared__ float red[8];
    int row = blockIdx.x, d = threadIdx.x;
    size_t off = (size_t)row * 256 + d;
    float val = t[off] + res[off];
    float s = val;
#pragma unroll
    for (int o = 16; o > 0; o >>= 1) s += __shfl_xor_sync(~0u, s, o);
    if ((d & 31) == 0) red[d >> 5] = s;
    __syncthreads();
    float tot = 0.f;
#pragma unroll
    for (int i = 0; i < 8; ++i) tot += red[i];
    float mean = tot * (1.0f / 256.0f);
    float dv = val - mean;
    __syncthreads();
    float s2 = dv * dv;
#pragma unroll
    for (int o = 16; o > 0; o >>= 1) s2 += __shfl_xor_sync(~0u, s2, o);
    if ((d & 31) == 0) red[d >> 5] = s2;
    __syncthreads();
    float tot2 = 0.f;
#pragma unroll
    for (int i = 0; i < 8; ++i) tot2 += red[i];
    float o = dv * rsqrtf(tot2 * (1.0f / 256.0f) + 1e-5f) * gam[d] + bet[d];
    if ((row & 511) >= srcL[row >> 9]) o = 0.f;
    out[off] = o;
    __half hh = __float2half_rn(o);
    float lo = o - __half2float(hh);
    oh[off] = __half_as_ushort(hh);
    ol[off] = __half_as_ushort(__float2half_rn(lo));
    size_t p8 = (size_t)row * 512 + ((d >> 4) * 32) + (d & 15);
    o8[p8] = (unsigned char)(fp8x2(lo * 2048.f, 0.f) & 0xFF);
    o8[p8 + 16] = (unsigned char)(fp8x2(o, 0.f) & 0xFF);
}

__global__ void k_packsplit(const float* __restrict__ src, unsigned* __restrict__ Uh,
                            unsigned* __restrict__ Ul, int nshift) {
    size_t idx = (size_t)blockIdx.x * 256 + threadIdx.x;
    size_t kp = idx >> nshift;
    int n = (int)(idx & ((1u << nshift) - 1));
    size_t N = (size_t)1 << nshift;
    float a = src[(2 * kp) * N + n], b = src[(2 * kp + 1) * N + n];
    ushort_t ha, la, hb, lb;
    split1(a, ha, la); split1(b, hb, lb);
    Uh[idx] = (unsigned)ha | ((unsigned)hb << 16);
    Ul[idx] = (unsigned)la | ((unsigned)lb << 16);
}

// ================= MAS + expand =================
__global__ void k_vtrans(const float* __restrict__ val, float* __restrict__ vt,
                         const int* __restrict__ srcL, const int* __restrict__ melL) {
    __shared__ float s[32][33];
    int b = blockIdx.z;
    int x0 = blockIdx.x * 32, y0 = blockIdx.y * 32;
    int sl = srcL[b], ml = melL[b];
    const float* vp = val + (size_t)b * 512 * 1024;
    float* op = vt + (size_t)b * 1024 * 512;
    for (int i = threadIdx.y; i < 32; i += 8) {
        int x = x0 + i, y = y0 + threadIdx.x;
        float v = vp[(size_t)x * 1024 + y];
        s[i][threadIdx.x] = (x < sl && y < ml) ? v : 0.f;
    }
    __syncthreads();
    for (int j = threadIdx.y; j < 32; j += 8)
        op[(size_t)(y0 + j) * 512 + x0 + threadIdx.x] = s[threadIdx.x][j];
}

__global__ void k_masdp(const float* __restrict__ vt, const int* __restrict__ srcL,
                        const int* __restrict__ melL, unsigned* __restrict__ dir) {
    __shared__ float sv[512];
    int b = blockIdx.x, x = threadIdx.x;
    int sl = srcL[b], ml = melL[b];
    int lane = x & 31, wid = x >> 5;
    float v = 0.f;
    for (int j = 0; j < 1024; ++j) {
        sv[x] = v;
        __syncthreads();
        float v0 = x ? sv[x - 1] : NEGF;
        float val = vt[((size_t)b * 1024 + j) * 512 + x];
        bool d = (v >= v0);
        float vmax = d ? v : v0;
        float vnew = (x <= j) ? (vmax + val) : NEGF;
        bool dm = (x < sl && j < ml) ? d : true;
        unsigned bal = __ballot_sync(0xffffffffu, dm);
        if (lane == 0) dir[((size_t)b * 1024 + j) * 16 + wid] = bal;
        v = vnew;
        __syncthreads();
    }
}

__global__ void k_masbt(const unsigned* __restrict__ dir, const int* __restrict__ srcL,
                        int* __restrict__ idxout) {
    int b = threadIdx.x;
    if (b >= 32) return;
    int idx = srcL[b] - 1;
    for (int y = 1023; y >= 0; --y) {
        idxout[b * 1024 + y] = idx;
        unsigned w = dir[((size_t)b * 1024 + y) * 16 + (idx >> 5)];
        idx += (int)((w >> (idx & 31)) & 1u) - 1;
    }
}

__global__ void k_expand(const float* __restrict__ X, const int* __restrict__ idx,
                         const int* __restrict__ srcL, const int* __restrict__ melL,
                         float* __restrict__ out) {
    int row = blockIdx.x;
    int b = row >> 10, y = row & 1023;
    int d = threadIdx.x;
    float o = 0.f;
    if (y < melL[b]) {
        int ix = idx[row];
        if (ix >= 0 && ix < srcL[b])
            o = X[((size_t)(b << 9) + ix) * 256 + d];
    }
    out[(size_t)row * 256 + d] = o;
}

// ================= launch =================
extern "C" void kernel_launch(void* const* d_in, const int* in_sizes, int n_in,
                              void* d_out, int out_size) {
    const int* tokens = (const int*)d_in[0];
    const int* srcL   = (const int*)d_in[1];
    const int* melL   = (const int*)d_in[2];
    const float* value = (const float*)d_in[3];
    const float* embed = (const float*)d_in[4];
    const float* pos   = (const float*)d_in[5];
    const float* wq = (const float*)d_in[6];  const float* bq = (const float*)d_in[7];
    const float* wk = (const float*)d_in[8];  const float* bk = (const float*)d_in[9];
    const float* wv = (const float*)d_in[10]; const float* bv = (const float*)d_in[11];
    const float* wo = (const float*)d_in[12]; const float* bo = (const float*)d_in[13];
    const float* ln1g = (const float*)d_in[14]; const float* ln1b = (const float*)d_in[15];
    const float* c1w = (const float*)d_in[16]; const float* c1b = (const float*)d_in[17];
    const float* c2w = (const float*)d_in[18]; const float* c2b = (const float*)d_in[19];
    const float* ln2g = (const float*)d_in[20]; const float* ln2b = (const float*)d_in[21];
    float* out = (float*)d_out;

    float *px, *pt, *ps, *pvt;
    ushort_t *pxh, *pxl, *pqh, *pql, *pkh, *pkl, *pvh, *pvl, *poh, *pol;
    ushort_t *psh, *psl, *phh, *pw1h, *pw2h;
    unsigned char *px8, *ph8, *pw1i, *pw2i;
    unsigned *pwqh, *pwql, *pwkh, *pwkl, *pwvh, *pwvl, *pwoh, *pwol;
    unsigned* pdir; int* pidx;
    cudaGetSymbolAddress((void**)&px, g_x);   cudaGetSymbolAddress((void**)&pt, g_t);
    cudaGetSymbolAddress((void**)&ps, g_s);   cudaGetSymbolAddress((void**)&pvt, g_vt);
    cudaGetSymbolAddress((void**)&pxh, g_xh); cudaGetSymbolAddress((void**)&pxl, g_xl);
    cudaGetSymbolAddress((void**)&px8, g_x8);
    cudaGetSymbolAddress((void**)&pqh, g_qh); cudaGetSymbolAddress((void**)&pql, g_ql);
    cudaGetSymbolAddress((void**)&pkh, g_kh); cudaGetSymbolAddress((void**)&pkl, g_kl);
    cudaGetSymbolAddress((void**)&pvh, g_vh); cudaGetSymbolAddress((void**)&pvl, g_vl);
    cudaGetSymbolAddress((void**)&poh, g_oh); cudaGetSymbolAddress((void**)&pol, g_ol);
    cudaGetSymbolAddress((void**)&psh, g_sh); cudaGetSymbolAddress((void**)&psl, g_sl);
    cudaGetSymbolAddress((void**)&phh, g_hh); cudaGetSymbolAddress((void**)&ph8, g_h8);
    cudaGetSymbolAddress((void**)&pw1h, g_w1h); cudaGetSymbolAddress((void**)&pw1i, g_w1i);
    cudaGetSymbolAddress((void**)&pw2h, g_w2h); cudaGetSymbolAddress((void**)&pw2i, g_w2i);
    cudaGetSymbolAddress((void**)&pwqh, g_wqh); cudaGetSymbolAddress((void**)&pwql, g_wql);
    cudaGetSymbolAddress((void**)&pwkh, g_wkh); cudaGetSymbolAddress((void**)&pwkl, g_wkl);
    cudaGetSymbolAddress((void**)&pwvh, g_wvh); cudaGetSymbolAddress((void**)&pwvl, g_wvl);
    cudaGetSymbolAddress((void**)&pwoh, g_woh); cudaGetSymbolAddress((void**)&pwol, g_wol);
    cudaGetSymbolAddress((void**)&pdir, g_dir); cudaGetSymbolAddress((void**)&pidx, g_idx);

    dim3 blk256(256);
    // weight prep
    k_wprep<<<18432, blk256>>>(c1w, pw1h, pw1i, 1024, 256);
    k_wprep<<<18432, blk256>>>(c2w, pw2h, pw2i, 256, 1024);
    k_packsplit<<<512, blk256>>>(wq, pwqh, pwql, 8);
    k_packsplit<<<512, blk256>>>(wk, pwkh, pwkl, 8);
    k_packsplit<<<512, blk256>>>(wv, pwvh, pwvl, 8);
    k_packsplit<<<512, blk256>>>(wo, pwoh, pwol, 8);
    // inputs
    k_vtrans<<<dim3(16, 32, 32), dim3(32, 8)>>>(value, pvt, srcL, melL);
    k_embed<<<16384, blk256>>>(tokens, embed, pos, px, pxh, pxl);

    for (int l = 0; l < 4; ++l) {
        const unsigned *wqh_l = pwqh + l * 32768, *wql_l = pwql + l * 32768;
        const unsigned *wkh_l = pwkh + l * 32768, *wkl_l = pwkl + l * 32768;
        const unsigned *wvh_l = pwvh + l * 32768, *wvl_l = pwvl + l * 32768;
        const unsigned *woh_l = pwoh + l * 32768, *wol_l = pwol + l * 32768;

        k_gemm_bias<<<dim3(2, 128), blk256>>>(pxh, pxl, wqh_l, wql_l, bq + l * 256, nullptr, pqh, pql);
        k_gemm_bias<<<dim3(2, 128), blk256>>>(pxh, pxl, wkh_l, wkl_l, bk + l * 256, nullptr, pkh, pkl);
        k_gemm_bias<<<dim3(2, 128), blk256>>>(pxh, pxl, wvh_l, wvl_l, bv + l * 256, nullptr, pvh, pvl);
        k_scores<<<dim3(4, 4, 64), blk256>>>(pqh, pql, pkh, pkl, ps, srcL);
        k_softmax<<<32768, 128>>>(ps, psh, psl);
        k_attnout<<<dim3(1, 4, 64), blk256>>>(psh, psl, pvh, pvl, poh, pol);
        k_gemm_bias<<<dim3(2, 128), blk256>>>(poh, pol, woh_l, wol_l, bo + l * 256, pt, nullptr, nullptr);
        k_lnres<<<16384, blk256>>>(pt, px, ln1g + l * 256, ln1b + l * 256, srcL, px,
                                   pxh, pxl, px8);

        k_conv<<<dim3(8, 128), blk256>>>(pxh, px8,
            pw1h + (size_t)l * 2359296, pw1i + (size_t)l * 4718592,
            c1b + l * 1024, 256, 4, 1, phh, ph8, nullptr, 1024);
        k_conv<<<dim3(2, 128), blk256>>>(phh, ph8,
            pw2h + (size_t)l * 2359296, pw2i + (size_t)l * 4718592,
            c2b + l * 256, 1024, 6, 0, nullptr, nullptr, pt, 256);
        k_lnres<<<16384, blk256>>>(pt, px, ln2g + l * 256, ln2b + l * 256, srcL, px,
                                   pxh, pxl, px8);
    }

    k_masdp<<<32, 512>>>(pvt, srcL, melL, pdir);
    k_masbt<<<1, 32>>>(pdir, srcL, pidx);
    k_expand<<<32768, blk256>>>(px, pidx, srcL, melL, out);
}

// round 13
// speedup vs baseline: 1.6024x; 1.5050x over previous
#include <cuda_runtime.h>
#include <cuda_fp16.h>
#include <stdint.h>
#include <math.h>

#define NEGF (-1e9f)
typedef unsigned short ushort_t;

// ---------- scratch ----------
__device__ float    g_x [4194304];
__device__ float    g_t [4194304];
__device__ float    g_s [16777216];
__device__ float    g_vt[16777216];
__device__ ushort_t g_xh[4194304],  g_xl[4194304];
__device__ ushort_t g_qh[4194304],  g_ql[4194304];
__device__ ushort_t g_kh[4194304],  g_kl[4194304];
__device__ ushort_t g_vh[4194304],  g_vl[4194304];
__device__ ushort_t g_oh[4194304],  g_ol[4194304];
__device__ ushort_t g_sh[16777216], g_sl[16777216];
__device__ ushort_t g_hh[16777216], g_hl[16777216];
__device__ ushort_t g_w1h[9437184];   // [L][9][1024][256] fp16 (transposed)
__device__ ushort_t g_w2h[9437184];   // [L][9][256][1024]
__device__ unsigned g_wqh[131072], g_wql[131072], g_wkh[131072], g_wkl[131072];
__device__ unsigned g_wvh[131072], g_wvl[131072], g_woh[131072], g_wol[131072];
__device__ unsigned g_dir[524288];
__device__ int      g_idx[32768];

// ---------- fp16 split helpers ----------
__device__ __forceinline__ void split1(float v, ushort_t& h, ushort_t& l) {
    __half hh = __float2half_rn(v);
    __half ll = __float2half_rn(v - __half2float(hh));
    h = __half_as_ushort(hh); l = __half_as_ushort(ll);
}
__device__ __forceinline__ void wsplit2(ushort_t* Ph, ushort_t* Pl, size_t off,
                                        float v0, float v1) {
    ushort_t h0, l0, h1, l1;
    split1(v0, h0, l0); split1(v1, h1, l1);
    *(unsigned*)&Ph[off] = (unsigned)h0 | ((unsigned)h1 << 16);
    *(unsigned*)&Pl[off] = (unsigned)l0 | ((unsigned)l1 << 16);
}
__device__ __forceinline__ unsigned smem_u32(const void* p) {
    unsigned a;
    asm("{ .reg .u64 t; cvta.to.shared.u64 t, %1; cvt.u32.u64 %0, t; }" : "=r"(a) : "l"(p));
    return a;
}

// ---------- mma core ----------
__device__ __forceinline__ void mma16(float c[4], const unsigned a[4], const unsigned b[2]) {
    asm volatile(
        "mma.sync.aligned.m16n8k16.row.col.f32.f16.f16.f32 "
        "{%0,%1,%2,%3},{%4,%5,%6,%7},{%8,%9},{%0,%1,%2,%3};\n"
        : "+f"(c[0]), "+f"(c[1]), "+f"(c[2]), "+f"(c[3])
        : "r"(a[0]), "r"(a[1]), "r"(a[2]), "r"(a[3]), "r"(b[0]), "r"(b[1]));
}

#define CPA(d, s, n) \
    asm volatile("cp.async.cg.shared.global [%0],[%1],16,%2;" :: "r"(d), "l"(s), "r"(n) : "memory")

// ================= conv: 2-pass fp16 split (aH*bH + aL*bH), K-chunk 32, pipelined =================
// Buffer (30720 B): Ahi[128 rows x 80B] @0 | Alo @10240 | Bhi @20480.  2 buffers = 61440 B dynamic.
__global__ void __launch_bounds__(256, 2)
k_conv(const ushort_t* __restrict__ Ah, const ushort_t* __restrict__ Al,
       const ushort_t* __restrict__ Wh,
       const float* __restrict__ bias, int Cin, int nsh, int relu_split,
       ushort_t* __restrict__ OHh, ushort_t* __restrict__ OHl,
       float* __restrict__ Of, int outld) {
    extern __shared__ __align__(16) char smem[];
    unsigned sbase = smem_u32(smem);
    int tid = threadIdx.x, wd = tid >> 5, lane = tid & 31;
    int wm = wd & 3, wn = wd >> 2, g = lane >> 2, tig = lane & 3;
    int n0 = blockIdx.x * 128, m0 = blockIdx.y * 128;
    int Coutv = gridDim.x * 128;
    int bbase = m0 & ~511, tb = m0 & 511;
    int ncmask = (1 << nsh) - 1;
    int NIT = 9 << nsh;
    int lrow = tid >> 1, lhalf = tid & 1;
    size_t wstr = (size_t)Coutv * Cin;
    float acc[16][4] = {};

#define ISSUE(itv, bo) do {                                                   \
        int dk_ = (itv) >> nsh; int kc_ = ((itv) & ncmask) << 5;              \
        int t_ = tb + lrow + dk_ - 4;                                         \
        unsigned okn = ((unsigned)t_ < 512u) ? 16u : 0u;                      \
        size_t ar_ = (size_t)(bbase + t_) * Cin + kc_ + lhalf * 16;          \
        unsigned da_ = sbase + (bo) + lrow * 80 + lhalf * 32;                 \
        CPA(da_, Ah + ar_, okn);        CPA(da_ + 16, Ah + ar_ + 8, okn);     \
        CPA(da_ + 10240, Al + ar_, okn); CPA(da_ + 10256, Al + ar_ + 8, okn); \
        size_t wr_ = (size_t)dk_ * wstr + (size_t)(n0 + lrow) * Cin + kc_ + lhalf * 16; \
        CPA(da_ + 20480, Wh + wr_, 16u); CPA(da_ + 20496, Wh + wr_ + 8, 16u); \
    } while (0)

    ISSUE(0, 0);
    asm volatile("cp.async.commit_group;" ::: "memory");
    for (int it = 0; it < NIT; ++it) {
        int cbo = (it & 1) * 30720, nbo = 30720 - cbo;
        if (it + 1 < NIT) {
            ISSUE(it + 1, nbo);
            asm volatile("cp.async.commit_group;" ::: "memory");
            asm volatile("cp.async.wait_group 1;" ::: "memory");
        } else {
            asm volatile("cp.async.wait_group 0;" ::: "memory");
        }
        __syncthreads();
        const unsigned* AH = (const unsigned*)(smem + cbo);
        const unsigned* AL = (const unsigned*)(smem + cbo + 10240);
        const unsigned* BH = (const unsigned*)(smem + cbo + 20480);
        unsigned aH0[2][4], aH1[2][4], aL0[2][4], aL1[2][4];
#pragma unroll
        for (int i = 0; i < 2; ++i) {
            int r = wm * 32 + i * 16 + g;
            int b0 = r * 20 + tig, b1 = (r + 8) * 20 + tig;
            aH0[i][0] = AH[b0];     aH0[i][1] = AH[b1];
            aH0[i][2] = AH[b0 + 4]; aH0[i][3] = AH[b1 + 4];
            aH1[i][0] = AH[b0 + 8];  aH1[i][1] = AH[b1 + 8];
            aH1[i][2] = AH[b0 + 12]; aH1[i][3] = AH[b1 + 12];
            aL0[i][0] = AL[b0];     aL0[i][1] = AL[b1];
            aL0[i][2] = AL[b0 + 4]; aL0[i][3] = AL[b1 + 4];
            aL1[i][0] = AL[b0 + 8];  aL1[i][1] = AL[b1 + 8];
            aL1[i][2] = AL[b0 + 12]; aL1[i][3] = AL[b1 + 12];
        }
#pragma unroll
        for (int j = 0; j < 8; ++j) {
            int c = (wn * 64 + j * 8 + g) * 20 + tig;
            unsigned bF0[2] = {BH[c], BH[c + 4]};
            unsigned bF1[2] = {BH[c + 8], BH[c + 12]};
#pragma unroll
            for (int i = 0; i < 2; ++i) {
                mma16(acc[i * 8 + j], aH0[i], bF0);
                mma16(acc[i * 8 + j], aH1[i], bF1);
                mma16(acc[i * 8 + j], aL0[i], bF0);
                mma16(acc[i * 8 + j], aL1[i], bF1);
            }
        }
        __syncthreads();
    }
#undef ISSUE
#pragma unroll
    for (int i = 0; i < 2; ++i)
#pragma unroll
        for (int j = 0; j < 8; ++j) {
            int m = m0 + wm * 32 + i * 16 + g;
            int n = n0 + wn * 64 + j * 8 + 2 * tig;
            float* a = acc[i * 8 + j];
            float b0 = bias[n], b1 = bias[n + 1];
            float v0 = a[0] + b0, v1 = a[1] + b1, v2 = a[2] + b0, v3 = a[3] + b1;
            size_t o0 = (size_t)m * outld + n, o1 = (size_t)(m + 8) * outld + n;
            if (relu_split) {
                v0 = fmaxf(v0, 0.f); v1 = fmaxf(v1, 0.f);
                v2 = fmaxf(v2, 0.f); v3 = fmaxf(v3, 0.f);
                wsplit2(OHh, OHl, o0, v0, v1);
                wsplit2(OHh, OHl, o1, v2, v3);
            } else {
                *(float2*)&Of[o0] = make_float2(v0, v1);
                *(float2*)&Of[o1] = make_float2(v2, v3);
            }
        }
}

// conv weight prep: src[l][R][C][9] fp32 -> Wh [l][9][R][C] fp16 (hi only)
__global__ void k_wprep(const float* __restrict__ src, ushort_t* __restrict__ Wh,
                        int R, int C) {
    size_t idx = ((size_t)blockIdx.x * 256 + threadIdx.x) * 2;
    int c = (int)(idx % C);
    size_t t1 = idx / C;
    int r = (int)(t1 % R);
    size_t t2 = t1 / R;
    int dk = (int)(t2 % 9);
    int l = (int)(t2 / 9);
    size_t sb = (((size_t)l * R + r) * C + c) * 9 + dk;
    __half h0 = __float2half_rn(src[sb]), h1 = __float2half_rn(src[sb + 9]);
    *(unsigned*)&Wh[idx] = (unsigned)__half_as_ushort(h0) | ((unsigned)__half_as_ushort(h1) << 16);
}

// ================= mma.sync attention (3-pass, proven R8) =================
__device__ __forceinline__ void mma_tile16(const unsigned* AsH, const unsigned* AsL,
                                           const unsigned* BsH, const unsigned* BsL,
                                           int wm, int wn, int g, int tig,
                                           float (*acc)[4]) {
    unsigned aH[2][4], aL[2][4];
#pragma unroll
    for (int i = 0; i < 2; ++i) {
        int r = (wm * 32 + i * 16 + g) * 12 + tig;
        aH[i][0] = AsH[r]; aH[i][1] = AsH[r + 96]; aH[i][2] = AsH[r + 4]; aH[i][3] = AsH[r + 100];
        aL[i][0] = AsL[r]; aL[i][1] = AsL[r + 96]; aL[i][2] = AsL[r + 4]; aL[i][3] = AsL[r + 100];
    }
#pragma unroll
    for (int j = 0; j < 8; ++j) {
        int nb = wn * 64 + j * 8 + g;
        unsigned bH[2] = {BsH[tig * 136 + nb], BsH[(tig + 4) * 136 + nb]};
        unsigned bL[2] = {BsL[tig * 136 + nb], BsL[(tig + 4) * 136 + nb]};
#pragma unroll
        for (int i = 0; i < 2; ++i) {
            mma16(acc[i * 8 + j], aH[i], bH);
            mma16(acc[i * 8 + j], aL[i], bH);
            mma16(acc[i * 8 + j], aH[i], bL);
        }
    }
}

__global__ void __launch_bounds__(256, 2)
k_gemm_bias(const ushort_t* __restrict__ Ah, const ushort_t* __restrict__ Al,
            const unsigned* __restrict__ Bph, const unsigned* __restrict__ Bpl,
            const float* __restrict__ bias, float* __restrict__ Cf,
            ushort_t* __restrict__ Ch, ushort_t* __restrict__ Cl) {
    __shared__ unsigned AsH[1536], AsL[1536], BsH[1088], BsL[1088];
    int tid = threadIdx.x, w = tid >> 5, lane = tid & 31;
    int wm = w & 3, wn = w >> 2, g = lane >> 2, tig = lane & 3;
    int n0 = blockIdx.x * 128, m0 = blockIdx.y * 128;
    int arow = tid >> 1, apart = tid & 1;
    int bp = tid >> 5, bc = lane * 4;
    float acc[16][4] = {};
    for (int k0 = 0; k0 < 256; k0 += 16) {
        size_t aoff = (size_t)(m0 + arow) * 256 + k0 + apart * 8;
        uint4 ah = *(const uint4*)(Ah + aoff);
        uint4 al = *(const uint4*)(Al + aoff);
        size_t boff = (size_t)(k0 / 2 + bp) * 256 + n0 + bc;
        uint4 bh = *(const uint4*)(Bph + boff);
        uint4 bl = *(const uint4*)(Bpl + boff);
        __syncthreads();
        *(uint4*)&AsH[arow * 12 + apart * 4] = ah;
        *(uint4*)&AsL[arow * 12 + apart * 4] = al;
        *(uint4*)&BsH[bp * 136 + bc] = bh;
        *(uint4*)&BsL[bp * 136 + bc] = bl;
        __syncthreads();
        mma_tile16(AsH, AsL, BsH, BsL, wm, wn, g, tig, acc);
    }
#pragma unroll
    for (int i = 0; i < 2; ++i)
#pragma unroll
        for (int j = 0; j < 8; ++j) {
            int m = m0 + wm * 32 + i * 16 + g;
            int n = n0 + wn * 64 + j * 8 + 2 * tig;
            float b0 = bias[n], b1 = bias[n + 1];
            float* a = acc[i * 8 + j];
            float v0 = a[0] + b0, v1 = a[1] + b1, v2 = a[2] + b0, v3 = a[3] + b1;
            if (Cf) {
                *(float2*)&Cf[(size_t)m * 256 + n] = make_float2(v0, v1);
                *(float2*)&Cf[(size_t)(m + 8) * 256 + n] = make_float2(v2, v3);
            }
            if (Ch) {
                wsplit2(Ch, Cl, (size_t)m * 256 + n, v0, v1);
                wsplit2(Ch, Cl, (size_t)(m + 8) * 256 + n, v2, v3);
            }
        }
}

__global__ void __launch_bounds__(256, 2)
k_scores(const ushort_t* __restrict__ Qh, const ushort_t* __restrict__ Ql,
         const ushort_t* __restrict__ Kh, const ushort_t* __restrict__ Kl,
         float* __restrict__ S, const int* __restrict__ srcL) {
    __shared__ unsigned AsH[1536], AsL[1536], BsH[1088], BsL[1088];
    int tid = threadIdx.x, w = tid >> 5, lane = tid & 31;
    int wm = w & 3, wn = w >> 2, g = lane >> 2, tig = lane & 3;
    int n0 = blockIdx.x * 128, m0 = blockIdx.y * 128, bh = blockIdx.z;
    int b = bh >> 1, h = bh & 1;
    int arow = tid >> 1, apart = tid & 1;
    int btn = tid & 127, bpb = (tid >> 7) * 4;
    float acc[16][4] = {};
    for (int k0 = 0; k0 < 128; k0 += 16) {
        size_t aoff = (size_t)(b * 512 + m0 + arow) * 256 + h * 128 + k0 + apart * 8;
        uint4 ah = *(const uint4*)(Qh + aoff);
        uint4 al = *(const uint4*)(Ql + aoff);
        size_t koff = (size_t)(b * 512 + n0 + btn) * 256 + h * 128 + k0 + bpb * 2;
        uint4 bh4 = *(const uint4*)(Kh + koff);
        uint4 bl4 = *(const uint4*)(Kl + koff);
        __syncthreads();
        *(uint4*)&AsH[arow * 12 + apart * 4] = ah;
        *(uint4*)&AsL[arow * 12 + apart * 4] = al;
        BsH[(bpb + 0) * 136 + btn] = bh4.x; BsH[(bpb + 1) * 136 + btn] = bh4.y;
        BsH[(bpb + 2) * 136 + btn] = bh4.z; BsH[(bpb + 3) * 136 + btn] = bh4.w;
        BsL[(bpb + 0) * 136 + btn] = bl4.x; BsL[(bpb + 1) * 136 + btn] = bl4.y;
        BsL[(bpb + 2) * 136 + btn] = bl4.z; BsL[(bpb + 3) * 136 + btn] = bl4.w;
        __syncthreads();
        mma_tile16(AsH, AsL, BsH, BsL, wm, wn, g, tig, acc);
    }
    int sl = srcL[b];
    const float scale = 0.08838834764831845f;
#pragma unroll
    for (int i = 0; i < 2; ++i)
#pragma unroll
        for (int j = 0; j < 8; ++j) {
            int m = m0 + wm * 32 + i * 16 + g;
            int n = n0 + wn * 64 + j * 8 + 2 * tig;
            float* a = acc[i * 8 + j];
            bool p0 = (n >= sl), p1 = (n + 1 >= sl);
            float2 r0 = {p0 ? NEGF : a[0] * scale, p1 ? NEGF : a[1] * scale};
            float2 r1 = {p0 ? NEGF : a[2] * scale, p1 ? NEGF : a[3] * scale};
            *(float2*)&S[((size_t)bh * 512 + m) * 512 + n] = r0;
            *(float2*)&S[((size_t)bh * 512 + m + 8) * 512 + n] = r1;
        }
}

__global__ void __launch_bounds__(256, 2)
k_attnout(const ushort_t* __restrict__ Sh, const ushort_t* __restrict__ Sl,
          const ushort_t* __restrict__ Vh, const ushort_t* __restrict__ Vl,
          ushort_t* __restrict__ Oh, ushort_t* __restrict__ Ol) {
    __shared__ unsigned AsH[1536], AsL[1536], BsH[1088], BsL[1088];
    int tid = threadIdx.x, w = tid >> 5, lane = tid & 31;
    int wm = w & 3, wn = w >> 2, g = lane >> 2, tig = lane & 3;
    int m0 = blockIdx.y * 128, bh = blockIdx.z;
    int b = bh >> 1, h = bh & 1;
    int arow = tid >> 1, apart = tid & 1;
    int bp = tid >> 5, bc = lane * 4;
    float acc[16][4] = {};
    for (int k0 = 0; k0 < 512; k0 += 16) {
        size_t aoff = ((size_t)bh * 512 + m0 + arow) * 512 + k0 + apart * 8;
        uint4 ah = *(const uint4*)(Sh + aoff);
        uint4 al = *(const uint4*)(Sl + aoff);
        const ushort_t* r0h = Vh + (size_t)(b * 512 + k0 + 2 * bp) * 256 + h * 128 + bc;
        uint2 uah = *(const uint2*)r0h, ubh = *(const uint2*)(r0h + 256);
        const ushort_t* r0l = Vl + (size_t)(b * 512 + k0 + 2 * bp) * 256 + h * 128 + bc;
        uint2 ual = *(const uint2*)r0l, ubl = *(const uint2*)(r0l + 256);
        __syncthreads();
        *(uint4*)&AsH[arow * 12 + apart * 4] = ah;
        *(uint4*)&AsL[arow * 12 + apart * 4] = al;
        BsH[bp * 136 + bc + 0] = (uah.x & 0xFFFFu) | (ubh.x << 16);
        BsH[bp * 136 + bc + 1] = (uah.x >> 16) | (ubh.x & 0xFFFF0000u);
        BsH[bp * 136 + bc + 2] = (uah.y & 0xFFFFu) | (ubh.y << 16);
        BsH[bp * 136 + bc + 3] = (uah.y >> 16) | (ubh.y & 0xFFFF0000u);
        BsL[bp * 136 + bc + 0] = (ual.x & 0xFFFFu) | (ubl.x << 16);
        BsL[bp * 136 + bc + 1] = (ual.x >> 16) | (ubl.x & 0xFFFF0000u);
        BsL[bp * 136 + bc + 2] = (ual.y & 0xFFFFu) | (ubl.y << 16);
        BsL[bp * 136 + bc + 3] = (ual.y >> 16) | (ubl.y & 0xFFFF0000u);
        __syncthreads();
        mma_tile16(AsH, AsL, BsH, BsL, wm, wn, g, tig, acc);
    }
#pragma unroll
    for (int i = 0; i < 2; ++i)
#pragma unroll
        for (int j = 0; j < 8; ++j) {
            int m = m0 + wm * 32 + i * 16 + g;
            int n = h * 128 + wn * 64 + j * 8 + 2 * tig;
            float* a = acc[i * 8 + j];
            wsplit2(Oh, Ol, (size_t)(b * 512 + m) * 256 + n, a[0], a[1]);
            wsplit2(Oh, Ol, (size_t)(b * 512 + m + 8) * 256 + n, a[2], a[3]);
        }
}

// ================= producers / elementwise =================
__global__ void k_embed(const int* __restrict__ tok, const float* __restrict__ emb,
                        const float* __restrict__ pos, float* __restrict__ x,
                        ushort_t* __restrict__ xh, ushort_t* __restrict__ xl) {
    int row = blockIdx.x, d = threadIdx.x;
    int t = row & 511;
    int id = tok[row];
    size_t off = (size_t)row * 256 + d;
    float v = emb[(size_t)id * 256 + d] + pos[(size_t)t * 256 + d];
    x[off] = v;
    ushort_t h, l; split1(v, h, l);
    xh[off] = h; xl[off] = l;
}

__global__ void k_softmax(const float* __restrict__ S, ushort_t* __restrict__ Sh,
                          ushort_t* __restrict__ Sl) {
    __shared__ float red[4];
    size_t row = blockIdx.x;
    float4 v = ((const float4*)(S + row * 512))[threadIdx.x];
    int lane = threadIdx.x & 31, wid = threadIdx.x >> 5;
    float m = fmaxf(fmaxf(v.x, v.y), fmaxf(v.z, v.w));
#pragma unroll
    for (int o = 16; o > 0; o >>= 1) m = fmaxf(m, __shfl_xor_sync(~0u, m, o));
    if (lane == 0) red[wid] = m;
    __syncthreads();
    m = fmaxf(fmaxf(red[0], red[1]), fmaxf(red[2], red[3]));
    __syncthreads();
    v.x = expf(v.x - m); v.y = expf(v.y - m); v.z = expf(v.z - m); v.w = expf(v.w - m);
    float s = v.x + v.y + v.z + v.w;
#pragma unroll
    for (int o = 16; o > 0; o >>= 1) s += __shfl_xor_sync(~0u, s, o);
    if (lane == 0) red[wid] = s;
    __syncthreads();
    s = red[0] + red[1] + red[2] + red[3];
    float inv = 1.0f / s;
    size_t off = row * 512 + threadIdx.x * 4;
    wsplit2(Sh, Sl, off, v.x * inv, v.y * inv);
    wsplit2(Sh, Sl, off + 2, v.z * inv, v.w * inv);
}

__global__ void k_lnres(const float* __restrict__ t, const float* __restrict__ res,
                        const float* __restrict__ gam, const float* __restrict__ bet,
                        const int* __restrict__ srcL, float* __restrict__ out,
                        ushort_t* __restrict__ oh, ushort_t* __restrict__ ol) {
    __shared__ float red[8];
    int row = blockIdx.x, d = threadIdx.x;
    size_t off = (size_t)row * 256 + d;
    float val = t[off] + res[off];
    float s = val;
#pragma unroll
    for (int o = 16; o > 0; o >>= 1) s += __shfl_xor_sync(~0u, s, o);
    if ((d & 31) == 0) red[d >> 5] = s;
    __syncthreads();
    float tot = 0.f;
#pragma unroll
    for (int i = 0; i < 8; ++i) tot += red[i];
    float mean = tot * (1.0f / 256.0f);
    float dv = val - mean;
    __syncthreads();
    float s2 = dv * dv;
#pragma unroll
    for (int o = 16; o > 0; o >>= 1) s2 += __shfl_xor_sync(~0u, s2, o);
    if ((d & 31) == 0) red[d >> 5] = s2;
    __syncthreads();
    float tot2 = 0.f;
#pragma unroll
    for (int i = 0; i < 8; ++i) tot2 += red[i];
    float o = dv * rsqrtf(tot2 * (1.0f / 256.0f) + 1e-5f) * gam[d] + bet[d];
    if ((row & 511) >= srcL[row >> 9]) o = 0.f;
    out[off] = o;
    ushort_t h, l; split1(o, h, l);
    oh[off] = h; ol[off] = l;
}

__global__ void k_packsplit(const float* __restrict__ src, unsigned* __restrict__ Uh,
                            unsigned* __restrict__ Ul, int nshift) {
    size_t idx = (size_t)blockIdx.x * 256 + threadIdx.x;
    size_t kp = idx >> nshift;
    int n = (int)(idx & ((1u << nshift) - 1));
    size_t N = (size_t)1 << nshift;
    float a = src[(2 * kp) * N + n], b = src[(2 * kp + 1) * N + n];
    ushort_t ha, la, hb, lb;
    split1(a, ha, la); split1(b, hb, lb);
    Uh[idx] = (unsigned)ha | ((unsigned)hb << 16);
    Ul[idx] = (unsigned)la | ((unsigned)lb << 16);
}

// ================= MAS + expand =================
__global__ void k_vtrans(const float* __restrict__ val, float* __restrict__ vt,
                         const int* __restrict__ srcL, const int* __restrict__ melL) {
    __shared__ float s[32][33];
    int b = blockIdx.z;
    int x0 = blockIdx.x * 32, y0 = blockIdx.y * 32;
    int sl = srcL[b], ml = melL[b];
    const float* vp = val + (size_t)b * 512 * 1024;
    float* op = vt + (size_t)b * 1024 * 512;
    for (int i = threadIdx.y; i < 32; i += 8) {
        int x = x0 + i, y = y0 + threadIdx.x;
        float v = vp[(size_t)x * 1024 + y];
        s[i][threadIdx.x] = (x < sl && y < ml) ? v : 0.f;
    }
    __syncthreads();
    for (int j = threadIdx.y; j < 32; j += 8)
        op[(size_t)(y0 + j) * 512 + x0 + threadIdx.x] = s[threadIdx.x][j];
}

__global__ void k_masdp(const float* __restrict__ vt, const int* __restrict__ srcL,
                        const int* __restrict__ melL, unsigned* __restrict__ dir) {
    __shared__ float sv[512];
    int b = blockIdx.x, x = threadIdx.x;
    int sl = srcL[b], ml = melL[b];
    int lane = x & 31, wid = x >> 5;
    float v = 0.f;
    for (int j = 0; j < 1024; ++j) {
        sv[x] = v;
        __syncthreads();
        float v0 = x ? sv[x - 1] : NEGF;
        float val = vt[((size_t)b * 1024 + j) * 512 + x];
        bool d = (v >= v0);
        float vmax = d ? v : v0;
        float vnew = (x <= j) ? (vmax + val) : NEGF;
        bool dm = (x < sl && j < ml) ? d : true;
        unsigned bal = __ballot_sync(0xffffffffu, dm);
        if (lane == 0) dir[((size_t)b * 1024 + j) * 16 + wid] = bal;
        v = vnew;
        __syncthreads();
    }
}

__global__ void k_masbt(const unsigned* __restrict__ dir, const int* __restrict__ srcL,
                        int* __restrict__ idxout) {
    int b = threadIdx.x;
    if (b >= 32) return;
    int idx = srcL[b] - 1;
    for (int y = 1023; y >= 0; --y) {
        idxout[b * 1024 + y] = idx;
        unsigned w = dir[((size_t)b * 1024 + y) * 16 + (idx >> 5)];
        idx += (int)((w >> (idx & 31)) & 1u) - 1;
    }
}

__global__ void k_expand(const float* __restrict__ X, const int* __restrict__ idx,
                         const int* __restrict__ srcL, const int* __restrict__ melL,
                         float* __restrict__ out) {
    int row = blockIdx.x;
    int b = row >> 10, y = row & 1023;
    int d = threadIdx.x;
    float o = 0.f;
    if (y < melL[b]) {
        int ix = idx[row];
        if (ix >= 0 && ix < srcL[b])
            o = X[((size_t)(b << 9) + ix) * 256 + d];
    }
    out[(size_t)row * 256 + d] = o;
}

// ================= launch =================
extern "C" void kernel_launch(void* const* d_in, const int* in_sizes, int n_in,
                              void* d_out, int out_size) {
    const int* tokens = (const int*)d_in[0];
    const int* srcL   = (const int*)d_in[1];
    const int* melL   = (const int*)d_in[2];
    const float* value = (const float*)d_in[3];
    const float* embed = (const float*)d_in[4];
    const float* pos   = (const float*)d_in[5];
    const float* wq = (const float*)d_in[6];  const float* bq = (const float*)d_in[7];
    const float* wk = (const float*)d_in[8];  const float* bk = (const float*)d_in[9];
    const float* wv = (const float*)d_in[10]; const float* bv = (const float*)d_in[11];
    const float* wo = (const float*)d_in[12]; const float* bo = (const float*)d_in[13];
    const float* ln1g = (const float*)d_in[14]; const float* ln1b = (const float*)d_in[15];
    const float* c1w = (const float*)d_in[16]; const float* c1b = (const float*)d_in[17];
    const float* c2w = (const float*)d_in[18]; const float* c2b = (const float*)d_in[19];
    const float* ln2g = (const float*)d_in[20]; const float* ln2b = (const float*)d_in[21];
    float* out = (float*)d_out;

    float *px, *pt, *ps, *pvt;
    ushort_t *pxh, *pxl, *pqh, *pql, *pkh, *pkl, *pvh, *pvl, *poh, *pol;
    ushort_t *psh, *psl, *phh, *phl, *pw1h, *pw2h;
    unsigned *pwqh, *pwql, *pwkh, *pwkl, *pwvh, *pwvl, *pwoh, *pwol;
    unsigned* pdir; int* pidx;
    cudaGetSymbolAddress((void**)&px, g_x);   cudaGetSymbolAddress((void**)&pt, g_t);
    cudaGetSymbolAddress((void**)&ps, g_s);   cudaGetSymbolAddress((void**)&pvt, g_vt);
    cudaGetSymbolAddress((void**)&pxh, g_xh); cudaGetSymbolAddress((void**)&pxl, g_xl);
    cudaGetSymbolAddress((void**)&pqh, g_qh); cudaGetSymbolAddress((void**)&pql, g_ql);
    cudaGetSymbolAddress((void**)&pkh, g_kh); cudaGetSymbolAddress((void**)&pkl, g_kl);
    cudaGetSymbolAddress((void**)&pvh, g_vh); cudaGetSymbolAddress((void**)&pvl, g_vl);
    cudaGetSymbolAddress((void**)&poh, g_oh); cudaGetSymbolAddress((void**)&pol, g_ol);
    cudaGetSymbolAddress((void**)&psh, g_sh); cudaGetSymbolAddress((void**)&psl, g_sl);
    cudaGetSymbolAddress((void**)&phh, g_hh); cudaGetSymbolAddress((void**)&phl, g_hl);
    cudaGetSymbolAddress((void**)&pw1h, g_w1h); cudaGetSymbolAddress((void**)&pw2h, g_w2h);
    cudaGetSymbolAddress((void**)&pwqh, g_wqh); cudaGetSymbolAddress((void**)&pwql, g_wql);
    cudaGetSymbolAddress((void**)&pwkh, g_wkh); cudaGetSymbolAddress((void**)&pwkl, g_wkl);
    cudaGetSymbolAddress((void**)&pwvh, g_wvh); cudaGetSymbolAddress((void**)&pwvl, g_wvl);
    cudaGetSymbolAddress((void**)&pwoh, g_woh); cudaGetSymbolAddress((void**)&pwol, g_wol);
    cudaGetSymbolAddress((void**)&pdir, g_dir); cudaGetSymbolAddress((void**)&pidx, g_idx);

    const int SMEMC = 61440;
    cudaFuncSetAttribute(k_conv, cudaFuncAttributeMaxDynamicSharedMemorySize, SMEMC);

    dim3 blk256(256);
    // weight prep
    k_wprep<<<18432, blk256>>>(c1w, pw1h, 1024, 256);
    k_wprep<<<18432, blk256>>>(c2w, pw2h, 256, 1024);
    k_packsplit<<<512, blk256>>>(wq, pwqh, pwql, 8);
    k_packsplit<<<512, blk256>>>(wk, pwkh, pwkl, 8);
    k_packsplit<<<512, blk256>>>(wv, pwvh, pwvl, 8);
    k_packsplit<<<512, blk256>>>(wo, pwoh, pwol, 8);
    // inputs
    k_vtrans<<<dim3(16, 32, 32), dim3(32, 8)>>>(value, pvt, srcL, melL);
    k_embed<<<16384, blk256>>>(tokens, embed, pos, px, pxh, pxl);

    for (int l = 0; l < 4; ++l) {
        const unsigned *wqh_l = pwqh + l * 32768, *wql_l = pwql + l * 32768;
        const unsigned *wkh_l = pwkh + l * 32768, *wkl_l = pwkl + l * 32768;
        const unsigned *wvh_l = pwvh + l * 32768, *wvl_l = pwvl + l * 32768;
        const unsigned *woh_l = pwoh + l * 32768, *wol_l = pwol + l * 32768;

        k_gemm_bias<<<dim3(2, 128), blk256>>>(pxh, pxl, wqh_l, wql_l, bq + l * 256, nullptr, pqh, pql);
        k_gemm_bias<<<dim3(2, 128), blk256>>>(pxh, pxl, wkh_l, wkl_l, bk + l * 256, nullptr, pkh, pkl);
        k_gemm_bias<<<dim3(2, 128), blk256>>>(pxh, pxl, wvh_l, wvl_l, bv + l * 256, nullptr, pvh, pvl);
        k_scores<<<dim3(4, 4, 64), blk256>>>(pqh, pql, pkh, pkl, ps, srcL);
        k_softmax<<<32768, 128>>>(ps, psh, psl);
        k_attnout<<<dim3(1, 4, 64), blk256>>>(psh, psl, pvh, pvl, poh, pol);
        k_gemm_bias<<<dim3(2, 128), blk256>>>(poh, pol, woh_l, wol_l, bo + l * 256, pt, nullptr, nullptr);
        k_lnres<<<16384, blk256>>>(pt, px, ln1g + l * 256, ln1b + l * 256, srcL, px, pxh, pxl);

        k_conv<<<dim3(8, 128), blk256, SMEMC>>>(pxh, pxl, pw1h + (size_t)l * 2359296,
                                                c1b + l * 1024, 256, 3, 1, phh, phl, nullptr, 1024);
        k_conv<<<dim3(2, 128), blk256, SMEMC>>>(phh, phl, pw2h + (size_t)l * 2359296,
                                                c2b + l * 256, 1024, 5, 0, nullptr, nullptr, pt, 256);
        k_lnres<<<16384, blk256>>>(pt, px, ln2g + l * 256, ln2b + l * 256, srcL, px, pxh, pxl);
    }

    k_masdp<<<32, 512>>>(pvt, srcL, melL, pdir);
    k_masbt<<<1, 32>>>(pdir, srcL, pidx);
    k_expand<<<32768, blk256>>>(px, pidx, srcL, melL, out);
}

// round 14
// speedup vs baseline: 1.6358x; 1.0208x over previous
#include <cuda_runtime.h>
#include <cuda_fp16.h>
#include <stdint.h>
#include <math.h>

#define NEGF (-1e9f)
typedef unsigned short ushort_t;

// ---------- scratch ----------
__device__ float    g_x [4194304];
__device__ float    g_t [4194304];
__device__ float    g_s [16777216];
__device__ float    g_vt[16777216];
__device__ ushort_t g_xh[4194304],  g_xl[4194304];
__device__ ushort_t g_qh[4194304],  g_ql[4194304];
__device__ ushort_t g_kh[4194304],  g_kl[4194304];
__device__ ushort_t g_vh[4194304],  g_vl[4194304];
__device__ ushort_t g_oh[4194304],  g_ol[4194304];
__device__ ushort_t g_sh[16777216], g_sl[16777216];
__device__ ushort_t g_hh[16777216], g_hl[16777216];
__device__ ushort_t g_w1h[9437184];   // [L][9][1024][256] fp16 (transposed)
__device__ ushort_t g_w2h[9437184];   // [L][9][256][1024]
__device__ unsigned g_wqh[131072], g_wql[131072], g_wkh[131072], g_wkl[131072];
__device__ unsigned g_wvh[131072], g_wvl[131072], g_woh[131072], g_wol[131072];
__device__ unsigned g_dir[524288];
__device__ int      g_idx[32768];

// ---------- fp16 split helpers ----------
__device__ __forceinline__ void split1(float v, ushort_t& h, ushort_t& l) {
    __half hh = __float2half_rn(v);
    __half ll = __float2half_rn(v - __half2float(hh));
    h = __half_as_ushort(hh); l = __half_as_ushort(ll);
}
__device__ __forceinline__ void wsplit2(ushort_t* Ph, ushort_t* Pl, size_t off,
                                        float v0, float v1) {
    ushort_t h0, l0, h1, l1;
    split1(v0, h0, l0); split1(v1, h1, l1);
    *(unsigned*)&Ph[off] = (unsigned)h0 | ((unsigned)h1 << 16);
    *(unsigned*)&Pl[off] = (unsigned)l0 | ((unsigned)l1 << 16);
}
__device__ __forceinline__ unsigned smem_u32(const void* p) {
    unsigned a;
    asm("{ .reg .u64 t; cvta.to.shared.u64 t, %1; cvt.u32.u64 %0, t; }" : "=r"(a) : "l"(p));
    return a;
}

// ---------- mma core ----------
__device__ __forceinline__ void mma16(float c[4], const unsigned a[4], const unsigned b[2]) {
    asm volatile(
        "mma.sync.aligned.m16n8k16.row.col.f32.f16.f16.f32 "
        "{%0,%1,%2,%3},{%4,%5,%6,%7},{%8,%9},{%0,%1,%2,%3};\n"
        : "+f"(c[0]), "+f"(c[1]), "+f"(c[2]), "+f"(c[3])
        : "r"(a[0]), "r"(a[1]), "r"(a[2]), "r"(a[3]), "r"(b[0]), "r"(b[1]));
}

#define CPA(d, s, n) \
    asm volatile("cp.async.cg.shared.global [%0],[%1],16,%2;" :: "r"(d), "l"(s), "r"(n) : "memory")
#define CPA4(d, s) \
    asm volatile("cp.async.ca.shared.global [%0],[%1],4;" :: "r"(d), "l"(s) : "memory")

// ================= conv: 2-pass fp16 split (aH*bH + aL*bH), K-chunk 32, pipelined =================
// Buffer (30720 B): Ahi[128 rows x 80B] @0 | Alo @10240 | Bhi @20480.  2 buffers = 61440 B dynamic.
__global__ void __launch_bounds__(256, 2)
k_conv(const ushort_t* __restrict__ Ah, const ushort_t* __restrict__ Al,
       const ushort_t* __restrict__ Wh,
       const float* __restrict__ bias, int Cin, int nsh, int relu_split,
       ushort_t* __restrict__ OHh, ushort_t* __restrict__ OHl,
       float* __restrict__ Of, int outld) {
    extern __shared__ __align__(16) char smem[];
    unsigned sbase = smem_u32(smem);
    int tid = threadIdx.x, wd = tid >> 5, lane = tid & 31;
    int wm = wd & 3, wn = wd >> 2, g = lane >> 2, tig = lane & 3;
    int n0 = blockIdx.x * 128, m0 = blockIdx.y * 128;
    int Coutv = gridDim.x * 128;
    int bbase = m0 & ~511, tb = m0 & 511;
    int ncmask = (1 << nsh) - 1;
    int NIT = 9 << nsh;
    int lrow = tid >> 1, lhalf = tid & 1;
    size_t wstr = (size_t)Coutv * Cin;
    float acc[16][4] = {};

#define ISSUE(itv, bo) do {                                                   \
        int dk_ = (itv) >> nsh; int kc_ = ((itv) & ncmask) << 5;              \
        int t_ = tb + lrow + dk_ - 4;                                         \
        unsigned okn = ((unsigned)t_ < 512u) ? 16u : 0u;                      \
        size_t ar_ = (size_t)(bbase + t_) * Cin + kc_ + lhalf * 16;          \
        unsigned da_ = sbase + (bo) + lrow * 80 + lhalf * 32;                 \
        CPA(da_, Ah + ar_, okn);        CPA(da_ + 16, Ah + ar_ + 8, okn);     \
        CPA(da_ + 10240, Al + ar_, okn); CPA(da_ + 10256, Al + ar_ + 8, okn); \
        size_t wr_ = (size_t)dk_ * wstr + (size_t)(n0 + lrow) * Cin + kc_ + lhalf * 16; \
        CPA(da_ + 20480, Wh + wr_, 16u); CPA(da_ + 20496, Wh + wr_ + 8, 16u); \
    } while (0)

    ISSUE(0, 0);
    asm volatile("cp.async.commit_group;" ::: "memory");
    for (int it = 0; it < NIT; ++it) {
        int cbo = (it & 1) * 30720, nbo = 30720 - cbo;
        if (it + 1 < NIT) {
            ISSUE(it + 1, nbo);
            asm volatile("cp.async.commit_group;" ::: "memory");
            asm volatile("cp.async.wait_group 1;" ::: "memory");
        } else {
            asm volatile("cp.async.wait_group 0;" ::: "memory");
        }
        __syncthreads();
        const unsigned* AH = (const unsigned*)(smem + cbo);
        const unsigned* AL = (const unsigned*)(smem + cbo + 10240);
        const unsigned* BH = (const unsigned*)(smem + cbo + 20480);
        unsigned aH0[2][4], aH1[2][4], aL0[2][4], aL1[2][4];
#pragma unroll
        for (int i = 0; i < 2; ++i) {
            int r = wm * 32 + i * 16 + g;
            int b0 = r * 20 + tig, b1 = (r + 8) * 20 + tig;
            aH0[i][0] = AH[b0];     aH0[i][1] = AH[b1];
            aH0[i][2] = AH[b0 + 4]; aH0[i][3] = AH[b1 + 4];
            aH1[i][0] = AH[b0 + 8];  aH1[i][1] = AH[b1 + 8];
            aH1[i][2] = AH[b0 + 12]; aH1[i][3] = AH[b1 + 12];
            aL0[i][0] = AL[b0];     aL0[i][1] = AL[b1];
            aL0[i][2] = AL[b0 + 4]; aL0[i][3] = AL[b1 + 4];
            aL1[i][0] = AL[b0 + 8];  aL1[i][1] = AL[b1 + 8];
            aL1[i][2] = AL[b0 + 12]; aL1[i][3] = AL[b1 + 12];
        }
#pragma unroll
        for (int j = 0; j < 8; ++j) {
            int c = (wn * 64 + j * 8 + g) * 20 + tig;
            unsigned bF0[2] = {BH[c], BH[c + 4]};
            unsigned bF1[2] = {BH[c + 8], BH[c + 12]};
#pragma unroll
            for (int i = 0; i < 2; ++i) {
                mma16(acc[i * 8 + j], aH0[i], bF0);
                mma16(acc[i * 8 + j], aH1[i], bF1);
                mma16(acc[i * 8 + j], aL0[i], bF0);
                mma16(acc[i * 8 + j], aL1[i], bF1);
            }
        }
        __syncthreads();
    }
#undef ISSUE
#pragma unroll
    for (int i = 0; i < 2; ++i)
#pragma unroll
        for (int j = 0; j < 8; ++j) {
            int m = m0 + wm * 32 + i * 16 + g;
            int n = n0 + wn * 64 + j * 8 + 2 * tig;
            float* a = acc[i * 8 + j];
            float b0 = bias[n], b1 = bias[n + 1];
            float v0 = a[0] + b0, v1 = a[1] + b1, v2 = a[2] + b0, v3 = a[3] + b1;
            size_t o0 = (size_t)m * outld + n, o1 = (size_t)(m + 8) * outld + n;
            if (relu_split) {
                v0 = fmaxf(v0, 0.f); v1 = fmaxf(v1, 0.f);
                v2 = fmaxf(v2, 0.f); v3 = fmaxf(v3, 0.f);
                wsplit2(OHh, OHl, o0, v0, v1);
                wsplit2(OHh, OHl, o1, v2, v3);
            } else {
                *(float2*)&Of[o0] = make_float2(v0, v1);
                *(float2*)&Of[o1] = make_float2(v2, v3);
            }
        }
}

// conv weight prep: src[l][R][C][9] fp32 -> Wh [l][9][R][C] fp16 (hi only)
__global__ void k_wprep(const float* __restrict__ src, ushort_t* __restrict__ Wh,
                        int R, int C) {
    size_t idx = ((size_t)blockIdx.x * 256 + threadIdx.x) * 2;
    int c = (int)(idx % C);
    size_t t1 = idx / C;
    int r = (int)(t1 % R);
    size_t t2 = t1 / R;
    int dk = (int)(t2 % 9);
    int l = (int)(t2 / 9);
    size_t sb = (((size_t)l * R + r) * C + c) * 9 + dk;
    __half h0 = __float2half_rn(src[sb]), h1 = __float2half_rn(src[sb + 9]);
    *(unsigned*)&Wh[idx] = (unsigned)__half_as_ushort(h0) | ((unsigned)__half_as_ushort(h1) << 16);
}

// ================= mma.sync attention (3-pass) =================
__device__ __forceinline__ void mma_tile16(const unsigned* AsH, const unsigned* AsL,
                                           const unsigned* BsH, const unsigned* BsL,
                                           int wm, int wn, int g, int tig,
                                           float (*acc)[4]) {
    unsigned aH[2][4], aL[2][4];
#pragma unroll
    for (int i = 0; i < 2; ++i) {
        int r = (wm * 32 + i * 16 + g) * 12 + tig;
        aH[i][0] = AsH[r]; aH[i][1] = AsH[r + 96]; aH[i][2] = AsH[r + 4]; aH[i][3] = AsH[r + 100];
        aL[i][0] = AsL[r]; aL[i][1] = AsL[r + 96]; aL[i][2] = AsL[r + 4]; aL[i][3] = AsL[r + 100];
    }
#pragma unroll
    for (int j = 0; j < 8; ++j) {
        int nb = wn * 64 + j * 8 + g;
        unsigned bH[2] = {BsH[tig * 136 + nb], BsH[(tig + 4) * 136 + nb]};
        unsigned bL[2] = {BsL[tig * 136 + nb], BsL[(tig + 4) * 136 + nb]};
#pragma unroll
        for (int i = 0; i < 2; ++i) {
            mma16(acc[i * 8 + j], aH[i], bH);
            mma16(acc[i * 8 + j], aL[i], bH);
            mma16(acc[i * 8 + j], aH[i], bL);
        }
    }
}

// pipelined projection GEMM: buffer = AsH 6144 | AsL 6144 | BsH 4352 | BsL 4352 = 20992 B
__global__ void __launch_bounds__(256, 2)
k_gemm_bias(const ushort_t* __restrict__ Ah, const ushort_t* __restrict__ Al,
            const unsigned* __restrict__ Bph, const unsigned* __restrict__ Bpl,
            const float* __restrict__ bias, float* __restrict__ Cf,
            ushort_t* __restrict__ Ch, ushort_t* __restrict__ Cl) {
    __shared__ __align__(16) char smem[41984];
    unsigned sbase = smem_u32(smem);
    int tid = threadIdx.x, w = tid >> 5, lane = tid & 31;
    int wm = w & 3, wn = w >> 2, g = lane >> 2, tig = lane & 3;
    int n0 = blockIdx.x * 128, m0 = blockIdx.y * 128;
    int arow = tid >> 1, apart = tid & 1;
    int bp = tid >> 5;
    float acc[16][4] = {};
#define GISSUE(k0v, bo) do {                                                  \
        size_t aoff = (size_t)(m0 + arow) * 256 + (k0v) + apart * 8;          \
        unsigned da = sbase + (bo) + arow * 48 + apart * 16;                  \
        CPA(da, Ah + aoff, 16u); CPA(da + 6144, Al + aoff, 16u);              \
        size_t boff = (size_t)((k0v) / 2 + bp) * 256 + n0 + lane * 4;         \
        unsigned db = sbase + (bo) + 12288 + bp * 544 + lane * 16;            \
        CPA(db, Bph + boff, 16u); CPA(db + 4352, Bpl + boff, 16u);            \
    } while (0)
    GISSUE(0, 0);
    asm volatile("cp.async.commit_group;" ::: "memory");
    for (int it = 0; it < 16; ++it) {
        int cbo = (it & 1) * 20992, nbo = 20992 - cbo;
        if (it < 15) {
            GISSUE((it + 1) * 16, nbo);
            asm volatile("cp.async.commit_group;" ::: "memory");
            asm volatile("cp.async.wait_group 1;" ::: "memory");
        } else {
            asm volatile("cp.async.wait_group 0;" ::: "memory");
        }
        __syncthreads();
        mma_tile16((const unsigned*)(smem + cbo), (const unsigned*)(smem + cbo + 6144),
                   (const unsigned*)(smem + cbo + 12288), (const unsigned*)(smem + cbo + 16640),
                   wm, wn, g, tig, acc);
        __syncthreads();
    }
#undef GISSUE
#pragma unroll
    for (int i = 0; i < 2; ++i)
#pragma unroll
        for (int j = 0; j < 8; ++j) {
            int m = m0 + wm * 32 + i * 16 + g;
            int n = n0 + wn * 64 + j * 8 + 2 * tig;
            float b0 = bias[n], b1 = bias[n + 1];
            float* a = acc[i * 8 + j];
            float v0 = a[0] + b0, v1 = a[1] + b1, v2 = a[2] + b0, v3 = a[3] + b1;
            if (Cf) {
                *(float2*)&Cf[(size_t)m * 256 + n] = make_float2(v0, v1);
                *(float2*)&Cf[(size_t)(m + 8) * 256 + n] = make_float2(v2, v3);
            }
            if (Ch) {
                wsplit2(Ch, Cl, (size_t)m * 256 + n, v0, v1);
                wsplit2(Ch, Cl, (size_t)(m + 8) * 256 + n, v2, v3);
            }
        }
}

// pipelined scores
__global__ void __launch_bounds__(256, 2)
k_scores(const ushort_t* __restrict__ Qh, const ushort_t* __restrict__ Ql,
         const ushort_t* __restrict__ Kh, const ushort_t* __restrict__ Kl,
         float* __restrict__ S, const int* __restrict__ srcL) {
    __shared__ __align__(16) char smem[41984];
    unsigned sbase = smem_u32(smem);
    int tid = threadIdx.x, w = tid >> 5, lane = tid & 31;
    int wm = w & 3, wn = w >> 2, g = lane >> 2, tig = lane & 3;
    int n0 = blockIdx.x * 128, m0 = blockIdx.y * 128, bh = blockIdx.z;
    int b = bh >> 1, h = bh & 1;
    int arow = tid >> 1, apart = tid & 1;
    int btn = tid & 127, bpb = (tid >> 7) * 4;
    float acc[16][4] = {};
#define SISSUE(k0v, bo) do {                                                  \
        size_t aoff = (size_t)(b * 512 + m0 + arow) * 256 + h * 128 + (k0v) + apart * 8; \
        unsigned da = sbase + (bo) + arow * 48 + apart * 16;                  \
        CPA(da, Qh + aoff, 16u); CPA(da + 6144, Ql + aoff, 16u);              \
        size_t koff = (size_t)(b * 512 + n0 + btn) * 256 + h * 128 + (k0v) + bpb * 2; \
        const char* ksrc = (const char*)(Kh + koff);                          \
        const char* lsrc = (const char*)(Kl + koff);                          \
        _Pragma("unroll")                                                     \
        for (int i_ = 0; i_ < 4; ++i_) {                                      \
            unsigned db = sbase + (bo) + 12288 + ((bpb + i_) * 136 + btn) * 4; \
            CPA4(db, ksrc + i_ * 4);                                          \
            CPA4(db + 4352, lsrc + i_ * 4);                                   \
        }                                                                     \
    } while (0)
    SISSUE(0, 0);
    asm volatile("cp.async.commit_group;" ::: "memory");
    for (int it = 0; it < 8; ++it) {
        int cbo = (it & 1) * 20992, nbo = 20992 - cbo;
        if (it < 7) {
            SISSUE((it + 1) * 16, nbo);
            asm volatile("cp.async.commit_group;" ::: "memory");
            asm volatile("cp.async.wait_group 1;" ::: "memory");
        } else {
            asm volatile("cp.async.wait_group 0;" ::: "memory");
        }
        __syncthreads();
        mma_tile16((const unsigned*)(smem + cbo), (const unsigned*)(smem + cbo + 6144),
                   (const unsigned*)(smem + cbo + 12288), (const unsigned*)(smem + cbo + 16640),
                   wm, wn, g, tig, acc);
        __syncthreads();
    }
#undef SISSUE
    int sl = srcL[b];
    const float scale = 0.08838834764831845f;
#pragma unroll
    for (int i = 0; i < 2; ++i)
#pragma unroll
        for (int j = 0; j < 8; ++j) {
            int m = m0 + wm * 32 + i * 16 + g;
            int n = n0 + wn * 64 + j * 8 + 2 * tig;
            float* a = acc[i * 8 + j];
            bool p0 = (n >= sl), p1 = (n + 1 >= sl);
            float2 r0 = {p0 ? NEGF : a[0] * scale, p1 ? NEGF : a[1] * scale};
            float2 r1 = {p0 ? NEGF : a[2] * scale, p1 ? NEGF : a[3] * scale};
            *(float2*)&S[((size_t)bh * 512 + m) * 512 + n] = r0;
            *(float2*)&S[((size_t)bh * 512 + m + 8) * 512 + n] = r1;
        }
}

__global__ void __launch_bounds__(256, 2)
k_attnout(const ushort_t* __restrict__ Sh, const ushort_t* __restrict__ Sl,
          const ushort_t* __restrict__ Vh, const ushort_t* __restrict__ Vl,
          ushort_t* __restrict__ Oh, ushort_t* __restrict__ Ol) {
    __shared__ unsigned AsH[1536], AsL[1536], BsH[1088], BsL[1088];
    int tid = threadIdx.x, w = tid >> 5, lane = tid & 31;
    int wm = w & 3, wn = w >> 2, g = lane >> 2, tig = lane & 3;
    int m0 = blockIdx.y * 128, bh = blockIdx.z;
    int b = bh >> 1, h = bh & 1;
    int arow = tid >> 1, apart = tid & 1;
    int bp = tid >> 5, bc = lane * 4;
    float acc[16][4] = {};
    for (int k0 = 0; k0 < 512; k0 += 16) {
        size_t aoff = ((size_t)bh * 512 + m0 + arow) * 512 + k0 + apart * 8;
        uint4 ah = *(const uint4*)(Sh + aoff);
        uint4 al = *(const uint4*)(Sl + aoff);
        const ushort_t* r0h = Vh + (size_t)(b * 512 + k0 + 2 * bp) * 256 + h * 128 + bc;
        uint2 uah = *(const uint2*)r0h, ubh = *(const uint2*)(r0h + 256);
        const ushort_t* r0l = Vl + (size_t)(b * 512 + k0 + 2 * bp) * 256 + h * 128 + bc;
        uint2 ual = *(const uint2*)r0l, ubl = *(const uint2*)(r0l + 256);
        __syncthreads();
        *(uint4*)&AsH[arow * 12 + apart * 4] = ah;
        *(uint4*)&AsL[arow * 12 + apart * 4] = al;
        BsH[bp * 136 + bc + 0] = (uah.x & 0xFFFFu) | (ubh.x << 16);
        BsH[bp * 136 + bc + 1] = (uah.x >> 16) | (ubh.x & 0xFFFF0000u);
        BsH[bp * 136 + bc + 2] = (uah.y & 0xFFFFu) | (ubh.y << 16);
        BsH[bp * 136 + bc + 3] = (uah.y >> 16) | (ubh.y & 0xFFFF0000u);
        BsL[bp * 136 + bc + 0] = (ual.x & 0xFFFFu) | (ubl.x << 16);
        BsL[bp * 136 + bc + 1] = (ual.x >> 16) | (ubl.x & 0xFFFF0000u);
        BsL[bp * 136 + bc + 2] = (ual.y & 0xFFFFu) | (ubl.y << 16);
        BsL[bp * 136 + bc + 3] = (ual.y >> 16) | (ubl.y & 0xFFFF0000u);
        __syncthreads();
        mma_tile16(AsH, AsL, BsH, BsL, wm, wn, g, tig, acc);
    }
#pragma unroll
    for (int i = 0; i < 2; ++i)
#pragma unroll
        for (int j = 0; j < 8; ++j) {
            int m = m0 + wm * 32 + i * 16 + g;
            int n = h * 128 + wn * 64 + j * 8 + 2 * tig;
            float* a = acc[i * 8 + j];
            wsplit2(Oh, Ol, (size_t)(b * 512 + m) * 256 + n, a[0], a[1]);
            wsplit2(Oh, Ol, (size_t)(b * 512 + m + 8) * 256 + n, a[2], a[3]);
        }
}

// ================= producers / elementwise =================
__global__ void k_embed(const int* __restrict__ tok, const float* __restrict__ emb,
                        const float* __restrict__ pos, float* __restrict__ x,
                        ushort_t* __restrict__ xh, ushort_t* __restrict__ xl) {
    int row = blockIdx.x, d = threadIdx.x;
    int t = row & 511;
    int id = tok[row];
    size_t off = (size_t)row * 256 + d;
    float v = emb[(size_t)id * 256 + d] + pos[(size_t)t * 256 + d];
    x[off] = v;
    ushort_t h, l; split1(v, h, l);
    xh[off] = h; xl[off] = l;
}

__global__ void k_softmax(const float* __restrict__ S, ushort_t* __restrict__ Sh,
                          ushort_t* __restrict__ Sl) {
    __shared__ float red[4];
    size_t row = blockIdx.x;
    float4 v = ((const float4*)(S + row * 512))[threadIdx.x];
    int lane = threadIdx.x & 31, wid = threadIdx.x >> 5;
    float m = fmaxf(fmaxf(v.x, v.y), fmaxf(v.z, v.w));
#pragma unroll
    for (int o = 16; o > 0; o >>= 1) m = fmaxf(m, __shfl_xor_sync(~0u, m, o));
    if (lane == 0) red[wid] = m;
    __syncthreads();
    m = fmaxf(fmaxf(red[0], red[1]), fmaxf(red[2], red[3]));
    __syncthreads();
    v.x = expf(v.x - m); v.y = expf(v.y - m); v.z = expf(v.z - m); v.w = expf(v.w - m);
    float s = v.x + v.y + v.z + v.w;
#pragma unroll
    for (int o = 16; o > 0; o >>= 1) s += __shfl_xor_sync(~0u, s, o);
    if (lane == 0) red[wid] = s;
    __syncthreads();
    s = red[0] + red[1] + red[2] + red[3];
    float inv = 1.0f / s;
    size_t off = row * 512 + threadIdx.x * 4;
    wsplit2(Sh, Sl, off, v.x * inv, v.y * inv);
    wsplit2(Sh, Sl, off + 2, v.z * inv, v.w * inv);
}

__global__ void k_lnres(const float* __restrict__ t, const float* __restrict__ res,
                        const float* __restrict__ gam, const float* __restrict__ bet,
                        const int* __restrict__ srcL, float* __restrict__ out,
                        ushort_t* __restrict__ oh, ushort_t* __restrict__ ol) {
    __shared__ float red[8];
    int row = blockIdx.x, d = threadIdx.x;
    size_t off = (size_t)row * 256 + d;
    float val = t[off] + res[off];
    float s = val;
#pragma unroll
    for (int o = 16; o > 0; o >>= 1) s += __shfl_xor_sync(~0u, s, o);
    if ((d & 31) == 0) red[d >> 5] = s;
    __syncthreads();
    float tot = 0.f;
#pragma unroll
    for (int i = 0; i < 8; ++i) tot += red[i];
    float mean = tot * (1.0f / 256.0f);
    float dv = val - mean;
    __syncthreads();
    float s2 = dv * dv;
#pragma unroll
    for (int o = 16; o > 0; o >>= 1) s2 += __shfl_xor_sync(~0u, s2, o);
    if ((d & 31) == 0) red[d >> 5] = s2;
    __syncthreads();
    float tot2 = 0.f;
#pragma unroll
    for (int i = 0; i < 8; ++i) tot2 += red[i];
    float o = dv * rsqrtf(tot2 * (1.0f / 256.0f) + 1e-5f) * gam[d] + bet[d];
    if ((row & 511) >= srcL[row >> 9]) o = 0.f;
    out[off] = o;
    ushort_t h, l; split1(o, h, l);
    oh[off] = h; ol[off] = l;
}

__global__ void k_packsplit(const float* __restrict__ src, unsigned* __restrict__ Uh,
                            unsigned* __restrict__ Ul, int nshift) {
    size_t idx = (size_t)blockIdx.x * 256 + threadIdx.x;
    size_t kp = idx >> nshift;
    int n = (int)(idx & ((1u << nshift) - 1));
    size_t N = (size_t)1 << nshift;
    float a = src[(2 * kp) * N + n], b = src[(2 * kp + 1) * N + n];
    ushort_t ha, la, hb, lb;
    split1(a, ha, la); split1(b, hb, lb);
    Uh[idx] = (unsigned)ha | ((unsigned)hb << 16);
    Ul[idx] = (unsigned)la | ((unsigned)lb << 16);
}

// ================= MAS + expand =================
__global__ void k_vtrans(const float* __restrict__ val, float* __restrict__ vt,
                         const int* __restrict__ srcL, const int* __restrict__ melL) {
    __shared__ float s[32][33];
    int b = blockIdx.z;
    int x0 = blockIdx.x * 32, y0 = blockIdx.y * 32;
    int sl = srcL[b], ml = melL[b];
    const float* vp = val + (size_t)b * 512 * 1024;
    float* op = vt + (size_t)b * 1024 * 512;
    for (int i = threadIdx.y; i < 32; i += 8) {
        int x = x0 + i, y = y0 + threadIdx.x;
        float v = vp[(size_t)x * 1024 + y];
        s[i][threadIdx.x] = (x < sl && y < ml) ? v : 0.f;
    }
    __syncthreads();
    for (int j = threadIdx.y; j < 32; j += 8)
        op[(size_t)(y0 + j) * 512 + x0 + threadIdx.x] = s[threadIdx.x][j];
}

// one-sync DP: boundary via shfl + double-buffered per-warp edge values; val prefetched
__global__ void k_masdp(const float* __restrict__ vt, const int* __restrict__ srcL,
                        const int* __restrict__ melL, unsigned* __restrict__ dir) {
    __shared__ float bnd[2][16];
    int b = blockIdx.x, x = threadIdx.x;
    int sl = srcL[b], ml = melL[b];
    int lane = x & 31, wid = x >> 5;
    float v = 0.f;
    float val = vt[(size_t)b * 1024 * 512 + x];
    for (int j = 0; j < 1024; ++j) {
        if (lane == 31) bnd[j & 1][wid] = v;
        __syncthreads();
        float v0 = __shfl_up_sync(0xffffffffu, v, 1);
        if (lane == 0) v0 = wid ? bnd[j & 1][wid - 1] : NEGF;
        float valn = 0.f;
        if (j + 1 < 1024) valn = vt[((size_t)b * 1024 + j + 1) * 512 + x];
        bool d = (v >= v0);
        float vmax = d ? v : v0;
        float vnew = (x <= j) ? (vmax + val) : NEGF;
        bool dm = (x < sl && j < ml) ? d : true;
        unsigned bal = __ballot_sync(0xffffffffu, dm);
        if (lane == 0) dir[((size_t)b * 1024 + j) * 16 + wid] = bal;
        v = vnew;
        val = valn;
    }
}

// grouped-prefetch backtrack: over 8 steps idx drops <=7, so word is w0 or w0-1
__global__ void k_masbt(const unsigned* __restrict__ dir, const int* __restrict__ srcL,
                        int* __restrict__ idxout) {
    int b = threadIdx.x;
    if (b >= 32) return;
    int idx = srcL[b] - 1;
    for (int y0 = 1023; y0 >= 0; y0 -= 8) {
        int w0 = idx >> 5;
        unsigned wA[8], wB[8];
#pragma unroll
        for (int d = 0; d < 8; ++d) {
            size_t base = ((size_t)b * 1024 + (y0 - d)) * 16;
            wA[d] = dir[base + w0];
            wB[d] = (w0 > 0) ? dir[base + w0 - 1] : 0u;
        }
#pragma unroll
        for (int d = 0; d < 8; ++d) {
            int y = y0 - d;
            idxout[b * 1024 + y] = idx;
            int wcur = idx >> 5;
            unsigned word = (wcur == w0) ? wA[d] : wB[d];
            idx += (int)((word >> (idx & 31)) & 1u) - 1;
        }
    }
}

__global__ void k_expand(const float* __restrict__ X, const int* __restrict__ idx,
                         const int* __restrict__ srcL, const int* __restrict__ melL,
                         float* __restrict__ out) {
    int row = blockIdx.x;
    int b = row >> 10, y = row & 1023;
    int d = threadIdx.x;
    float o = 0.f;
    if (y < melL[b]) {
        int ix = idx[row];
        if (ix >= 0 && ix < srcL[b])
            o = X[((size_t)(b << 9) + ix) * 256 + d];
    }
    out[(size_t)row * 256 + d] = o;
}

// ================= launch =================
extern "C" void kernel_launch(void* const* d_in, const int* in_sizes, int n_in,
                              void* d_out, int out_size) {
    const int* tokens = (const int*)d_in[0];
    const int* srcL   = (const int*)d_in[1];
    const int* melL   = (const int*)d_in[2];
    const float* value = (const float*)d_in[3];
    const float* embed = (const float*)d_in[4];
    const float* pos   = (const float*)d_in[5];
    const float* wq = (const float*)d_in[6];  const float* bq = (const float*)d_in[7];
    const float* wk = (const float*)d_in[8];  const float* bk = (const float*)d_in[9];
    const float* wv = (const float*)d_in[10]; const float* bv = (const float*)d_in[11];
    const float* wo = (const float*)d_in[12]; const float* bo = (const float*)d_in[13];
    const float* ln1g = (const float*)d_in[14]; const float* ln1b = (const float*)d_in[15];
    const float* c1w = (const float*)d_in[16]; const float* c1b = (const float*)d_in[17];
    const float* c2w = (const float*)d_in[18]; const float* c2b = (const float*)d_in[19];
    const float* ln2g = (const float*)d_in[20]; const float* ln2b = (const float*)d_in[21];
    float* out = (float*)d_out;

    float *px, *pt, *ps, *pvt;
    ushort_t *pxh, *pxl, *pqh, *pql, *pkh, *pkl, *pvh, *pvl, *poh, *pol;
    ushort_t *psh, *psl, *phh, *phl, *pw1h, *pw2h;
    unsigned *pwqh, *pwql, *pwkh, *pwkl, *pwvh, *pwvl, *pwoh, *pwol;
    unsigned* pdir; int* pidx;
    cudaGetSymbolAddress((void**)&px, g_x);   cudaGetSymbolAddress((void**)&pt, g_t);
    cudaGetSymbolAddress((void**)&ps, g_s);   cudaGetSymbolAddress((void**)&pvt, g_vt);
    cudaGetSymbolAddress((void**)&pxh, g_xh); cudaGetSymbolAddress((void**)&pxl, g_xl);
    cudaGetSymbolAddress((void**)&pqh, g_qh); cudaGetSymbolAddress((void**)&pql, g_ql);
    cudaGetSymbolAddress((void**)&pkh, g_kh); cudaGetSymbolAddress((void**)&pkl, g_kl);
    cudaGetSymbolAddress((void**)&pvh, g_vh); cudaGetSymbolAddress((void**)&pvl, g_vl);
    cudaGetSymbolAddress((void**)&poh, g_oh); cudaGetSymbolAddress((void**)&pol, g_ol);
    cudaGetSymbolAddress((void**)&psh, g_sh); cudaGetSymbolAddress((void**)&psl, g_sl);
    cudaGetSymbolAddress((void**)&phh, g_hh); cudaGetSymbolAddress((void**)&phl, g_hl);
    cudaGetSymbolAddress((void**)&pw1h, g_w1h); cudaGetSymbolAddress((void**)&pw2h, g_w2h);
    cudaGetSymbolAddress((void**)&pwqh, g_wqh); cudaGetSymbolAddress((void**)&pwql, g_wql);
    cudaGetSymbolAddress((void**)&pwkh, g_wkh); cudaGetSymbolAddress((void**)&pwkl, g_wkl);
    cudaGetSymbolAddress((void**)&pwvh, g_wvh); cudaGetSymbolAddress((void**)&pwvl, g_wvl);
    cudaGetSymbolAddress((void**)&pwoh, g_woh); cudaGetSymbolAddress((void**)&pwol, g_wol);
    cudaGetSymbolAddress((void**)&pdir, g_dir); cudaGetSymbolAddress((void**)&pidx, g_idx);

    const int SMEMC = 61440;
    cudaFuncSetAttribute(k_conv, cudaFuncAttributeMaxDynamicSharedMemorySize, SMEMC);

    dim3 blk256(256);
    // weight prep
    k_wprep<<<18432, blk256>>>(c1w, pw1h, 1024, 256);
    k_wprep<<<18432, blk256>>>(c2w, pw2h, 256, 1024);
    k_packsplit<<<512, blk256>>>(wq, pwqh, pwql, 8);
    k_packsplit<<<512, blk256>>>(wk, pwkh, pwkl, 8);
    k_packsplit<<<512, blk256>>>(wv, pwvh, pwvl, 8);
    k_packsplit<<<512, blk256>>>(wo, pwoh, pwol, 8);
    // inputs
    k_vtrans<<<dim3(16, 32, 32), dim3(32, 8)>>>(value, pvt, srcL, melL);
    k_embed<<<16384, blk256>>>(tokens, embed, pos, px, pxh, pxl);

    for (int l = 0; l < 4; ++l) {
        const unsigned *wqh_l = pwqh + l * 32768, *wql_l = pwql + l * 32768;
        const unsigned *wkh_l = pwkh + l * 32768, *wkl_l = pwkl + l * 32768;
        const unsigned *wvh_l = pwvh + l * 32768, *wvl_l = pwvl + l * 32768;
        const unsigned *woh_l = pwoh + l * 32768, *wol_l = pwol + l * 32768;

        k_gemm_bias<<<dim3(2, 128), blk256>>>(pxh, pxl, wqh_l, wql_l, bq + l * 256, nullptr, pqh, pql);
        k_gemm_bias<<<dim3(2, 128), blk256>>>(pxh, pxl, wkh_l, wkl_l, bk + l * 256, nullptr, pkh, pkl);
        k_gemm_bias<<<dim3(2, 128), blk256>>>(pxh, pxl, wvh_l, wvl_l, bv + l * 256, nullptr, pvh, pvl);
        k_scores<<<dim3(4, 4, 64), blk256>>>(pqh, pql, pkh, pkl, ps, srcL);
        k_softmax<<<32768, 128>>>(ps, psh, psl);
        k_attnout<<<dim3(1, 4, 64), blk256>>>(psh, psl, pvh, pvl, poh, pol);
        k_gemm_bias<<<dim3(2, 128), blk256>>>(poh, pol, woh_l, wol_l, bo + l * 256, pt, nullptr, nullptr);
        k_lnres<<<16384, blk256>>>(pt, px, ln1g + l * 256, ln1b + l * 256, srcL, px, pxh, pxl);

        k_conv<<<dim3(8, 128), blk256, SMEMC>>>(pxh, pxl, pw1h + (size_t)l * 2359296,
                                                c1b + l * 1024, 256, 3, 1, phh, phl, nullptr, 1024);
        k_conv<<<dim3(2, 128), blk256, SMEMC>>>(phh, phl, pw2h + (size_t)l * 2359296,
                                                c2b + l * 256, 1024, 5, 0, nullptr, nullptr, pt, 256);
        k_lnres<<<16384, blk256>>>(pt, px, ln2g + l * 256, ln2b + l * 256, srcL, px, pxh, pxl);
    }

    k_masdp<<<32, 512>>>(pvt, srcL, melL, pdir);
    k_masbt<<<1, 32>>>(pdir, srcL, pidx);
    k_expand<<<32768, blk256>>>(px, pidx, srcL, melL, out);
}

// round 15
// speedup vs baseline: 2.2698x; 1.3876x over previous
#include <cuda_runtime.h>
#include <cuda_fp16.h>
#include <stdint.h>
#include <math.h>

#define NEGF (-1e9f)
typedef unsigned short ushort_t;

// ---------- scratch ----------
__device__ float    g_x [4194304];
__device__ float    g_t [4194304];
__device__ float    g_s [16777216];
__device__ float    g_vt[16777216];
__device__ ushort_t g_xh[4194304],  g_xl[4194304];
__device__ ushort_t g_qh[4194304],  g_ql[4194304];
__device__ ushort_t g_kh[4194304],  g_kl[4194304];
__device__ ushort_t g_vh[4194304],  g_vl[4194304];
__device__ ushort_t g_oh[4194304],  g_ol[4194304];
__device__ ushort_t g_sh[16777216], g_sl[16777216];
__device__ ushort_t g_hh[16777216];
__device__ ushort_t g_w1h[9437184];   // [L][9][1024][256] fp16 (transposed)
__device__ ushort_t g_w2h[9437184];   // [L][9][256][1024]
__device__ unsigned g_wqh[131072], g_wql[131072], g_wkh[131072], g_wkl[131072];
__device__ unsigned g_wvh[131072], g_wvl[131072], g_woh[131072], g_wol[131072];
__device__ unsigned g_dir[524288];
__device__ int      g_idx[32768];

// ---------- fp16 split helpers ----------
__device__ __forceinline__ void split1(float v, ushort_t& h, ushort_t& l) {
    __half hh = __float2half_rn(v);
    __half ll = __float2half_rn(v - __half2float(hh));
    h = __half_as_ushort(hh); l = __half_as_ushort(ll);
}
__device__ __forceinline__ void wsplit2(ushort_t* Ph, ushort_t* Pl, size_t off,
                                        float v0, float v1) {
    ushort_t h0, l0, h1, l1;
    split1(v0, h0, l0); split1(v1, h1, l1);
    *(unsigned*)&Ph[off] = (unsigned)h0 | ((unsigned)h1 << 16);
    *(unsigned*)&Pl[off] = (unsigned)l0 | ((unsigned)l1 << 16);
}
__device__ __forceinline__ unsigned smem_u32(const void* p) {
    unsigned a;
    asm("{ .reg .u64 t; cvta.to.shared.u64 t, %1; cvt.u32.u64 %0, t; }" : "=r"(a) : "l"(p));
    return a;
}

// ---------- mma core ----------
__device__ __forceinline__ void mma16(float c[4], const unsigned a[4], const unsigned b[2]) {
    asm volatile(
        "mma.sync.aligned.m16n8k16.row.col.f32.f16.f16.f32 "
        "{%0,%1,%2,%3},{%4,%5,%6,%7},{%8,%9},{%0,%1,%2,%3};\n"
        : "+f"(c[0]), "+f"(c[1]), "+f"(c[2]), "+f"(c[3])
        : "r"(a[0]), "r"(a[1]), "r"(a[2]), "r"(a[3]), "r"(b[0]), "r"(b[1]));
}

#define CPA(d, s, n) \
    asm volatile("cp.async.cg.shared.global [%0],[%1],16,%2;" :: "r"(d), "l"(s), "r"(n) : "memory")
#define CPA4(d, s) \
    asm volatile("cp.async.ca.shared.global [%0],[%1],4;" :: "r"(d), "l"(s) : "memory")

// ================= conv: pure fp16 (aH*bH), K-chunk 32, pipelined =================
// Buffer (20480 B): Ahi[128 rows x 80B] @0 | Bhi @10240.  2 buffers = 40960 B dynamic.
__global__ void __launch_bounds__(256, 2)
k_conv(const ushort_t* __restrict__ Ah,
       const ushort_t* __restrict__ Wh,
       const float* __restrict__ bias, int Cin, int nsh, int relu_split,
       ushort_t* __restrict__ OHh,
       float* __restrict__ Of, int outld) {
    extern __shared__ __align__(16) char smem[];
    unsigned sbase = smem_u32(smem);
    int tid = threadIdx.x, wd = tid >> 5, lane = tid & 31;
    int wm = wd & 3, wn = wd >> 2, g = lane >> 2, tig = lane & 3;
    int n0 = blockIdx.x * 128, m0 = blockIdx.y * 128;
    int Coutv = gridDim.x * 128;
    int bbase = m0 & ~511, tb = m0 & 511;
    int ncmask = (1 << nsh) - 1;
    int NIT = 9 << nsh;
    int lrow = tid >> 1, lhalf = tid & 1;
    size_t wstr = (size_t)Coutv * Cin;
    float acc[16][4] = {};

#define ISSUE(itv, bo) do {                                                   \
        int dk_ = (itv) >> nsh; int kc_ = ((itv) & ncmask) << 5;              \
        int t_ = tb + lrow + dk_ - 4;                                         \
        unsigned okn = ((unsigned)t_ < 512u) ? 16u : 0u;                      \
        size_t ar_ = (size_t)(bbase + t_) * Cin + kc_ + lhalf * 16;          \
        unsigned da_ = sbase + (bo) + lrow * 80 + lhalf * 32;                 \
        CPA(da_, Ah + ar_, okn);        CPA(da_ + 16, Ah + ar_ + 8, okn);     \
        size_t wr_ = (size_t)dk_ * wstr + (size_t)(n0 + lrow) * Cin + kc_ + lhalf * 16; \
        CPA(da_ + 10240, Wh + wr_, 16u); CPA(da_ + 10256, Wh + wr_ + 8, 16u); \
    } while (0)

    ISSUE(0, 0);
    asm volatile("cp.async.commit_group;" ::: "memory");
    for (int it = 0; it < NIT; ++it) {
        int cbo = (it & 1) * 20480, nbo = 20480 - cbo;
        if (it + 1 < NIT) {
            ISSUE(it + 1, nbo);
            asm volatile("cp.async.commit_group;" ::: "memory");
            asm volatile("cp.async.wait_group 1;" ::: "memory");
        } else {
            asm volatile("cp.async.wait_group 0;" ::: "memory");
        }
        __syncthreads();
        const unsigned* AH = (const unsigned*)(smem + cbo);
        const unsigned* BH = (const unsigned*)(smem + cbo + 10240);
        unsigned aH0[2][4], aH1[2][4];
#pragma unroll
        for (int i = 0; i < 2; ++i) {
            int r = wm * 32 + i * 16 + g;
            int b0 = r * 20 + tig, b1 = (r + 8) * 20 + tig;
            aH0[i][0] = AH[b0];     aH0[i][1] = AH[b1];
            aH0[i][2] = AH[b0 + 4]; aH0[i][3] = AH[b1 + 4];
            aH1[i][0] = AH[b0 + 8];  aH1[i][1] = AH[b1 + 8];
            aH1[i][2] = AH[b0 + 12]; aH1[i][3] = AH[b1 + 12];
        }
#pragma unroll
        for (int j = 0; j < 8; ++j) {
            int c = (wn * 64 + j * 8 + g) * 20 + tig;
            unsigned bF0[2] = {BH[c], BH[c + 4]};
            unsigned bF1[2] = {BH[c + 8], BH[c + 12]};
#pragma unroll
            for (int i = 0; i < 2; ++i) {
                mma16(acc[i * 8 + j], aH0[i], bF0);
                mma16(acc[i * 8 + j], aH1[i], bF1);
            }
        }
        __syncthreads();
    }
#undef ISSUE
#pragma unroll
    for (int i = 0; i < 2; ++i)
#pragma unroll
        for (int j = 0; j < 8; ++j) {
            int m = m0 + wm * 32 + i * 16 + g;
            int n = n0 + wn * 64 + j * 8 + 2 * tig;
            float* a = acc[i * 8 + j];
            float b0 = bias[n], b1 = bias[n + 1];
            float v0 = a[0] + b0, v1 = a[1] + b1, v2 = a[2] + b0, v3 = a[3] + b1;
            size_t o0 = (size_t)m * outld + n, o1 = (size_t)(m + 8) * outld + n;
            if (relu_split) {
                __half h0 = __float2half_rn(fmaxf(v0, 0.f));
                __half h1 = __float2half_rn(fmaxf(v1, 0.f));
                __half h2 = __float2half_rn(fmaxf(v2, 0.f));
                __half h3 = __float2half_rn(fmaxf(v3, 0.f));
                *(unsigned*)&OHh[o0] = (unsigned)__half_as_ushort(h0) | ((unsigned)__half_as_ushort(h1) << 16);
                *(unsigned*)&OHh[o1] = (unsigned)__half_as_ushort(h2) | ((unsigned)__half_as_ushort(h3) << 16);
            } else {
                *(float2*)&Of[o0] = make_float2(v0, v1);
                *(float2*)&Of[o1] = make_float2(v2, v3);
            }
        }
}

// conv weight prep: src[l][R][C][9] fp32 -> Wh [l][9][R][C] fp16 (hi only)
__global__ void k_wprep(const float* __restrict__ src, ushort_t* __restrict__ Wh,
                        int R, int C) {
    size_t idx = ((size_t)blockIdx.x * 256 + threadIdx.x) * 2;
    int c = (int)(idx % C);
    size_t t1 = idx / C;
    int r = (int)(t1 % R);
    size_t t2 = t1 / R;
    int dk = (int)(t2 % 9);
    int l = (int)(t2 / 9);
    size_t sb = (((size_t)l * R + r) * C + c) * 9 + dk;
    __half h0 = __float2half_rn(src[sb]), h1 = __float2half_rn(src[sb + 9]);
    *(unsigned*)&Wh[idx] = (unsigned)__half_as_ushort(h0) | ((unsigned)__half_as_ushort(h1) << 16);
}

// ================= mma.sync attention (3-pass) =================
__device__ __forceinline__ void mma_tile16(const unsigned* AsH, const unsigned* AsL,
                                           const unsigned* BsH, const unsigned* BsL,
                                           int wm, int wn, int g, int tig,
                                           float (*acc)[4]) {
    unsigned aH[2][4], aL[2][4];
#pragma unroll
    for (int i = 0; i < 2; ++i) {
        int r = (wm * 32 + i * 16 + g) * 12 + tig;
        aH[i][0] = AsH[r]; aH[i][1] = AsH[r + 96]; aH[i][2] = AsH[r + 4]; aH[i][3] = AsH[r + 100];
        aL[i][0] = AsL[r]; aL[i][1] = AsL[r + 96]; aL[i][2] = AsL[r + 4]; aL[i][3] = AsL[r + 100];
    }
#pragma unroll
    for (int j = 0; j < 8; ++j) {
        int nb = wn * 64 + j * 8 + g;
        unsigned bH[2] = {BsH[tig * 136 + nb], BsH[(tig + 4) * 136 + nb]};
        unsigned bL[2] = {BsL[tig * 136 + nb], BsL[(tig + 4) * 136 + nb]};
#pragma unroll
        for (int i = 0; i < 2; ++i) {
            mma16(acc[i * 8 + j], aH[i], bH);
            mma16(acc[i * 8 + j], aL[i], bH);
            mma16(acc[i * 8 + j], aH[i], bL);
        }
    }
}

// pipelined projection GEMM: buffer = AsH 6144 | AsL 6144 | BsH 4352 | BsL 4352 = 20992 B
__global__ void __launch_bounds__(256, 2)
k_gemm_bias(const ushort_t* __restrict__ Ah, const ushort_t* __restrict__ Al,
            const unsigned* __restrict__ Bph, const unsigned* __restrict__ Bpl,
            const float* __restrict__ bias, float* __restrict__ Cf,
            ushort_t* __restrict__ Ch, ushort_t* __restrict__ Cl) {
    __shared__ __align__(16) char smem[41984];
    unsigned sbase = smem_u32(smem);
    int tid = threadIdx.x, w = tid >> 5, lane = tid & 31;
    int wm = w & 3, wn = w >> 2, g = lane >> 2, tig = lane & 3;
    int n0 = blockIdx.x * 128, m0 = blockIdx.y * 128;
    int arow = tid >> 1, apart = tid & 1;
    int bp = tid >> 5;
    float acc[16][4] = {};
#define GISSUE(k0v, bo) do {                                                  \
        size_t aoff = (size_t)(m0 + arow) * 256 + (k0v) + apart * 8;          \
        unsigned da = sbase + (bo) + arow * 48 + apart * 16;                  \
        CPA(da, Ah + aoff, 16u); CPA(da + 6144, Al + aoff, 16u);              \
        size_t boff = (size_t)((k0v) / 2 + bp) * 256 + n0 + lane * 4;         \
        unsigned db = sbase + (bo) + 12288 + bp * 544 + lane * 16;            \
        CPA(db, Bph + boff, 16u); CPA(db + 4352, Bpl + boff, 16u);            \
    } while (0)
    GISSUE(0, 0);
    asm volatile("cp.async.commit_group;" ::: "memory");
    for (int it = 0; it < 16; ++it) {
        int cbo = (it & 1) * 20992, nbo = 20992 - cbo;
        if (it < 15) {
            GISSUE((it + 1) * 16, nbo);
            asm volatile("cp.async.commit_group;" ::: "memory");
            asm volatile("cp.async.wait_group 1;" ::: "memory");
        } else {
            asm volatile("cp.async.wait_group 0;" ::: "memory");
        }
        __syncthreads();
        mma_tile16((const unsigned*)(smem + cbo), (const unsigned*)(smem + cbo + 6144),
                   (const unsigned*)(smem + cbo + 12288), (const unsigned*)(smem + cbo + 16640),
                   wm, wn, g, tig, acc);
        __syncthreads();
    }
#undef GISSUE
#pragma unroll
    for (int i = 0; i < 2; ++i)
#pragma unroll
        for (int j = 0; j < 8; ++j) {
            int m = m0 + wm * 32 + i * 16 + g;
            int n = n0 + wn * 64 + j * 8 + 2 * tig;
            float b0 = bias[n], b1 = bias[n + 1];
            float* a = acc[i * 8 + j];
            float v0 = a[0] + b0, v1 = a[1] + b1, v2 = a[2] + b0, v3 = a[3] + b1;
            if (Cf) {
                *(float2*)&Cf[(size_t)m * 256 + n] = make_float2(v0, v1);
                *(float2*)&Cf[(size_t)(m + 8) * 256 + n] = make_float2(v2, v3);
            }
            if (Ch) {
                wsplit2(Ch, Cl, (size_t)m * 256 + n, v0, v1);
                wsplit2(Ch, Cl, (size_t)(m + 8) * 256 + n, v2, v3);
            }
        }
}

// pipelined scores
__global__ void __launch_bounds__(256, 2)
k_scores(const ushort_t* __restrict__ Qh, const ushort_t* __restrict__ Ql,
         const ushort_t* __restrict__ Kh, const ushort_t* __restrict__ Kl,
         float* __restrict__ S, const int* __restrict__ srcL) {
    __shared__ __align__(16) char smem[41984];
    unsigned sbase = smem_u32(smem);
    int tid = threadIdx.x, w = tid >> 5, lane = tid & 31;
    int wm = w & 3, wn = w >> 2, g = lane >> 2, tig = lane & 3;
    int n0 = blockIdx.x * 128, m0 = blockIdx.y * 128, bh = blockIdx.z;
    int b = bh >> 1, h = bh & 1;
    int arow = tid >> 1, apart = tid & 1;
    int btn = tid & 127, bpb = (tid >> 7) * 4;
    float acc[16][4] = {};
#define SISSUE(k0v, bo) do {                                                  \
        size_t aoff = (size_t)(b * 512 + m0 + arow) * 256 + h * 128 + (k0v) + apart * 8; \
        unsigned da = sbase + (bo) + arow * 48 + apart * 16;                  \
        CPA(da, Qh + aoff, 16u); CPA(da + 6144, Ql + aoff, 16u);              \
        size_t koff = (size_t)(b * 512 + n0 + btn) * 256 + h * 128 + (k0v) + bpb * 2; \
        const char* ksrc = (const char*)(Kh + koff);                          \
        const char* lsrc = (const char*)(Kl + koff);                          \
        _Pragma("unroll")                                                     \
        for (int i_ = 0; i_ < 4; ++i_) {                                      \
            unsigned db = sbase + (bo) + 12288 + ((bpb + i_) * 136 + btn) * 4; \
            CPA4(db, ksrc + i_ * 4);                                          \
            CPA4(db + 4352, lsrc + i_ * 4);                                   \
        }                                                                     \
    } while (0)
    SISSUE(0, 0);
    asm volatile("cp.async.commit_group;" ::: "memory");
    for (int it = 0; it < 8; ++it) {
        int cbo = (it & 1) * 20992, nbo = 20992 - cbo;
        if (it < 7) {
            SISSUE((it + 1) * 16, nbo);
            asm volatile("cp.async.commit_group;" ::: "memory");
            asm volatile("cp.async.wait_group 1;" ::: "memory");
        } else {
            asm volatile("cp.async.wait_group 0;" ::: "memory");
        }
        __syncthreads();
        mma_tile16((const unsigned*)(smem + cbo), (const unsigned*)(smem + cbo + 6144),
                   (const unsigned*)(smem + cbo + 12288), (const unsigned*)(smem + cbo + 16640),
                   wm, wn, g, tig, acc);
        __syncthreads();
    }
#undef SISSUE
    int sl = srcL[b];
    const float scale = 0.08838834764831845f;
#pragma unroll
    for (int i = 0; i < 2; ++i)
#pragma unroll
        for (int j = 0; j < 8; ++j) {
            int m = m0 + wm * 32 + i * 16 + g;
            int n = n0 + wn * 64 + j * 8 + 2 * tig;
            float* a = acc[i * 8 + j];
            bool p0 = (n >= sl), p1 = (n + 1 >= sl);
            float2 r0 = {p0 ? NEGF : a[0] * scale, p1 ? NEGF : a[1] * scale};
            float2 r1 = {p0 ? NEGF : a[2] * scale, p1 ? NEGF : a[3] * scale};
            *(float2*)&S[((size_t)bh * 512 + m) * 512 + n] = r0;
            *(float2*)&S[((size_t)bh * 512 + m + 8) * 512 + n] = r1;
        }
}

__global__ void __launch_bounds__(256, 2)
k_attnout(const ushort_t* __restrict__ Sh, const ushort_t* __restrict__ Sl,
          const ushort_t* __restrict__ Vh, const ushort_t* __restrict__ Vl,
          ushort_t* __restrict__ Oh, ushort_t* __restrict__ Ol) {
    __shared__ unsigned AsH[1536], AsL[1536], BsH[1088], BsL[1088];
    int tid = threadIdx.x, w = tid >> 5, lane = tid & 31;
    int wm = w & 3, wn = w >> 2, g = lane >> 2, tig = lane & 3;
    int m0 = blockIdx.y * 128, bh = blockIdx.z;
    int b = bh >> 1, h = bh & 1;
    int arow = tid >> 1, apart = tid & 1;
    int bp = tid >> 5, bc = lane * 4;
    float acc[16][4] = {};
    for (int k0 = 0; k0 < 512; k0 += 16) {
        size_t aoff = ((size_t)bh * 512 + m0 + arow) * 512 + k0 + apart * 8;
        uint4 ah = *(const uint4*)(Sh + aoff);
        uint4 al = *(const uint4*)(Sl + aoff);
        const ushort_t* r0h = Vh + (size_t)(b * 512 + k0 + 2 * bp) * 256 + h * 128 + bc;
        uint2 uah = *(const uint2*)r0h, ubh = *(const uint2*)(r0h + 256);
        const ushort_t* r0l = Vl + (size_t)(b * 512 + k0 + 2 * bp) * 256 + h * 128 + bc;
        uint2 ual = *(const uint2*)r0l, ubl = *(const uint2*)(r0l + 256);
        __syncthreads();
        *(uint4*)&AsH[arow * 12 + apart * 4] = ah;
        *(uint4*)&AsL[arow * 12 + apart * 4] = al;
        BsH[bp * 136 + bc + 0] = (uah.x & 0xFFFFu) | (ubh.x << 16);
        BsH[bp * 136 + bc + 1] = (uah.x >> 16) | (ubh.x & 0xFFFF0000u);
        BsH[bp * 136 + bc + 2] = (uah.y & 0xFFFFu) | (ubh.y << 16);
        BsH[bp * 136 + bc + 3] = (uah.y >> 16) | (ubh.y & 0xFFFF0000u);
        BsL[bp * 136 + bc + 0] = (ual.x & 0xFFFFu) | (ubl.x << 16);
        BsL[bp * 136 + bc + 1] = (ual.x >> 16) | (ubl.x & 0xFFFF0000u);
        BsL[bp * 136 + bc + 2] = (ual.y & 0xFFFFu) | (ubl.y << 16);
        BsL[bp * 136 + bc + 3] = (ual.y >> 16) | (ubl.y & 0xFFFF0000u);
        __syncthreads();
        mma_tile16(AsH, AsL, BsH, BsL, wm, wn, g, tig, acc);
    }
#pragma unroll
    for (int i = 0; i < 2; ++i)
#pragma unroll
        for (int j = 0; j < 8; ++j) {
            int m = m0 + wm * 32 + i * 16 + g;
            int n = h * 128 + wn * 64 + j * 8 + 2 * tig;
            float* a = acc[i * 8 + j];
            wsplit2(Oh, Ol, (size_t)(b * 512 + m) * 256 + n, a[0], a[1]);
            wsplit2(Oh, Ol, (size_t)(b * 512 + m + 8) * 256 + n, a[2], a[3]);
        }
}

// ================= producers / elementwise =================
__global__ void k_embed(const int* __restrict__ tok, const float* __restrict__ emb,
                        const float* __restrict__ pos, float* __restrict__ x,
                        ushort_t* __restrict__ xh, ushort_t* __restrict__ xl) {
    int row = blockIdx.x, d = threadIdx.x;
    int t = row & 511;
    int id = tok[row];
    size_t off = (size_t)row * 256 + d;
    float v = emb[(size_t)id * 256 + d] + pos[(size_t)t * 256 + d];
    x[off] = v;
    ushort_t h, l; split1(v, h, l);
    xh[off] = h; xl[off] = l;
}

__global__ void k_softmax(const float* __restrict__ S, ushort_t* __restrict__ Sh,
                          ushort_t* __restrict__ Sl) {
    __shared__ float red[4];
    size_t row = blockIdx.x;
    float4 v = ((const float4*)(S + row * 512))[threadIdx.x];
    int lane = threadIdx.x & 31, wid = threadIdx.x >> 5;
    float m = fmaxf(fmaxf(v.x, v.y), fmaxf(v.z, v.w));
#pragma unroll
    for (int o = 16; o > 0; o >>= 1) m = fmaxf(m, __shfl_xor_sync(~0u, m, o));
    if (lane == 0) red[wid] = m;
    __syncthreads();
    m = fmaxf(fmaxf(red[0], red[1]), fmaxf(red[2], red[3]));
    __syncthreads();
    v.x = expf(v.x - m); v.y = expf(v.y - m); v.z = expf(v.z - m); v.w = expf(v.w - m);
    float s = v.x + v.y + v.z + v.w;
#pragma unroll
    for (int o = 16; o > 0; o >>= 1) s += __shfl_xor_sync(~0u, s, o);
    if (lane == 0) red[wid] = s;
    __syncthreads();
    s = red[0] + red[1] + red[2] + red[3];
    float inv = 1.0f / s;
    size_t off = row * 512 + threadIdx.x * 4;
    wsplit2(Sh, Sl, off, v.x * inv, v.y * inv);
    wsplit2(Sh, Sl, off + 2, v.z * inv, v.w * inv);
}

__global__ void k_lnres(const float* __restrict__ t, const float* __restrict__ res,
                        const float* __restrict__ gam, const float* __restrict__ bet,
                        const int* __restrict__ srcL, float* __restrict__ out,
                        ushort_t* __restrict__ oh, ushort_t* __restrict__ ol) {
    __shared__ float red[8];
    int row = blockIdx.x, d = threadIdx.x;
    size_t off = (size_t)row * 256 + d;
    float val = t[off] + res[off];
    float s = val;
#pragma unroll
    for (int o = 16; o > 0; o >>= 1) s += __shfl_xor_sync(~0u, s, o);
    if ((d & 31) == 0) red[d >> 5] = s;
    __syncthreads();
    float tot = 0.f;
#pragma unroll
    for (int i = 0; i < 8; ++i) tot += red[i];
    float mean = tot * (1.0f / 256.0f);
    float dv = val - mean;
    __syncthreads();
    float s2 = dv * dv;
#pragma unroll
    for (int o = 16; o > 0; o >>= 1) s2 += __shfl_xor_sync(~0u, s2, o);
    if ((d & 31) == 0) red[d >> 5] = s2;
    __syncthreads();
    float tot2 = 0.f;
#pragma unroll
    for (int i = 0; i < 8; ++i) tot2 += red[i];
    float o = dv * rsqrtf(tot2 * (1.0f / 256.0f) + 1e-5f) * gam[d] + bet[d];
    if ((row & 511) >= srcL[row >> 9]) o = 0.f;
    out[off] = o;
    ushort_t h, l; split1(o, h, l);
    oh[off] = h; ol[off] = l;
}

__global__ void k_packsplit(const float* __restrict__ src, unsigned* __restrict__ Uh,
                            unsigned* __restrict__ Ul, int nshift) {
    size_t idx = (size_t)blockIdx.x * 256 + threadIdx.x;
    size_t kp = idx >> nshift;
    int n = (int)(idx & ((1u << nshift) - 1));
    size_t N = (size_t)1 << nshift;
    float a = src[(2 * kp) * N + n], b = src[(2 * kp + 1) * N + n];
    ushort_t ha, la, hb, lb;
    split1(a, ha, la); split1(b, hb, lb);
    Uh[idx] = (unsigned)ha | ((unsigned)hb << 16);
    Ul[idx] = (unsigned)la | ((unsigned)lb << 16);
}

// ================= MAS + expand =================
__global__ void k_vtrans(const float* __restrict__ val, float* __restrict__ vt,
                         const int* __restrict__ srcL, const int* __restrict__ melL) {
    __shared__ float s[32][33];
    int b = blockIdx.z;
    int x0 = blockIdx.x * 32, y0 = blockIdx.y * 32;
    int sl = srcL[b], ml = melL[b];
    const float* vp = val + (size_t)b * 512 * 1024;
    float* op = vt + (size_t)b * 1024 * 512;
    for (int i = threadIdx.y; i < 32; i += 8) {
        int x = x0 + i, y = y0 + threadIdx.x;
        float v = vp[(size_t)x * 1024 + y];
        s[i][threadIdx.x] = (x < sl && y < ml) ? v : 0.f;
    }
    __syncthreads();
    for (int j = threadIdx.y; j < 32; j += 8)
        op[(size_t)(y0 + j) * 512 + x0 + threadIdx.x] = s[threadIdx.x][j];
}

__global__ void k_masdp(const float* __restrict__ vt, const int* __restrict__ srcL,
                        const int* __restrict__ melL, unsigned* __restrict__ dir) {
    __shared__ float bnd[2][16];
    int b = blockIdx.x, x = threadIdx.x;
    int sl = srcL[b], ml = melL[b];
    int lane = x & 31, wid = x >> 5;
    float v = 0.f;
    float val = vt[(size_t)b * 1024 * 512 + x];
    for (int j = 0; j < 1024; ++j) {
        if (lane == 31) bnd[j & 1][wid] = v;
        __syncthreads();
        float v0 = __shfl_up_sync(0xffffffffu, v, 1);
        if (lane == 0) v0 = wid ? bnd[j & 1][wid - 1] : NEGF;
        float valn = 0.f;
        if (j + 1 < 1024) valn = vt[((size_t)b * 1024 + j + 1) * 512 + x];
        bool d = (v >= v0);
        float vmax = d ? v : v0;
        float vnew = (x <= j) ? (vmax + val) : NEGF;
        bool dm = (x < sl && j < ml) ? d : true;
        unsigned bal = __ballot_sync(0xffffffffu, dm);
        if (lane == 0) dir[((size_t)b * 1024 + j) * 16 + wid] = bal;
        v = vnew;
        val = valn;
    }
}

__global__ void k_masbt(const unsigned* __restrict__ dir, const int* __restrict__ srcL,
                        int* __restrict__ idxout) {
    int b = threadIdx.x;
    if (b >= 32) return;
    int idx = srcL[b] - 1;
    for (int y0 = 1023; y0 >= 0; y0 -= 8) {
        int w0 = idx >> 5;
        unsigned wA[8], wB[8];
#pragma unroll
        for (int d = 0; d < 8; ++d) {
            size_t base = ((size_t)b * 1024 + (y0 - d)) * 16;
            wA[d] = dir[base + w0];
            wB[d] = (w0 > 0) ? dir[base + w0 - 1] : 0u;
        }
#pragma unroll
        for (int d = 0; d < 8; ++d) {
            int y = y0 - d;
            idxout[b * 1024 + y] = idx;
            int wcur = idx >> 5;
            unsigned word = (wcur == w0) ? wA[d] : wB[d];
            idx += (int)((word >> (idx & 31)) & 1u) - 1;
        }
    }
}

__global__ void k_expand(const float* __restrict__ X, const int* __restrict__ idx,
                         const int* __restrict__ srcL, const int* __restrict__ melL,
                         float* __restrict__ out) {
    int row = blockIdx.x;
    int b = row >> 10, y = row & 1023;
    int d = threadIdx.x;
    float o = 0.f;
    if (y < melL[b]) {
        int ix = idx[row];
        if (ix >= 0 && ix < srcL[b])
            o = X[((size_t)(b << 9) + ix) * 256 + d];
    }
    out[(size_t)row * 256 + d] = o;
}

// ================= launch =================
extern "C" void kernel_launch(void* const* d_in, const int* in_sizes, int n_in,
                              void* d_out, int out_size) {
    const int* tokens = (const int*)d_in[0];
    const int* srcL   = (const int*)d_in[1];
    const int* melL   = (const int*)d_in[2];
    const float* value = (const float*)d_in[3];
    const float* embed = (const float*)d_in[4];
    const float* pos   = (const float*)d_in[5];
    const float* wq = (const float*)d_in[6];  const float* bq = (const float*)d_in[7];
    const float* wk = (const float*)d_in[8];  const float* bk = (const float*)d_in[9];
    const float* wv = (const float*)d_in[10]; const float* bv = (const float*)d_in[11];
    const float* wo = (const float*)d_in[12]; const float* bo = (const float*)d_in[13];
    const float* ln1g = (const float*)d_in[14]; const float* ln1b = (const float*)d_in[15];
    const float* c1w = (const float*)d_in[16]; const float* c1b = (const float*)d_in[17];
    const float* c2w = (const float*)d_in[18]; const float* c2b = (const float*)d_in[19];
    const float* ln2g = (const float*)d_in[20]; const float* ln2b = (const float*)d_in[21];
    float* out = (float*)d_out;

    float *px, *pt, *ps, *pvt;
    ushort_t *pxh, *pxl, *pqh, *pql, *pkh, *pkl, *pvh, *pvl, *poh, *pol;
    ushort_t *psh, *psl, *phh, *pw1h, *pw2h;
    unsigned *pwqh, *pwql, *pwkh, *pwkl, *pwvh, *pwvl, *pwoh, *pwol;
    unsigned* pdir; int* pidx;
    cudaGetSymbolAddress((void**)&px, g_x);   cudaGetSymbolAddress((void**)&pt, g_t);
    cudaGetSymbolAddress((void**)&ps, g_s);   cudaGetSymbolAddress((void**)&pvt, g_vt);
    cudaGetSymbolAddress((void**)&pxh, g_xh); cudaGetSymbolAddress((void**)&pxl, g_xl);
    cudaGetSymbolAddress((void**)&pqh, g_qh); cudaGetSymbolAddress((void**)&pql, g_ql);
    cudaGetSymbolAddress((void**)&pkh, g_kh); cudaGetSymbolAddress((void**)&pkl, g_kl);
    cudaGetSymbolAddress((void**)&pvh, g_vh); cudaGetSymbolAddress((void**)&pvl, g_vl);
    cudaGetSymbolAddress((void**)&poh, g_oh); cudaGetSymbolAddress((void**)&pol, g_ol);
    cudaGetSymbolAddress((void**)&psh, g_sh); cudaGetSymbolAddress((void**)&psl, g_sl);
    cudaGetSymbolAddress((void**)&phh, g_hh);
    cudaGetSymbolAddress((void**)&pw1h, g_w1h); cudaGetSymbolAddress((void**)&pw2h, g_w2h);
    cudaGetSymbolAddress((void**)&pwqh, g_wqh); cudaGetSymbolAddress((void**)&pwql, g_wql);
    cudaGetSymbolAddress((void**)&pwkh, g_wkh); cudaGetSymbolAddress((void**)&pwkl, g_wkl);
    cudaGetSymbolAddress((void**)&pwvh, g_wvh); cudaGetSymbolAddress((void**)&pwvl, g_wvl);
    cudaGetSymbolAddress((void**)&pwoh, g_woh); cudaGetSymbolAddress((void**)&pwol, g_wol);
    cudaGetSymbolAddress((void**)&pdir, g_dir); cudaGetSymbolAddress((void**)&pidx, g_idx);

    const int SMEMC = 40960;
    cudaFuncSetAttribute(k_conv, cudaFuncAttributeMaxDynamicSharedMemorySize, SMEMC);

    dim3 blk256(256);
    // weight prep
    k_wprep<<<18432, blk256>>>(c1w, pw1h, 1024, 256);
    k_wprep<<<18432, blk256>>>(c2w, pw2h, 256, 1024);
    k_packsplit<<<512, blk256>>>(wq, pwqh, pwql, 8);
    k_packsplit<<<512, blk256>>>(wk, pwkh, pwkl, 8);
    k_packsplit<<<512, blk256>>>(wv, pwvh, pwvl, 8);
    k_packsplit<<<512, blk256>>>(wo, pwoh, pwol, 8);
    // inputs
    k_vtrans<<<dim3(16, 32, 32), dim3(32, 8)>>>(value, pvt, srcL, melL);
    k_embed<<<16384, blk256>>>(tokens, embed, pos, px, pxh, pxl);

    for (int l = 0; l < 4; ++l) {
        const unsigned *wqh_l = pwqh + l * 32768, *wql_l = pwql + l * 32768;
        const unsigned *wkh_l = pwkh + l * 32768, *wkl_l = pwkl + l * 32768;
        const unsigned *wvh_l = pwvh + l * 32768, *wvl_l = pwvl + l * 32768;
        const unsigned *woh_l = pwoh + l * 32768, *wol_l = pwol + l * 32768;

        k_gemm_bias<<<dim3(2, 128), blk256>>>(pxh, pxl, wqh_l, wql_l, bq + l * 256, nullptr, pqh, pql);
        k_gemm_bias<<<dim3(2, 128), blk256>>>(pxh, pxl, wkh_l, wkl_l, bk + l * 256, nullptr, pkh, pkl);
        k_gemm_bias<<<dim3(2, 128), blk256>>>(pxh, pxl, wvh_l, wvl_l, bv + l * 256, nullptr, pvh, pvl);
        k_scores<<<dim3(4, 4, 64), blk256>>>(pqh, pql, pkh, pkl, ps, srcL);
        k_softmax<<<32768, 128>>>(ps, psh, psl);
        k_attnout<<<dim3(1, 4, 64), blk256>>>(psh, psl, pvh, pvl, poh, pol);
        k_gemm_bias<<<dim3(2, 128), blk256>>>(poh, pol, woh_l, wol_l, bo + l * 256, pt, nullptr, nullptr);
        k_lnres<<<16384, blk256>>>(pt, px, ln1g + l * 256, ln1b + l * 256, srcL, px, pxh, pxl);

        k_conv<<<dim3(8, 128), blk256, SMEMC>>>(pxh, pw1h + (size_t)l * 2359296,
                                                c1b + l * 1024, 256, 3, 1, phh, nullptr, 1024);
        k_conv<<<dim3(2, 128), blk256, SMEMC>>>(phh, pw2h + (size_t)l * 2359296,
                                                c2b + l * 256, 1024, 5, 0, nullptr, pt, 256);
        k_lnres<<<16384, blk256>>>(pt, px, ln2g + l * 256, ln2b + l * 256, srcL, px, pxh, pxl);
    }

    k_masdp<<<32, 512>>>(pvt, srcL, melL, pdir);
    k_masbt<<<1, 32>>>(pdir, srcL, pidx);
    k_expand<<<32768, blk256>>>(px, pidx, srcL, melL, out);
}

// round 16
// speedup vs baseline: 2.2869x; 1.0075x over previous
#include <cuda_runtime.h>
#include <cuda_fp16.h>
#include <stdint.h>
#include <math.h>

#define NEGF (-1e9f)
typedef unsigned short ushort_t;

// ---------- scratch ----------
__device__ float    g_x [4194304];
__device__ float    g_t [4194304];
__device__ float    g_s [16777216];
__device__ float    g_vt[16777216];
__device__ ushort_t g_xh[4194304],  g_xl[4194304];
__device__ ushort_t g_qh[4194304],  g_ql[4194304];
__device__ ushort_t g_kh[4194304],  g_kl[4194304];
__device__ ushort_t g_vh[4194304],  g_vl[4194304];
__device__ ushort_t g_oh[4194304],  g_ol[4194304];
__device__ ushort_t g_sh[16777216], g_sl[16777216];
__device__ ushort_t g_hh[16777216];
__device__ ushort_t g_w1h[9437184];   // [L][9][1024][256] fp16 (transposed)
__device__ ushort_t g_w2h[9437184];   // [L][9][256][1024]
__device__ unsigned g_wqkvh[393216], g_wqkvl[393216];  // [L][128kp][768]
__device__ unsigned g_woh[131072], g_wol[131072];
__device__ unsigned g_vph[2097152], g_vpl[2097152];    // [B][256kp][256] packed V
__device__ unsigned g_dir[524288];
__device__ int      g_idx[32768];

// ---------- fp16 split helpers ----------
__device__ __forceinline__ void split1(float v, ushort_t& h, ushort_t& l) {
    __half hh = __float2half_rn(v);
    __half ll = __float2half_rn(v - __half2float(hh));
    h = __half_as_ushort(hh); l = __half_as_ushort(ll);
}
__device__ __forceinline__ void wsplit2(ushort_t* Ph, ushort_t* Pl, size_t off,
                                        float v0, float v1) {
    ushort_t h0, l0, h1, l1;
    split1(v0, h0, l0); split1(v1, h1, l1);
    *(unsigned*)&Ph[off] = (unsigned)h0 | ((unsigned)h1 << 16);
    *(unsigned*)&Pl[off] = (unsigned)l0 | ((unsigned)l1 << 16);
}
__device__ __forceinline__ unsigned smem_u32(const void* p) {
    unsigned a;
    asm("{ .reg .u64 t; cvta.to.shared.u64 t, %1; cvt.u32.u64 %0, t; }" : "=r"(a) : "l"(p));
    return a;
}

// ---------- mma core ----------
__device__ __forceinline__ void mma16(float c[4], const unsigned a[4], const unsigned b[2]) {
    asm volatile(
        "mma.sync.aligned.m16n8k16.row.col.f32.f16.f16.f32 "
        "{%0,%1,%2,%3},{%4,%5,%6,%7},{%8,%9},{%0,%1,%2,%3};\n"
        : "+f"(c[0]), "+f"(c[1]), "+f"(c[2]), "+f"(c[3])
        : "r"(a[0]), "r"(a[1]), "r"(a[2]), "r"(a[3]), "r"(b[0]), "r"(b[1]));
}

#define CPA(d, s, n) \
    asm volatile("cp.async.cg.shared.global [%0],[%1],16,%2;" :: "r"(d), "l"(s), "r"(n) : "memory")
#define CPA4(d, s) \
    asm volatile("cp.async.ca.shared.global [%0],[%1],4;" :: "r"(d), "l"(s) : "memory")

// ================= conv: pure fp16 (aH*bH), K-chunk 32, pipelined =================
__global__ void __launch_bounds__(256, 2)
k_conv(const ushort_t* __restrict__ Ah,
       const ushort_t* __restrict__ Wh,
       const float* __restrict__ bias, int Cin, int nsh, int relu_split,
       ushort_t* __restrict__ OHh,
       float* __restrict__ Of, int outld) {
    extern __shared__ __align__(16) char smem[];
    unsigned sbase = smem_u32(smem);
    int tid = threadIdx.x, wd = tid >> 5, lane = tid & 31;
    int wm = wd & 3, wn = wd >> 2, g = lane >> 2, tig = lane & 3;
    int n0 = blockIdx.x * 128, m0 = blockIdx.y * 128;
    int Coutv = gridDim.x * 128;
    int bbase = m0 & ~511, tb = m0 & 511;
    int ncmask = (1 << nsh) - 1;
    int NIT = 9 << nsh;
    int lrow = tid >> 1, lhalf = tid & 1;
    size_t wstr = (size_t)Coutv * Cin;
    float acc[16][4] = {};

#define ISSUE(itv, bo) do {                                                   \
        int dk_ = (itv) >> nsh; int kc_ = ((itv) & ncmask) << 5;              \
        int t_ = tb + lrow + dk_ - 4;                                         \
        unsigned okn = ((unsigned)t_ < 512u) ? 16u : 0u;                      \
        size_t ar_ = (size_t)(bbase + t_) * Cin + kc_ + lhalf * 16;          \
        unsigned da_ = sbase + (bo) + lrow * 80 + lhalf * 32;                 \
        CPA(da_, Ah + ar_, okn);        CPA(da_ + 16, Ah + ar_ + 8, okn);     \
        size_t wr_ = (size_t)dk_ * wstr + (size_t)(n0 + lrow) * Cin + kc_ + lhalf * 16; \
        CPA(da_ + 10240, Wh + wr_, 16u); CPA(da_ + 10256, Wh + wr_ + 8, 16u); \
    } while (0)

    ISSUE(0, 0);
    asm volatile("cp.async.commit_group;" ::: "memory");
    for (int it = 0; it < NIT; ++it) {
        int cbo = (it & 1) * 20480, nbo = 20480 - cbo;
        if (it + 1 < NIT) {
            ISSUE(it + 1, nbo);
            asm volatile("cp.async.commit_group;" ::: "memory");
            asm volatile("cp.async.wait_group 1;" ::: "memory");
        } else {
            asm volatile("cp.async.wait_group 0;" ::: "memory");
        }
        __syncthreads();
        const unsigned* AH = (const unsigned*)(smem + cbo);
        const unsigned* BH = (const unsigned*)(smem + cbo + 10240);
        unsigned aH0[2][4], aH1[2][4];
#pragma unroll
        for (int i = 0; i < 2; ++i) {
            int r = wm * 32 + i * 16 + g;
            int b0 = r * 20 + tig, b1 = (r + 8) * 20 + tig;
            aH0[i][0] = AH[b0];     aH0[i][1] = AH[b1];
            aH0[i][2] = AH[b0 + 4]; aH0[i][3] = AH[b1 + 4];
            aH1[i][0] = AH[b0 + 8];  aH1[i][1] = AH[b1 + 8];
            aH1[i][2] = AH[b0 + 12]; aH1[i][3] = AH[b1 + 12];
        }
#pragma unroll
        for (int j = 0; j < 8; ++j) {
            int c = (wn * 64 + j * 8 + g) * 20 + tig;
            unsigned bF0[2] = {BH[c], BH[c + 4]};
            unsigned bF1[2] = {BH[c + 8], BH[c + 12]};
#pragma unroll
            for (int i = 0; i < 2; ++i) {
                mma16(acc[i * 8 + j], aH0[i], bF0);
                mma16(acc[i * 8 + j], aH1[i], bF1);
            }
        }
        __syncthreads();
    }
#undef ISSUE
#pragma unroll
    for (int i = 0; i < 2; ++i)
#pragma unroll
        for (int j = 0; j < 8; ++j) {
            int m = m0 + wm * 32 + i * 16 + g;
            int n = n0 + wn * 64 + j * 8 + 2 * tig;
            float* a = acc[i * 8 + j];
            float b0 = bias[n], b1 = bias[n + 1];
            float v0 = a[0] + b0, v1 = a[1] + b1, v2 = a[2] + b0, v3 = a[3] + b1;
            size_t o0 = (size_t)m * outld + n, o1 = (size_t)(m + 8) * outld + n;
            if (relu_split) {
                __half h0 = __float2half_rn(fmaxf(v0, 0.f));
                __half h1 = __float2half_rn(fmaxf(v1, 0.f));
                __half h2 = __float2half_rn(fmaxf(v2, 0.f));
                __half h3 = __float2half_rn(fmaxf(v3, 0.f));
                *(unsigned*)&OHh[o0] = (unsigned)__half_as_ushort(h0) | ((unsigned)__half_as_ushort(h1) << 16);
                *(unsigned*)&OHh[o1] = (unsigned)__half_as_ushort(h2) | ((unsigned)__half_as_ushort(h3) << 16);
            } else {
                *(float2*)&Of[o0] = make_float2(v0, v1);
                *(float2*)&Of[o1] = make_float2(v2, v3);
            }
        }
}

// conv weight prep: src[l][R][C][9] fp32 -> Wh [l][9][R][C] fp16 (hi only)
__global__ void k_wprep(const float* __restrict__ src, ushort_t* __restrict__ Wh,
                        int R, int C) {
    size_t idx = ((size_t)blockIdx.x * 256 + threadIdx.x) * 2;
    int c = (int)(idx % C);
    size_t t1 = idx / C;
    int r = (int)(t1 % R);
    size_t t2 = t1 / R;
    int dk = (int)(t2 % 9);
    int l = (int)(t2 / 9);
    size_t sb = (((size_t)l * R + r) * C + c) * 9 + dk;
    __half h0 = __float2half_rn(src[sb]), h1 = __float2half_rn(src[sb + 9]);
    *(unsigned*)&Wh[idx] = (unsigned)__half_as_ushort(h0) | ((unsigned)__half_as_ushort(h1) << 16);
}

// ================= mma.sync attention (3-pass) =================
__device__ __forceinline__ void mma_tile16(const unsigned* AsH, const unsigned* AsL,
                                           const unsigned* BsH, const unsigned* BsL,
                                           int wm, int wn, int g, int tig,
                                           float (*acc)[4]) {
    unsigned aH[2][4], aL[2][4];
#pragma unroll
    for (int i = 0; i < 2; ++i) {
        int r = (wm * 32 + i * 16 + g) * 12 + tig;
        aH[i][0] = AsH[r]; aH[i][1] = AsH[r + 96]; aH[i][2] = AsH[r + 4]; aH[i][3] = AsH[r + 100];
        aL[i][0] = AsL[r]; aL[i][1] = AsL[r + 96]; aL[i][2] = AsL[r + 4]; aL[i][3] = AsL[r + 100];
    }
#pragma unroll
    for (int j = 0; j < 8; ++j) {
        int nb = wn * 64 + j * 8 + g;
        unsigned bH[2] = {BsH[tig * 136 + nb], BsH[(tig + 4) * 136 + nb]};
        unsigned bL[2] = {BsL[tig * 136 + nb], BsL[(tig + 4) * 136 + nb]};
#pragma unroll
        for (int i = 0; i < 2; ++i) {
            mma16(acc[i * 8 + j], aH[i], bH);
            mma16(acc[i * 8 + j], aL[i], bH);
            mma16(acc[i * 8 + j], aH[i], bL);
        }
    }
}

// merged QKV projection: W packed [128kp][768]; segment (q/k/v) chosen by n0>>8
__global__ void __launch_bounds__(256, 2)
k_gemmqkv(const ushort_t* __restrict__ Ah, const ushort_t* __restrict__ Al,
          const unsigned* __restrict__ Bph, const unsigned* __restrict__ Bpl,
          const float* __restrict__ bq, const float* __restrict__ bk,
          const float* __restrict__ bv,
          ushort_t* __restrict__ Qh, ushort_t* __restrict__ Ql,
          ushort_t* __restrict__ Kh, ushort_t* __restrict__ Kl,
          ushort_t* __restrict__ Vh, ushort_t* __restrict__ Vl) {
    __shared__ __align__(16) char smem[41984];
    unsigned sbase = smem_u32(smem);
    int tid = threadIdx.x, w = tid >> 5, lane = tid & 31;
    int wm = w & 3, wn = w >> 2, g = lane >> 2, tig = lane & 3;
    int n0 = blockIdx.x * 128, m0 = blockIdx.y * 128;
    int arow = tid >> 1, apart = tid & 1;
    int bp = tid >> 5;
    float acc[16][4] = {};
#define QISSUE(k0v, bo) do {                                                  \
        size_t aoff = (size_t)(m0 + arow) * 256 + (k0v) + apart * 8;          \
        unsigned da = sbase + (bo) + arow * 48 + apart * 16;                  \
        CPA(da, Ah + aoff, 16u); CPA(da + 6144, Al + aoff, 16u);              \
        size_t boff = (size_t)((k0v) / 2 + bp) * 768 + n0 + lane * 4;         \
        unsigned db = sbase + (bo) + 12288 + bp * 544 + lane * 16;            \
        CPA(db, Bph + boff, 16u); CPA(db + 4352, Bpl + boff, 16u);            \
    } while (0)
    QISSUE(0, 0);
    asm volatile("cp.async.commit_group;" ::: "memory");
    for (int it = 0; it < 16; ++it) {
        int cbo = (it & 1) * 20992, nbo = 20992 - cbo;
        if (it < 15) {
            QISSUE((it + 1) * 16, nbo);
            asm volatile("cp.async.commit_group;" ::: "memory");
            asm volatile("cp.async.wait_group 1;" ::: "memory");
        } else {
            asm volatile("cp.async.wait_group 0;" ::: "memory");
        }
        __syncthreads();
        mma_tile16((const unsigned*)(smem + cbo), (const unsigned*)(smem + cbo + 6144),
                   (const unsigned*)(smem + cbo + 12288), (const unsigned*)(smem + cbo + 16640),
                   wm, wn, g, tig, acc);
        __syncthreads();
    }
#undef QISSUE
    int seg = n0 >> 8;
    const float* bias = (seg == 0) ? bq : ((seg == 1) ? bk : bv);
    ushort_t* Ch = (seg == 0) ? Qh : ((seg == 1) ? Kh : Vh);
    ushort_t* Cl = (seg == 0) ? Ql : ((seg == 1) ? Kl : Vl);
#pragma unroll
    for (int i = 0; i < 2; ++i)
#pragma unroll
        for (int j = 0; j < 8; ++j) {
            int m = m0 + wm * 32 + i * 16 + g;
            int n = n0 + wn * 64 + j * 8 + 2 * tig;
            int col = n & 255;
            float b0 = bias[col], b1 = bias[col + 1];
            float* a = acc[i * 8 + j];
            wsplit2(Ch, Cl, (size_t)m * 256 + col, a[0] + b0, a[1] + b1);
            wsplit2(Ch, Cl, (size_t)(m + 8) * 256 + col, a[2] + b0, a[3] + b1);
        }
}

// pipelined projection GEMM (used for O-projection)
__global__ void __launch_bounds__(256, 2)
k_gemm_bias(const ushort_t* __restrict__ Ah, const ushort_t* __restrict__ Al,
            const unsigned* __restrict__ Bph, const unsigned* __restrict__ Bpl,
            const float* __restrict__ bias, float* __restrict__ Cf) {
    __shared__ __align__(16) char smem[41984];
    unsigned sbase = smem_u32(smem);
    int tid = threadIdx.x, w = tid >> 5, lane = tid & 31;
    int wm = w & 3, wn = w >> 2, g = lane >> 2, tig = lane & 3;
    int n0 = blockIdx.x * 128, m0 = blockIdx.y * 128;
    int arow = tid >> 1, apart = tid & 1;
    int bp = tid >> 5;
    float acc[16][4] = {};
#define GISSUE(k0v, bo) do {                                                  \
        size_t aoff = (size_t)(m0 + arow) * 256 + (k0v) + apart * 8;          \
        unsigned da = sbase + (bo) + arow * 48 + apart * 16;                  \
        CPA(da, Ah + aoff, 16u); CPA(da + 6144, Al + aoff, 16u);              \
        size_t boff = (size_t)((k0v) / 2 + bp) * 256 + n0 + lane * 4;         \
        unsigned db = sbase + (bo) + 12288 + bp * 544 + lane * 16;            \
        CPA(db, Bph + boff, 16u); CPA(db + 4352, Bpl + boff, 16u);            \
    } while (0)
    GISSUE(0, 0);
    asm volatile("cp.async.commit_group;" ::: "memory");
    for (int it = 0; it < 16; ++it) {
        int cbo = (it & 1) * 20992, nbo = 20992 - cbo;
        if (it < 15) {
            GISSUE((it + 1) * 16, nbo);
            asm volatile("cp.async.commit_group;" ::: "memory");
            asm volatile("cp.async.wait_group 1;" ::: "memory");
        } else {
            asm volatile("cp.async.wait_group 0;" ::: "memory");
        }
        __syncthreads();
        mma_tile16((const unsigned*)(smem + cbo), (const unsigned*)(smem + cbo + 6144),
                   (const unsigned*)(smem + cbo + 12288), (const unsigned*)(smem + cbo + 16640),
                   wm, wn, g, tig, acc);
        __syncthreads();
    }
#undef GISSUE
#pragma unroll
    for (int i = 0; i < 2; ++i)
#pragma unroll
        for (int j = 0; j < 8; ++j) {
            int m = m0 + wm * 32 + i * 16 + g;
            int n = n0 + wn * 64 + j * 8 + 2 * tig;
            float b0 = bias[n], b1 = bias[n + 1];
            float* a = acc[i * 8 + j];
            *(float2*)&Cf[(size_t)m * 256 + n] = make_float2(a[0] + b0, a[1] + b1);
            *(float2*)&Cf[(size_t)(m + 8) * 256 + n] = make_float2(a[2] + b0, a[3] + b1);
        }
}

// pipelined scores
__global__ void __launch_bounds__(256, 2)
k_scores(const ushort_t* __restrict__ Qh, const ushort_t* __restrict__ Ql,
         const ushort_t* __restrict__ Kh, const ushort_t* __restrict__ Kl,
         float* __restrict__ S, const int* __restrict__ srcL) {
    __shared__ __align__(16) char smem[41984];
    unsigned sbase = smem_u32(smem);
    int tid = threadIdx.x, w = tid >> 5, lane = tid & 31;
    int wm = w & 3, wn = w >> 2, g = lane >> 2, tig = lane & 3;
    int n0 = blockIdx.x * 128, m0 = blockIdx.y * 128, bh = blockIdx.z;
    int b = bh >> 1, h = bh & 1;
    int arow = tid >> 1, apart = tid & 1;
    int btn = tid & 127, bpb = (tid >> 7) * 4;
    float acc[16][4] = {};
#define SISSUE(k0v, bo) do {                                                  \
        size_t aoff = (size_t)(b * 512 + m0 + arow) * 256 + h * 128 + (k0v) + apart * 8; \
        unsigned da = sbase + (bo) + arow * 48 + apart * 16;                  \
        CPA(da, Qh + aoff, 16u); CPA(da + 6144, Ql + aoff, 16u);              \
        size_t koff = (size_t)(b * 512 + n0 + btn) * 256 + h * 128 + (k0v) + bpb * 2; \
        const char* ksrc = (const char*)(Kh + koff);                          \
        const char* lsrc = (const char*)(Kl + koff);                          \
        _Pragma("unroll")                                                     \
        for (int i_ = 0; i_ < 4; ++i_) {                                      \
            unsigned db = sbase + (bo) + 12288 + ((bpb + i_) * 136 + btn) * 4; \
            CPA4(db, ksrc + i_ * 4);                                          \
            CPA4(db + 4352, lsrc + i_ * 4);                                   \
        }                                                                     \
    } while (0)
    SISSUE(0, 0);
    asm volatile("cp.async.commit_group;" ::: "memory");
    for (int it = 0; it < 8; ++it) {
        int cbo = (it & 1) * 20992, nbo = 20992 - cbo;
        if (it < 7) {
            SISSUE((it + 1) * 16, nbo);
            asm volatile("cp.async.commit_group;" ::: "memory");
            asm volatile("cp.async.wait_group 1;" ::: "memory");
        } else {
            asm volatile("cp.async.wait_group 0;" ::: "memory");
        }
        __syncthreads();
        mma_tile16((const unsigned*)(smem + cbo), (const unsigned*)(smem + cbo + 6144),
                   (const unsigned*)(smem + cbo + 12288), (const unsigned*)(smem + cbo + 16640),
                   wm, wn, g, tig, acc);
        __syncthreads();
    }
#undef SISSUE
    int sl = srcL[b];
    const float scale = 0.08838834764831845f;
#pragma unroll
    for (int i = 0; i < 2; ++i)
#pragma unroll
        for (int j = 0; j < 8; ++j) {
            int m = m0 + wm * 32 + i * 16 + g;
            int n = n0 + wn * 64 + j * 8 + 2 * tig;
            float* a = acc[i * 8 + j];
            bool p0 = (n >= sl), p1 = (n + 1 >= sl);
            float2 r0 = {p0 ? NEGF : a[0] * scale, p1 ? NEGF : a[1] * scale};
            float2 r1 = {p0 ? NEGF : a[2] * scale, p1 ? NEGF : a[3] * scale};
            *(float2*)&S[((size_t)bh * 512 + m) * 512 + n] = r0;
            *(float2*)&S[((size_t)bh * 512 + m + 8) * 512 + n] = r1;
        }
}

// pack V rows into pair-packed planes: vp[b][kp][c] = vh[b][2kp][c] | vh[b][2kp+1][c]<<16
__global__ void k_vpack(const ushort_t* __restrict__ Vh, const ushort_t* __restrict__ Vl,
                        unsigned* __restrict__ Uh, unsigned* __restrict__ Ul) {
    size_t idx = (size_t)blockIdx.x * 256 + threadIdx.x;
    int c = (int)(idx & 255);
    int kp = (int)((idx >> 8) & 255);
    int b = (int)(idx >> 16);
    size_t r0 = ((size_t)b * 512 + 2 * kp) * 256 + c;
    Uh[idx] = (unsigned)Vh[r0] | ((unsigned)Vh[r0 + 256] << 16);
    Ul[idx] = (unsigned)Vl[r0] | ((unsigned)Vl[r0 + 256] << 16);
}

// pipelined attn out: O = S @ V (packed), K=512
__global__ void __launch_bounds__(256, 2)
k_attnout(const ushort_t* __restrict__ Sh, const ushort_t* __restrict__ Sl,
          const unsigned* __restrict__ Vph, const unsigned* __restrict__ Vpl,
          ushort_t* __restrict__ Oh, ushort_t* __restrict__ Ol) {
    __shared__ __align__(16) char smem[41984];
    unsigned sbase = smem_u32(smem);
    int tid = threadIdx.x, w = tid >> 5, lane = tid & 31;
    int wm = w & 3, wn = w >> 2, g = lane >> 2, tig = lane & 3;
    int m0 = blockIdx.y * 128, bh = blockIdx.z;
    int b = bh >> 1, h = bh & 1;
    int arow = tid >> 1, apart = tid & 1;
    int bp = tid >> 5;
    float acc[16][4] = {};
#define AISSUE(k0v, bo) do {                                                  \
        size_t aoff = ((size_t)bh * 512 + m0 + arow) * 512 + (k0v) + apart * 8; \
        unsigned da = sbase + (bo) + arow * 48 + apart * 16;                  \
        CPA(da, Sh + aoff, 16u); CPA(da + 6144, Sl + aoff, 16u);              \
        size_t boff = ((size_t)b * 256 + (k0v) / 2 + bp) * 256 + h * 128 + lane * 4; \
        unsigned db = sbase + (bo) + 12288 + bp * 544 + lane * 16;            \
        CPA(db, Vph + boff, 16u); CPA(db + 4352, Vpl + boff, 16u);            \
    } while (0)
    AISSUE(0, 0);
    asm volatile("cp.async.commit_group;" ::: "memory");
    for (int it = 0; it < 32; ++it) {
        int cbo = (it & 1) * 20992, nbo = 20992 - cbo;
        if (it < 31) {
            AISSUE((it + 1) * 16, nbo);
            asm volatile("cp.async.commit_group;" ::: "memory");
            asm volatile("cp.async.wait_group 1;" ::: "memory");
        } else {
            asm volatile("cp.async.wait_group 0;" ::: "memory");
        }
        __syncthreads();
        mma_tile16((const unsigned*)(smem + cbo), (const unsigned*)(smem + cbo + 6144),
                   (const unsigned*)(smem + cbo + 12288), (const unsigned*)(smem + cbo + 16640),
                   wm, wn, g, tig, acc);
        __syncthreads();
    }
#undef AISSUE
#pragma unroll
    for (int i = 0; i < 2; ++i)
#pragma unroll
        for (int j = 0; j < 8; ++j) {
            int m = m0 + wm * 32 + i * 16 + g;
            int n = h * 128 + wn * 64 + j * 8 + 2 * tig;
            float* a = acc[i * 8 + j];
            wsplit2(Oh, Ol, (size_t)(b * 512 + m) * 256 + n, a[0], a[1]);
            wsplit2(Oh, Ol, (size_t)(b * 512 + m + 8) * 256 + n, a[2], a[3]);
        }
}

// ================= producers / elementwise =================
__global__ void k_embed(const int* __restrict__ tok, const float* __restrict__ emb,
                        const float* __restrict__ pos, float* __restrict__ x,
                        ushort_t* __restrict__ xh, ushort_t* __restrict__ xl) {
    int row = blockIdx.x, d = threadIdx.x;
    int t = row & 511;
    int id = tok[row];
    size_t off = (size_t)row * 256 + d;
    float v = emb[(size_t)id * 256 + d] + pos[(size_t)t * 256 + d];
    x[off] = v;
    ushort_t h, l; split1(v, h, l);
    xh[off] = h; xl[off] = l;
}

__global__ void k_softmax(const float* __restrict__ S, ushort_t* __restrict__ Sh,
                          ushort_t* __restrict__ Sl) {
    __shared__ float red[4];
    size_t row = blockIdx.x;
    float4 v = ((const float4*)(S + row * 512))[threadIdx.x];
    int lane = threadIdx.x & 31, wid = threadIdx.x >> 5;
    float m = fmaxf(fmaxf(v.x, v.y), fmaxf(v.z, v.w));
#pragma unroll
    for (int o = 16; o > 0; o >>= 1) m = fmaxf(m, __shfl_xor_sync(~0u, m, o));
    if (lane == 0) red[wid] = m;
    __syncthreads();
    m = fmaxf(fmaxf(red[0], red[1]), fmaxf(red[2], red[3]));
    __syncthreads();
    v.x = expf(v.x - m); v.y = expf(v.y - m); v.z = expf(v.z - m); v.w = expf(v.w - m);
    float s = v.x + v.y + v.z + v.w;
#pragma unroll
    for (int o = 16; o > 0; o >>= 1) s += __shfl_xor_sync(~0u, s, o);
    if (lane == 0) red[wid] = s;
    __syncthreads();
    s = red[0] + red[1] + red[2] + red[3];
    float inv = 1.0f / s;
    size_t off = row * 512 + threadIdx.x * 4;
    wsplit2(Sh, Sl, off, v.x * inv, v.y * inv);
    wsplit2(Sh, Sl, off + 2, v.z * inv, v.w * inv);
}

__global__ void k_lnres(const float* __restrict__ t, const float* __restrict__ res,
                        const float* __restrict__ gam, const float* __restrict__ bet,
                        const int* __restrict__ srcL, float* __restrict__ out,
                        ushort_t* __restrict__ oh, ushort_t* __restrict__ ol) {
    __shared__ float red[8];
    int row = blockIdx.x, d = threadIdx.x;
    size_t off = (size_t)row * 256 + d;
    float val = t[off] + res[off];
    float s = val;
#pragma unroll
    for (int o = 16; o > 0; o >>= 1) s += __shfl_xor_sync(~0u, s, o);
    if ((d & 31) == 0) red[d >> 5] = s;
    __syncthreads();
    float tot = 0.f;
#pragma unroll
    for (int i = 0; i < 8; ++i) tot += red[i];
    float mean = tot * (1.0f / 256.0f);
    float dv = val - mean;
    __syncthreads();
    float s2 = dv * dv;
#pragma unroll
    for (int o = 16; o > 0; o >>= 1) s2 += __shfl_xor_sync(~0u, s2, o);
    if ((d & 31) == 0) red[d >> 5] = s2;
    __syncthreads();
    float tot2 = 0.f;
#pragma unroll
    for (int i = 0; i < 8; ++i) tot2 += red[i];
    float o = dv * rsqrtf(tot2 * (1.0f / 256.0f) + 1e-5f) * gam[d] + bet[d];
    if ((row & 511) >= srcL[row >> 9]) o = 0.f;
    out[off] = o;
    ushort_t h, l; split1(o, h, l);
    oh[off] = h; ol[off] = l;
}

// pack QKV weights: [L][256][256] x3 -> planes [L][128kp][768]
__global__ void k_packqkv(const float* __restrict__ wq, const float* __restrict__ wk,
                          const float* __restrict__ wv, unsigned* __restrict__ Uh,
                          unsigned* __restrict__ Ul) {
    size_t idx = (size_t)blockIdx.x * 256 + threadIdx.x;   // over 4*128*768
    int n = (int)(idx % 768);
    size_t t = idx / 768;
    int kp = (int)(t % 128);
    int l = (int)(t / 128);
    int seg = n >> 8, c = n & 255;
    const float* W = ((seg == 0) ? wq : ((seg == 1) ? wk : wv)) + (size_t)l * 65536;
    float a = W[(2 * kp) * 256 + c], b = W[(2 * kp + 1) * 256 + c];
    ushort_t ha, la, hb, lb;
    split1(a, ha, la); split1(b, hb, lb);
    Uh[idx] = (unsigned)ha | ((unsigned)hb << 16);
    Ul[idx] = (unsigned)la | ((unsigned)lb << 16);
}

__global__ void k_packsplit(const float* __restrict__ src, unsigned* __restrict__ Uh,
                            unsigned* __restrict__ Ul, int nshift) {
    size_t idx = (size_t)blockIdx.x * 256 + threadIdx.x;
    size_t kp = idx >> nshift;
    int n = (int)(idx & ((1u << nshift) - 1));
    size_t N = (size_t)1 << nshift;
    float a = src[(2 * kp) * N + n], b = src[(2 * kp + 1) * N + n];
    ushort_t ha, la, hb, lb;
    split1(a, ha, la); split1(b, hb, lb);
    Uh[idx] = (unsigned)ha | ((unsigned)hb << 16);
    Ul[idx] = (unsigned)la | ((unsigned)lb << 16);
}

// ================= MAS + expand =================
__global__ void k_vtrans(const float* __restrict__ val, float* __restrict__ vt,
                         const int* __restrict__ srcL, const int* __restrict__ melL) {
    __shared__ float s[32][33];
    int b = blockIdx.z;
    int x0 = blockIdx.x * 32, y0 = blockIdx.y * 32;
    int sl = srcL[b], ml = melL[b];
    const float* vp = val + (size_t)b * 512 * 1024;
    float* op = vt + (size_t)b * 1024 * 512;
    for (int i = threadIdx.y; i < 32; i += 8) {
        int x = x0 + i, y = y0 + threadIdx.x;
        float v = vp[(size_t)x * 1024 + y];
        s[i][threadIdx.x] = (x < sl && y < ml) ? v : 0.f;
    }
    __syncthreads();
    for (int j = threadIdx.y; j < 32; j += 8)
        op[(size_t)(y0 + j) * 512 + x0 + threadIdx.x] = s[threadIdx.x][j];
}

__global__ void k_masdp(const float* __restrict__ vt, const int* __restrict__ srcL,
                        const int* __restrict__ melL, unsigned* __restrict__ dir) {
    __shared__ float bnd[2][16];
    int b = blockIdx.x, x = threadIdx.x;
    int sl = srcL[b], ml = melL[b];
    int lane = x & 31, wid = x >> 5;
    float v = 0.f;
    float val = vt[(size_t)b * 1024 * 512 + x];
    for (int j = 0; j < 1024; ++j) {
        if (lane == 31) bnd[j & 1][wid] = v;
        __syncthreads();
        float v0 = __shfl_up_sync(0xffffffffu, v, 1);
        if (lane == 0) v0 = wid ? bnd[j & 1][wid - 1] : NEGF;
        float valn = 0.f;
        if (j + 1 < 1024) valn = vt[((size_t)b * 1024 + j + 1) * 512 + x];
        bool d = (v >= v0);
        float vmax = d ? v : v0;
        float vnew = (x <= j) ? (vmax + val) : NEGF;
        bool dm = (x < sl && j < ml) ? d : true;
        unsigned bal = __ballot_sync(0xffffffffu, dm);
        if (lane == 0) dir[((size_t)b * 1024 + j) * 16 + wid] = bal;
        v = vnew;
        val = valn;
    }
}

__global__ void k_masbt(const unsigned* __restrict__ dir, const int* __restrict__ srcL,
                        int* __restrict__ idxout) {
    int b = threadIdx.x;
    if (b >= 32) return;
    int idx = srcL[b] - 1;
    for (int y0 = 1023; y0 >= 0; y0 -= 8) {
        int w0 = idx >> 5;
        unsigned wA[8], wB[8];
#pragma unroll
        for (int d = 0; d < 8; ++d) {
            size_t base = ((size_t)b * 1024 + (y0 - d)) * 16;
            wA[d] = dir[base + w0];
            wB[d] = (w0 > 0) ? dir[base + w0 - 1] : 0u;
        }
#pragma unroll
        for (int d = 0; d < 8; ++d) {
            int y = y0 - d;
            idxout[b * 1024 + y] = idx;
            int wcur = idx >> 5;
            unsigned word = (wcur == w0) ? wA[d] : wB[d];
            idx += (int)((word >> (idx & 31)) & 1u) - 1;
        }
    }
}

__global__ void k_expand(const float* __restrict__ X, const int* __restrict__ idx,
                         const int* __restrict__ srcL, const int* __restrict__ melL,
                         float* __restrict__ out) {
    int row = blockIdx.x;
    int b = row >> 10, y = row & 1023;
    int d = threadIdx.x;
    float o = 0.f;
    if (y < melL[b]) {
        int ix = idx[row];
        if (ix >= 0 && ix < srcL[b])
            o = X[((size_t)(b << 9) + ix) * 256 + d];
    }
    out[(size_t)row * 256 + d] = o;
}

// ================= launch =================
extern "C" void kernel_launch(void* const* d_in, const int* in_sizes, int n_in,
                              void* d_out, int out_size) {
    const int* tokens = (const int*)d_in[0];
    const int* srcL   = (const int*)d_in[1];
    const int* melL   = (const int*)d_in[2];
    const float* value = (const float*)d_in[3];
    const float* embed = (const float*)d_in[4];
    const float* pos   = (const float*)d_in[5];
    const float* wq = (const float*)d_in[6];  const float* bq = (const float*)d_in[7];
    const float* wk = (const float*)d_in[8];  const float* bk = (const float*)d_in[9];
    const float* wv = (const float*)d_in[10]; const float* bv = (const float*)d_in[11];
    const float* wo = (const float*)d_in[12]; const float* bo = (const float*)d_in[13];
    const float* ln1g = (const float*)d_in[14]; const float* ln1b = (const float*)d_in[15];
    const float* c1w = (const float*)d_in[16]; const float* c1b = (const float*)d_in[17];
    const float* c2w = (const float*)d_in[18]; const float* c2b = (const float*)d_in[19];
    const float* ln2g = (const float*)d_in[20]; const float* ln2b = (const float*)d_in[21];
    float* out = (float*)d_out;

    float *px, *pt, *ps, *pvt;
    ushort_t *pxh, *pxl, *pqh, *pql, *pkh, *pkl, *pvh, *pvl, *poh, *pol;
    ushort_t *psh, *psl, *phh, *pw1h, *pw2h;
    unsigned *pwqkvh, *pwqkvl, *pwoh, *pwol, *pvph, *pvpl;
    unsigned* pdir; int* pidx;
    cudaGetSymbolAddress((void**)&px, g_x);   cudaGetSymbolAddress((void**)&pt, g_t);
    cudaGetSymbolAddress((void**)&ps, g_s);   cudaGetSymbolAddress((void**)&pvt, g_vt);
    cudaGetSymbolAddress((void**)&pxh, g_xh); cudaGetSymbolAddress((void**)&pxl, g_xl);
    cudaGetSymbolAddress((void**)&pqh, g_qh); cudaGetSymbolAddress((void**)&pql, g_ql);
    cudaGetSymbolAddress((void**)&pkh, g_kh); cudaGetSymbolAddress((void**)&pkl, g_kl);
    cudaGetSymbolAddress((void**)&pvh, g_vh); cudaGetSymbolAddress((void**)&pvl, g_vl);
    cudaGetSymbolAddress((void**)&poh, g_oh); cudaGetSymbolAddress((void**)&pol, g_ol);
    cudaGetSymbolAddress((void**)&psh, g_sh); cudaGetSymbolAddress((void**)&psl, g_sl);
    cudaGetSymbolAddress((void**)&phh, g_hh);
    cudaGetSymbolAddress((void**)&pw1h, g_w1h); cudaGetSymbolAddress((void**)&pw2h, g_w2h);
    cudaGetSymbolAddress((void**)&pwqkvh, g_wqkvh); cudaGetSymbolAddress((void**)&pwqkvl, g_wqkvl);
    cudaGetSymbolAddress((void**)&pwoh, g_woh); cudaGetSymbolAddress((void**)&pwol, g_wol);
    cudaGetSymbolAddress((void**)&pvph, g_vph); cudaGetSymbolAddress((void**)&pvpl, g_vpl);
    cudaGetSymbolAddress((void**)&pdir, g_dir); cudaGetSymbolAddress((void**)&pidx, g_idx);

    const int SMEMC = 40960;
    cudaFuncSetAttribute(k_conv, cudaFuncAttributeMaxDynamicSharedMemorySize, SMEMC);

    dim3 blk256(256);
    // weight prep
    k_wprep<<<18432, blk256>>>(c1w, pw1h, 1024, 256);
    k_wprep<<<18432, blk256>>>(c2w, pw2h, 256, 1024);
    k_packqkv<<<1536, blk256>>>(wq, wk, wv, pwqkvh, pwqkvl);
    k_packsplit<<<512, blk256>>>(wo, pwoh, pwol, 8);
    // inputs
    k_vtrans<<<dim3(16, 32, 32), dim3(32, 8)>>>(value, pvt, srcL, melL);
    k_embed<<<16384, blk256>>>(tokens, embed, pos, px, pxh, pxl);

    for (int l = 0; l < 4; ++l) {
        const unsigned *wqkvh_l = pwqkvh + l * 98304, *wqkvl_l = pwqkvl + l * 98304;
        const unsigned *woh_l = pwoh + l * 32768, *wol_l = pwol + l * 32768;

        k_gemmqkv<<<dim3(6, 128), blk256>>>(pxh, pxl, wqkvh_l, wqkvl_l,
                                            bq + l * 256, bk + l * 256, bv + l * 256,
                                            pqh, pql, pkh, pkl, pvh, pvl);
        k_vpack<<<8192, blk256>>>(pvh, pvl, pvph, pvpl);
        k_scores<<<dim3(4, 4, 64), blk256>>>(pqh, pql, pkh, pkl, ps, srcL);
        k_softmax<<<32768, 128>>>(ps, psh, psl);
        k_attnout<<<dim3(1, 4, 64), blk256>>>(psh, psl, pvph, pvpl, poh, pol);
        k_gemm_bias<<<dim3(2, 128), blk256>>>(poh, pol, woh_l, wol_l, bo + l * 256, pt);
        k_lnres<<<16384, blk256>>>(pt, px, ln1g + l * 256, ln1b + l * 256, srcL, px, pxh, pxl);

        k_conv<<<dim3(8, 128), blk256, SMEMC>>>(pxh, pw1h + (size_t)l * 2359296,
                                                c1b + l * 1024, 256, 3, 1, phh, nullptr, 1024);
        k_conv<<<dim3(2, 128), blk256, SMEMC>>>(phh, pw2h + (size_t)l * 2359296,
                                                c2b + l * 256, 1024, 5, 0, nullptr, pt, 256);
        k_lnres<<<16384, blk256>>>(pt, px, ln2g + l * 256, ln2b + l * 256, srcL, px, pxh, pxl);
    }

    k_masdp<<<32, 512>>>(pvt, srcL, melL, pdir);
    k_masbt<<<1, 32>>>(pdir, srcL, pidx);
    k_expand<<<32768, blk256>>>(px, pidx, srcL, melL, out);
}

// round 17
// speedup vs baseline: 2.3782x; 1.0399x over previous
#include <cuda_runtime.h>
#include <cuda_fp16.h>
#include <stdint.h>
#include <math.h>

#define NEGF (-1e9f)
typedef unsigned short ushort_t;

// ---------- scratch ----------
__device__ float    g_x [4194304];
__device__ float    g_t [4194304];
__device__ float    g_s [16777216];
__device__ float    g_vt[16777216];
__device__ ushort_t g_xh[4194304],  g_xl[4194304];
__device__ ushort_t g_qh[4194304],  g_ql[4194304];
__device__ ushort_t g_kh[4194304],  g_kl[4194304];
__device__ ushort_t g_vh[4194304],  g_vl[4194304];
__device__ ushort_t g_oh[4194304],  g_ol[4194304];
__device__ ushort_t g_sh[16777216], g_sl[16777216];
__device__ ushort_t g_hh[16777216];
__device__ ushort_t g_w1h[9437184];   // [L][9][1024][256] fp16 (transposed)
__device__ ushort_t g_w2h[9437184];   // [L][9][256][1024]
__device__ unsigned g_wqkvh[393216], g_wqkvl[393216];  // [L][128kp][768]
__device__ unsigned g_woh[131072], g_wol[131072];
__device__ unsigned g_vph[2097152], g_vpl[2097152];    // [B][256kp][256] packed V
__device__ unsigned g_dir[524288];
__device__ int      g_idx[32768];

// ---------- fp16 split helpers ----------
__device__ __forceinline__ void split1(float v, ushort_t& h, ushort_t& l) {
    __half hh = __float2half_rn(v);
    __half ll = __float2half_rn(v - __half2float(hh));
    h = __half_as_ushort(hh); l = __half_as_ushort(ll);
}
__device__ __forceinline__ void wsplit2(ushort_t* Ph, ushort_t* Pl, size_t off,
                                        float v0, float v1) {
    ushort_t h0, l0, h1, l1;
    split1(v0, h0, l0); split1(v1, h1, l1);
    *(unsigned*)&Ph[off] = (unsigned)h0 | ((unsigned)h1 << 16);
    *(unsigned*)&Pl[off] = (unsigned)l0 | ((unsigned)l1 << 16);
}
__device__ __forceinline__ unsigned smem_u32(const void* p) {
    unsigned a;
    asm("{ .reg .u64 t; cvta.to.shared.u64 t, %1; cvt.u32.u64 %0, t; }" : "=r"(a) : "l"(p));
    return a;
}

// ---------- mma core ----------
__device__ __forceinline__ void mma16(float c[4], const unsigned a[4], const unsigned b[2]) {
    asm volatile(
        "mma.sync.aligned.m16n8k16.row.col.f32.f16.f16.f32 "
        "{%0,%1,%2,%3},{%4,%5,%6,%7},{%8,%9},{%0,%1,%2,%3};\n"
        : "+f"(c[0]), "+f"(c[1]), "+f"(c[2]), "+f"(c[3])
        : "r"(a[0]), "r"(a[1]), "r"(a[2]), "r"(a[3]), "r"(b[0]), "r"(b[1]));
}

#define CPA(d, s, n) \
    asm volatile("cp.async.cg.shared.global [%0],[%1],16,%2;" :: "r"(d), "l"(s), "r"(n) : "memory")
#define CPA4(d, s) \
    asm volatile("cp.async.ca.shared.global [%0],[%1],4;" :: "r"(d), "l"(s) : "memory")

// ================= conv: pure fp16 (aH*bH), K-chunk 32, pipelined =================
__global__ void __launch_bounds__(256, 2)
k_conv(const ushort_t* __restrict__ Ah,
       const ushort_t* __restrict__ Wh,
       const float* __restrict__ bias, int Cin, int nsh, int relu_split,
       ushort_t* __restrict__ OHh,
       float* __restrict__ Of, int outld) {
    extern __shared__ __align__(16) char smem[];
    unsigned sbase = smem_u32(smem);
    int tid = threadIdx.x, wd = tid >> 5, lane = tid & 31;
    int wm = wd & 3, wn = wd >> 2, g = lane >> 2, tig = lane & 3;
    int n0 = blockIdx.x * 128, m0 = blockIdx.y * 128;
    int Coutv = gridDim.x * 128;
    int bbase = m0 & ~511, tb = m0 & 511;
    int ncmask = (1 << nsh) - 1;
    int NIT = 9 << nsh;
    int lrow = tid >> 1, lhalf = tid & 1;
    size_t wstr = (size_t)Coutv * Cin;
    float acc[16][4] = {};

#define ISSUE(itv, bo) do {                                                   \
        int dk_ = (itv) >> nsh; int kc_ = ((itv) & ncmask) << 5;              \
        int t_ = tb + lrow + dk_ - 4;                                         \
        unsigned okn = ((unsigned)t_ < 512u) ? 16u : 0u;                      \
        size_t ar_ = (size_t)(bbase + t_) * Cin + kc_ + lhalf * 16;          \
        unsigned da_ = sbase + (bo) + lrow * 80 + lhalf * 32;                 \
        CPA(da_, Ah + ar_, okn);        CPA(da_ + 16, Ah + ar_ + 8, okn);     \
        size_t wr_ = (size_t)dk_ * wstr + (size_t)(n0 + lrow) * Cin + kc_ + lhalf * 16; \
        CPA(da_ + 10240, Wh + wr_, 16u); CPA(da_ + 10256, Wh + wr_ + 8, 16u); \
    } while (0)

    ISSUE(0, 0);
    asm volatile("cp.async.commit_group;" ::: "memory");
    for (int it = 0; it < NIT; ++it) {
        int cbo = (it & 1) * 20480, nbo = 20480 - cbo;
        if (it + 1 < NIT) {
            ISSUE(it + 1, nbo);
            asm volatile("cp.async.commit_group;" ::: "memory");
            asm volatile("cp.async.wait_group 1;" ::: "memory");
        } else {
            asm volatile("cp.async.wait_group 0;" ::: "memory");
        }
        __syncthreads();
        const unsigned* AH = (const unsigned*)(smem + cbo);
        const unsigned* BH = (const unsigned*)(smem + cbo + 10240);
        unsigned aH0[2][4], aH1[2][4];
#pragma unroll
        for (int i = 0; i < 2; ++i) {
            int r = wm * 32 + i * 16 + g;
            int b0 = r * 20 + tig, b1 = (r + 8) * 20 + tig;
            aH0[i][0] = AH[b0];     aH0[i][1] = AH[b1];
            aH0[i][2] = AH[b0 + 4]; aH0[i][3] = AH[b1 + 4];
            aH1[i][0] = AH[b0 + 8];  aH1[i][1] = AH[b1 + 8];
            aH1[i][2] = AH[b0 + 12]; aH1[i][3] = AH[b1 + 12];
        }
#pragma unroll
        for (int j = 0; j < 8; ++j) {
            int c = (wn * 64 + j * 8 + g) * 20 + tig;
            unsigned bF0[2] = {BH[c], BH[c + 4]};
            unsigned bF1[2] = {BH[c + 8], BH[c + 12]};
#pragma unroll
            for (int i = 0; i < 2; ++i) {
                mma16(acc[i * 8 + j], aH0[i], bF0);
                mma16(acc[i * 8 + j], aH1[i], bF1);
            }
        }
        __syncthreads();
    }
#undef ISSUE
#pragma unroll
    for (int i = 0; i < 2; ++i)
#pragma unroll
        for (int j = 0; j < 8; ++j) {
            int m = m0 + wm * 32 + i * 16 + g;
            int n = n0 + wn * 64 + j * 8 + 2 * tig;
            float* a = acc[i * 8 + j];
            float b0 = bias[n], b1 = bias[n + 1];
            float v0 = a[0] + b0, v1 = a[1] + b1, v2 = a[2] + b0, v3 = a[3] + b1;
            size_t o0 = (size_t)m * outld + n, o1 = (size_t)(m + 8) * outld + n;
            if (relu_split) {
                __half h0 = __float2half_rn(fmaxf(v0, 0.f));
                __half h1 = __float2half_rn(fmaxf(v1, 0.f));
                __half h2 = __float2half_rn(fmaxf(v2, 0.f));
                __half h3 = __float2half_rn(fmaxf(v3, 0.f));
                *(unsigned*)&OHh[o0] = (unsigned)__half_as_ushort(h0) | ((unsigned)__half_as_ushort(h1) << 16);
                *(unsigned*)&OHh[o1] = (unsigned)__half_as_ushort(h2) | ((unsigned)__half_as_ushort(h3) << 16);
            } else {
                *(float2*)&Of[o0] = make_float2(v0, v1);
                *(float2*)&Of[o1] = make_float2(v2, v3);
            }
        }
}

// conv weight prep: src[l][R][C][9] fp32 -> Wh [l][9][R][C] fp16 (hi only)
__global__ void k_wprep(const float* __restrict__ src, ushort_t* __restrict__ Wh,
                        int R, int C) {
    size_t idx = ((size_t)blockIdx.x * 256 + threadIdx.x) * 2;
    int c = (int)(idx % C);
    size_t t1 = idx / C;
    int r = (int)(t1 % R);
    size_t t2 = t1 / R;
    int dk = (int)(t2 % 9);
    int l = (int)(t2 / 9);
    size_t sb = (((size_t)l * R + r) * C + c) * 9 + dk;
    __half h0 = __float2half_rn(src[sb]), h1 = __float2half_rn(src[sb + 9]);
    *(unsigned*)&Wh[idx] = (unsigned)__half_as_ushort(h0) | ((unsigned)__half_as_ushort(h1) << 16);
}

// ================= mma.sync attention (3-pass) =================
__device__ __forceinline__ void mma_tile16(const unsigned* AsH, const unsigned* AsL,
                                           const unsigned* BsH, const unsigned* BsL,
                                           int wm, int wn, int g, int tig,
                                           float (*acc)[4]) {
    unsigned aH[2][4], aL[2][4];
#pragma unroll
    for (int i = 0; i < 2; ++i) {
        int r = (wm * 32 + i * 16 + g) * 12 + tig;
        aH[i][0] = AsH[r]; aH[i][1] = AsH[r + 96]; aH[i][2] = AsH[r + 4]; aH[i][3] = AsH[r + 100];
        aL[i][0] = AsL[r]; aL[i][1] = AsL[r + 96]; aL[i][2] = AsL[r + 4]; aL[i][3] = AsL[r + 100];
    }
#pragma unroll
    for (int j = 0; j < 8; ++j) {
        int nb = wn * 64 + j * 8 + g;
        unsigned bH[2] = {BsH[tig * 136 + nb], BsH[(tig + 4) * 136 + nb]};
        unsigned bL[2] = {BsL[tig * 136 + nb], BsL[(tig + 4) * 136 + nb]};
#pragma unroll
        for (int i = 0; i < 2; ++i) {
            mma16(acc[i * 8 + j], aH[i], bH);
            mma16(acc[i * 8 + j], aL[i], bH);
            mma16(acc[i * 8 + j], aH[i], bL);
        }
    }
}

// merged QKV projection
__global__ void __launch_bounds__(256, 2)
k_gemmqkv(const ushort_t* __restrict__ Ah, const ushort_t* __restrict__ Al,
          const unsigned* __restrict__ Bph, const unsigned* __restrict__ Bpl,
          const float* __restrict__ bq, const float* __restrict__ bk,
          const float* __restrict__ bv,
          ushort_t* __restrict__ Qh, ushort_t* __restrict__ Ql,
          ushort_t* __restrict__ Kh, ushort_t* __restrict__ Kl,
          ushort_t* __restrict__ Vh, ushort_t* __restrict__ Vl) {
    __shared__ __align__(16) char smem[41984];
    unsigned sbase = smem_u32(smem);
    int tid = threadIdx.x, w = tid >> 5, lane = tid & 31;
    int wm = w & 3, wn = w >> 2, g = lane >> 2, tig = lane & 3;
    int n0 = blockIdx.x * 128, m0 = blockIdx.y * 128;
    int arow = tid >> 1, apart = tid & 1;
    int bp = tid >> 5;
    float acc[16][4] = {};
#define QISSUE(k0v, bo) do {                                                  \
        size_t aoff = (size_t)(m0 + arow) * 256 + (k0v) + apart * 8;          \
        unsigned da = sbase + (bo) + arow * 48 + apart * 16;                  \
        CPA(da, Ah + aoff, 16u); CPA(da + 6144, Al + aoff, 16u);              \
        size_t boff = (size_t)((k0v) / 2 + bp) * 768 + n0 + lane * 4;         \
        unsigned db = sbase + (bo) + 12288 + bp * 544 + lane * 16;            \
        CPA(db, Bph + boff, 16u); CPA(db + 4352, Bpl + boff, 16u);            \
    } while (0)
    QISSUE(0, 0);
    asm volatile("cp.async.commit_group;" ::: "memory");
    for (int it = 0; it < 16; ++it) {
        int cbo = (it & 1) * 20992, nbo = 20992 - cbo;
        if (it < 15) {
            QISSUE((it + 1) * 16, nbo);
            asm volatile("cp.async.commit_group;" ::: "memory");
            asm volatile("cp.async.wait_group 1;" ::: "memory");
        } else {
            asm volatile("cp.async.wait_group 0;" ::: "memory");
        }
        __syncthreads();
        mma_tile16((const unsigned*)(smem + cbo), (const unsigned*)(smem + cbo + 6144),
                   (const unsigned*)(smem + cbo + 12288), (const unsigned*)(smem + cbo + 16640),
                   wm, wn, g, tig, acc);
        __syncthreads();
    }
#undef QISSUE
    int seg = n0 >> 8;
    const float* bias = (seg == 0) ? bq : ((seg == 1) ? bk : bv);
    ushort_t* Ch = (seg == 0) ? Qh : ((seg == 1) ? Kh : Vh);
    ushort_t* Cl = (seg == 0) ? Ql : ((seg == 1) ? Kl : Vl);
#pragma unroll
    for (int i = 0; i < 2; ++i)
#pragma unroll
        for (int j = 0; j < 8; ++j) {
            int m = m0 + wm * 32 + i * 16 + g;
            int n = n0 + wn * 64 + j * 8 + 2 * tig;
            int col = n & 255;
            float b0 = bias[col], b1 = bias[col + 1];
            float* a = acc[i * 8 + j];
            wsplit2(Ch, Cl, (size_t)m * 256 + col, a[0] + b0, a[1] + b1);
            wsplit2(Ch, Cl, (size_t)(m + 8) * 256 + col, a[2] + b0, a[3] + b1);
        }
}

// pipelined O-projection GEMM
__global__ void __launch_bounds__(256, 2)
k_gemm_bias(const ushort_t* __restrict__ Ah, const ushort_t* __restrict__ Al,
            const unsigned* __restrict__ Bph, const unsigned* __restrict__ Bpl,
            const float* __restrict__ bias, float* __restrict__ Cf) {
    __shared__ __align__(16) char smem[41984];
    unsigned sbase = smem_u32(smem);
    int tid = threadIdx.x, w = tid >> 5, lane = tid & 31;
    int wm = w & 3, wn = w >> 2, g = lane >> 2, tig = lane & 3;
    int n0 = blockIdx.x * 128, m0 = blockIdx.y * 128;
    int arow = tid >> 1, apart = tid & 1;
    int bp = tid >> 5;
    float acc[16][4] = {};
#define GISSUE(k0v, bo) do {                                                  \
        size_t aoff = (size_t)(m0 + arow) * 256 + (k0v) + apart * 8;          \
        unsigned da = sbase + (bo) + arow * 48 + apart * 16;                  \
        CPA(da, Ah + aoff, 16u); CPA(da + 6144, Al + aoff, 16u);              \
        size_t boff = (size_t)((k0v) / 2 + bp) * 256 + n0 + lane * 4;         \
        unsigned db = sbase + (bo) + 12288 + bp * 544 + lane * 16;            \
        CPA(db, Bph + boff, 16u); CPA(db + 4352, Bpl + boff, 16u);            \
    } while (0)
    GISSUE(0, 0);
    asm volatile("cp.async.commit_group;" ::: "memory");
    for (int it = 0; it < 16; ++it) {
        int cbo = (it & 1) * 20992, nbo = 20992 - cbo;
        if (it < 15) {
            GISSUE((it + 1) * 16, nbo);
            asm volatile("cp.async.commit_group;" ::: "memory");
            asm volatile("cp.async.wait_group 1;" ::: "memory");
        } else {
            asm volatile("cp.async.wait_group 0;" ::: "memory");
        }
        __syncthreads();
        mma_tile16((const unsigned*)(smem + cbo), (const unsigned*)(smem + cbo + 6144),
                   (const unsigned*)(smem + cbo + 12288), (const unsigned*)(smem + cbo + 16640),
                   wm, wn, g, tig, acc);
        __syncthreads();
    }
#undef GISSUE
#pragma unroll
    for (int i = 0; i < 2; ++i)
#pragma unroll
        for (int j = 0; j < 8; ++j) {
            int m = m0 + wm * 32 + i * 16 + g;
            int n = n0 + wn * 64 + j * 8 + 2 * tig;
            float b0 = bias[n], b1 = bias[n + 1];
            float* a = acc[i * 8 + j];
            *(float2*)&Cf[(size_t)m * 256 + n] = make_float2(a[0] + b0, a[1] + b1);
            *(float2*)&Cf[(size_t)(m + 8) * 256 + n] = make_float2(a[2] + b0, a[3] + b1);
        }
}

// pipelined scores (skips GEMM for fully-masked n-blocks)
__global__ void __launch_bounds__(256, 2)
k_scores(const ushort_t* __restrict__ Qh, const ushort_t* __restrict__ Ql,
         const ushort_t* __restrict__ Kh, const ushort_t* __restrict__ Kl,
         float* __restrict__ S, const int* __restrict__ srcL) {
    __shared__ __align__(16) char smem[41984];
    unsigned sbase = smem_u32(smem);
    int tid = threadIdx.x, w = tid >> 5, lane = tid & 31;
    int wm = w & 3, wn = w >> 2, g = lane >> 2, tig = lane & 3;
    int n0 = blockIdx.x * 128, m0 = blockIdx.y * 128, bh = blockIdx.z;
    int b = bh >> 1, h = bh & 1;
    int sl = srcL[b];
    int arow = tid >> 1, apart = tid & 1;
    int btn = tid & 127, bpb = (tid >> 7) * 4;
    float acc[16][4] = {};
    if (n0 < sl) {
#define SISSUE(k0v, bo) do {                                                  \
        size_t aoff = (size_t)(b * 512 + m0 + arow) * 256 + h * 128 + (k0v) + apart * 8; \
        unsigned da = sbase + (bo) + arow * 48 + apart * 16;                  \
        CPA(da, Qh + aoff, 16u); CPA(da + 6144, Ql + aoff, 16u);              \
        size_t koff = (size_t)(b * 512 + n0 + btn) * 256 + h * 128 + (k0v) + bpb * 2; \
        const char* ksrc = (const char*)(Kh + koff);                          \
        const char* lsrc = (const char*)(Kl + koff);                          \
        _Pragma("unroll")                                                     \
        for (int i_ = 0; i_ < 4; ++i_) {                                      \
            unsigned db = sbase + (bo) + 12288 + ((bpb + i_) * 136 + btn) * 4; \
            CPA4(db, ksrc + i_ * 4);                                          \
            CPA4(db + 4352, lsrc + i_ * 4);                                   \
        }                                                                     \
    } while (0)
        SISSUE(0, 0);
        asm volatile("cp.async.commit_group;" ::: "memory");
        for (int it = 0; it < 8; ++it) {
            int cbo = (it & 1) * 20992, nbo = 20992 - cbo;
            if (it < 7) {
                SISSUE((it + 1) * 16, nbo);
                asm volatile("cp.async.commit_group;" ::: "memory");
                asm volatile("cp.async.wait_group 1;" ::: "memory");
            } else {
                asm volatile("cp.async.wait_group 0;" ::: "memory");
            }
            __syncthreads();
            mma_tile16((const unsigned*)(smem + cbo), (const unsigned*)(smem + cbo + 6144),
                       (const unsigned*)(smem + cbo + 12288), (const unsigned*)(smem + cbo + 16640),
                       wm, wn, g, tig, acc);
            __syncthreads();
        }
#undef SISSUE
    }
    const float scale = 0.08838834764831845f;
#pragma unroll
    for (int i = 0; i < 2; ++i)
#pragma unroll
        for (int j = 0; j < 8; ++j) {
            int m = m0 + wm * 32 + i * 16 + g;
            int n = n0 + wn * 64 + j * 8 + 2 * tig;
            float* a = acc[i * 8 + j];
            bool p0 = (n >= sl), p1 = (n + 1 >= sl);
            float2 r0 = {p0 ? NEGF : a[0] * scale, p1 ? NEGF : a[1] * scale};
            float2 r1 = {p0 ? NEGF : a[2] * scale, p1 ? NEGF : a[3] * scale};
            *(float2*)&S[((size_t)bh * 512 + m) * 512 + n] = r0;
            *(float2*)&S[((size_t)bh * 512 + m + 8) * 512 + n] = r1;
        }
}

// pack V rows into pair-packed planes
__global__ void k_vpack(const ushort_t* __restrict__ Vh, const ushort_t* __restrict__ Vl,
                        unsigned* __restrict__ Uh, unsigned* __restrict__ Ul) {
    size_t idx = (size_t)blockIdx.x * 256 + threadIdx.x;
    int c = (int)(idx & 255);
    int kp = (int)((idx >> 8) & 255);
    int b = (int)(idx >> 16);
    size_t r0 = ((size_t)b * 512 + 2 * kp) * 256 + c;
    Uh[idx] = (unsigned)Vh[r0] | ((unsigned)Vh[r0 + 256] << 16);
    Ul[idx] = (unsigned)Vl[r0] | ((unsigned)Vl[r0 + 256] << 16);
}

// pipelined attn out: K clamped to ceil(srcL/16) chunks (S exactly 0 beyond srcL)
__global__ void __launch_bounds__(256, 2)
k_attnout(const ushort_t* __restrict__ Sh, const ushort_t* __restrict__ Sl,
          const unsigned* __restrict__ Vph, const unsigned* __restrict__ Vpl,
          ushort_t* __restrict__ Oh, ushort_t* __restrict__ Ol,
          const int* __restrict__ srcL) {
    __shared__ __align__(16) char smem[41984];
    unsigned sbase = smem_u32(smem);
    int tid = threadIdx.x, w = tid >> 5, lane = tid & 31;
    int wm = w & 3, wn = w >> 2, g = lane >> 2, tig = lane & 3;
    int m0 = blockIdx.y * 128, bh = blockIdx.z;
    int b = bh >> 1, h = bh & 1;
    int NITa = (srcL[b] + 15) >> 4;
    int arow = tid >> 1, apart = tid & 1;
    int bp = tid >> 5;
    float acc[16][4] = {};
#define AISSUE(k0v, bo) do {                                                  \
        size_t aoff = ((size_t)bh * 512 + m0 + arow) * 512 + (k0v) + apart * 8; \
        unsigned da = sbase + (bo) + arow * 48 + apart * 16;                  \
        CPA(da, Sh + aoff, 16u); CPA(da + 6144, Sl + aoff, 16u);              \
        size_t boff = ((size_t)b * 256 + (k0v) / 2 + bp) * 256 + h * 128 + lane * 4; \
        unsigned db = sbase + (bo) + 12288 + bp * 544 + lane * 16;            \
        CPA(db, Vph + boff, 16u); CPA(db + 4352, Vpl + boff, 16u);            \
    } while (0)
    AISSUE(0, 0);
    asm volatile("cp.async.commit_group;" ::: "memory");
    for (int it = 0; it < NITa; ++it) {
        int cbo = (it & 1) * 20992, nbo = 20992 - cbo;
        if (it + 1 < NITa) {
            AISSUE((it + 1) * 16, nbo);
            asm volatile("cp.async.commit_group;" ::: "memory");
            asm volatile("cp.async.wait_group 1;" ::: "memory");
        } else {
            asm volatile("cp.async.wait_group 0;" ::: "memory");
        }
        __syncthreads();
        mma_tile16((const unsigned*)(smem + cbo), (const unsigned*)(smem + cbo + 6144),
                   (const unsigned*)(smem + cbo + 12288), (const unsigned*)(smem + cbo + 16640),
                   wm, wn, g, tig, acc);
        __syncthreads();
    }
#undef AISSUE
#pragma unroll
    for (int i = 0; i < 2; ++i)
#pragma unroll
        for (int j = 0; j < 8; ++j) {
            int m = m0 + wm * 32 + i * 16 + g;
            int n = h * 128 + wn * 64 + j * 8 + 2 * tig;
            float* a = acc[i * 8 + j];
            wsplit2(Oh, Ol, (size_t)(b * 512 + m) * 256 + n, a[0], a[1]);
            wsplit2(Oh, Ol, (size_t)(b * 512 + m + 8) * 256 + n, a[2], a[3]);
        }
}

// ================= producers / elementwise =================
__global__ void k_embed(const int* __restrict__ tok, const float* __restrict__ emb,
                        const float* __restrict__ pos, float* __restrict__ x,
                        ushort_t* __restrict__ xh, ushort_t* __restrict__ xl) {
    int row = blockIdx.x, d = threadIdx.x;
    int t = row & 511;
    int id = tok[row];
    size_t off = (size_t)row * 256 + d;
    float v = emb[(size_t)id * 256 + d] + pos[(size_t)t * 256 + d];
    x[off] = v;
    ushort_t h, l; split1(v, h, l);
    xh[off] = h; xl[off] = l;
}

// warp-per-row softmax (8 rows / 256-thread block; no block syncs)
__global__ void k_softmax(const float* __restrict__ S, ushort_t* __restrict__ Sh,
                          ushort_t* __restrict__ Sl) {
    int warp = threadIdx.x >> 5, lane = threadIdx.x & 31;
    size_t row = (size_t)blockIdx.x * 8 + warp;
    const float* p = S + row * 512;
    float4 v[4];
    float m = -3.4e38f;
#pragma unroll
    for (int q = 0; q < 4; ++q) {
        v[q] = *(const float4*)(p + q * 128 + lane * 4);
        m = fmaxf(m, fmaxf(fmaxf(v[q].x, v[q].y), fmaxf(v[q].z, v[q].w)));
    }
#pragma unroll
    for (int o = 16; o > 0; o >>= 1) m = fmaxf(m, __shfl_xor_sync(~0u, m, o));
    float s = 0.f;
#pragma unroll
    for (int q = 0; q < 4; ++q) {
        v[q].x = expf(v[q].x - m); v[q].y = expf(v[q].y - m);
        v[q].z = expf(v[q].z - m); v[q].w = expf(v[q].w - m);
        s += v[q].x + v[q].y + v[q].z + v[q].w;
    }
#pragma unroll
    for (int o = 16; o > 0; o >>= 1) s += __shfl_xor_sync(~0u, s, o);
    float inv = 1.0f / s;
#pragma unroll
    for (int q = 0; q < 4; ++q) {
        size_t off = row * 512 + q * 128 + lane * 4;
        wsplit2(Sh, Sl, off, v[q].x * inv, v[q].y * inv);
        wsplit2(Sh, Sl, off + 2, v[q].z * inv, v[q].w * inv);
    }
}

// warp-per-row layernorm(t+res) (8 rows / block; no block syncs)
__global__ void k_lnres(const float* __restrict__ t, const float* __restrict__ res,
                        const float* __restrict__ gam, const float* __restrict__ bet,
                        const int* __restrict__ srcL, float* __restrict__ out,
                        ushort_t* __restrict__ oh, ushort_t* __restrict__ ol) {
    int warp = threadIdx.x >> 5, lane = threadIdx.x & 31;
    int row = blockIdx.x * 8 + warp;
    size_t base = (size_t)row * 256;
    float v[8];
    float s = 0.f;
#pragma unroll
    for (int k = 0; k < 8; ++k) {
        int d = k * 32 + lane;
        v[k] = t[base + d] + res[base + d];
        s += v[k];
    }
#pragma unroll
    for (int o = 16; o > 0; o >>= 1) s += __shfl_xor_sync(~0u, s, o);
    float mean = s * (1.0f / 256.0f);
    float s2 = 0.f;
#pragma unroll
    for (int k = 0; k < 8; ++k) { v[k] -= mean; s2 += v[k] * v[k]; }
#pragma unroll
    for (int o = 16; o > 0; o >>= 1) s2 += __shfl_xor_sync(~0u, s2, o);
    float inv = rsqrtf(s2 * (1.0f / 256.0f) + 1e-5f);
    bool pad = ((row & 511) >= srcL[row >> 9]);
#pragma unroll
    for (int k = 0; k < 8; ++k) {
        int d = k * 32 + lane;
        float o = pad ? 0.f : (v[k] * inv * gam[d] + bet[d]);
        out[base + d] = o;
        ushort_t h, l; split1(o, h, l);
        oh[base + d] = h; ol[base + d] = l;
    }
}

// pack QKV weights: [L][256][256] x3 -> planes [L][128kp][768]
__global__ void k_packqkv(const float* __restrict__ wq, const float* __restrict__ wk,
                          const float* __restrict__ wv, unsigned* __restrict__ Uh,
                          unsigned* __restrict__ Ul) {
    size_t idx = (size_t)blockIdx.x * 256 + threadIdx.x;
    int n = (int)(idx % 768);
    size_t t = idx / 768;
    int kp = (int)(t % 128);
    int l = (int)(t / 128);
    int seg = n >> 8, c = n & 255;
    const float* W = ((seg == 0) ? wq : ((seg == 1) ? wk : wv)) + (size_t)l * 65536;
    float a = W[(2 * kp) * 256 + c], b = W[(2 * kp + 1) * 256 + c];
    ushort_t ha, la, hb, lb;
    split1(a, ha, la); split1(b, hb, lb);
    Uh[idx] = (unsigned)ha | ((unsigned)hb << 16);
    Ul[idx] = (unsigned)la | ((unsigned)lb << 16);
}

__global__ void k_packsplit(const float* __restrict__ src, unsigned* __restrict__ Uh,
                            unsigned* __restrict__ Ul, int nshift) {
    size_t idx = (size_t)blockIdx.x * 256 + threadIdx.x;
    size_t kp = idx >> nshift;
    int n = (int)(idx & ((1u << nshift) - 1));
    size_t N = (size_t)1 << nshift;
    float a = src[(2 * kp) * N + n], b = src[(2 * kp + 1) * N + n];
    ushort_t ha, la, hb, lb;
    split1(a, ha, la); split1(b, hb, lb);
    Uh[idx] = (unsigned)ha | ((unsigned)hb << 16);
    Ul[idx] = (unsigned)la | ((unsigned)lb << 16);
}

// ================= MAS + expand =================
__global__ void k_vtrans(const float* __restrict__ val, float* __restrict__ vt,
                         const int* __restrict__ srcL, const int* __restrict__ melL) {
    __shared__ float s[32][33];
    int b = blockIdx.z;
    int x0 = blockIdx.x * 32, y0 = blockIdx.y * 32;
    int sl = srcL[b], ml = melL[b];
    const float* vp = val + (size_t)b * 512 * 1024;
    float* op = vt + (size_t)b * 1024 * 512;
    for (int i = threadIdx.y; i < 32; i += 8) {
        int x = x0 + i, y = y0 + threadIdx.x;
        float v = vp[(size_t)x * 1024 + y];
        s[i][threadIdx.x] = (x < sl && y < ml) ? v : 0.f;
    }
    __syncthreads();
    for (int j = threadIdx.y; j < 32; j += 8)
        op[(size_t)(y0 + j) * 512 + x0 + threadIdx.x] = s[threadIdx.x][j];
}

__global__ void k_masdp(const float* __restrict__ vt, const int* __restrict__ srcL,
                        const int* __restrict__ melL, unsigned* __restrict__ dir) {
    __shared__ float bnd[2][16];
    int b = blockIdx.x, x = threadIdx.x;
    int sl = srcL[b], ml = melL[b];
    int lane = x & 31, wid = x >> 5;
    float v = 0.f;
    float val = vt[(size_t)b * 1024 * 512 + x];
    for (int j = 0; j < 1024; ++j) {
        if (lane == 31) bnd[j & 1][wid] = v;
        __syncthreads();
        float v0 = __shfl_up_sync(0xffffffffu, v, 1);
        if (lane == 0) v0 = wid ? bnd[j & 1][wid - 1] : NEGF;
        float valn = 0.f;
        if (j + 1 < 1024) valn = vt[((size_t)b * 1024 + j + 1) * 512 + x];
        bool d = (v >= v0);
        float vmax = d ? v : v0;
        float vnew = (x <= j) ? (vmax + val) : NEGF;
        bool dm = (x < sl && j < ml) ? d : true;
        unsigned bal = __ballot_sync(0xffffffffu, dm);
        if (lane == 0) dir[((size_t)b * 1024 + j) * 16 + wid] = bal;
        v = vnew;
        val = valn;
    }
}

__global__ void k_masbt(const unsigned* __restrict__ dir, const int* __restrict__ srcL,
                        int* __restrict__ idxout) {
    int b = threadIdx.x;
    if (b >= 32) return;
    int idx = srcL[b] - 1;
    for (int y0 = 1023; y0 >= 0; y0 -= 8) {
        int w0 = idx >> 5;
        unsigned wA[8], wB[8];
#pragma unroll
        for (int d = 0; d < 8; ++d) {
            size_t base = ((size_t)b * 1024 + (y0 - d)) * 16;
            wA[d] = dir[base + w0];
            wB[d] = (w0 > 0) ? dir[base + w0 - 1] : 0u;
        }
#pragma unroll
        for (int d = 0; d < 8; ++d) {
            int y = y0 - d;
            idxout[b * 1024 + y] = idx;
            int wcur = idx >> 5;
            unsigned word = (wcur == w0) ? wA[d] : wB[d];
            idx += (int)((word >> (idx & 31)) & 1u) - 1;
        }
    }
}

__global__ void k_expand(const float* __restrict__ X, const int* __restrict__ idx,
                         const int* __restrict__ srcL, const int* __restrict__ melL,
                         float* __restrict__ out) {
    int row = blockIdx.x;
    int b = row >> 10, y = row & 1023;
    int d = threadIdx.x;
    float o = 0.f;
    if (y < melL[b]) {
        int ix = idx[row];
        if (ix >= 0 && ix < srcL[b])
            o = X[((size_t)(b << 9) + ix) * 256 + d];
    }
    out[(size_t)row * 256 + d] = o;
}

// ================= launch =================
extern "C" void kernel_launch(void* const* d_in, const int* in_sizes, int n_in,
                              void* d_out, int out_size) {
    const int* tokens = (const int*)d_in[0];
    const int* srcL   = (const int*)d_in[1];
    const int* melL   = (const int*)d_in[2];
    const float* value = (const float*)d_in[3];
    const float* embed = (const float*)d_in[4];
    const float* pos   = (const float*)d_in[5];
    const float* wq = (const float*)d_in[6];  const float* bq = (const float*)d_in[7];
    const float* wk = (const float*)d_in[8];  const float* bk = (const float*)d_in[9];
    const float* wv = (const float*)d_in[10]; const float* bv = (const float*)d_in[11];
    const float* wo = (const float*)d_in[12]; const float* bo = (const float*)d_in[13];
    const float* ln1g = (const float*)d_in[14]; const float* ln1b = (const float*)d_in[15];
    const float* c1w = (const float*)d_in[16]; const float* c1b = (const float*)d_in[17];
    const float* c2w = (const float*)d_in[18]; const float* c2b = (const float*)d_in[19];
    const float* ln2g = (const float*)d_in[20]; const float* ln2b = (const float*)d_in[21];
    float* out = (float*)d_out;

    float *px, *pt, *ps, *pvt;
    ushort_t *pxh, *pxl, *pqh, *pql, *pkh, *pkl, *pvh, *pvl, *poh, *pol;
    ushort_t *psh, *psl, *phh, *pw1h, *pw2h;
    unsigned *pwqkvh, *pwqkvl, *pwoh, *pwol, *pvph, *pvpl;
    unsigned* pdir; int* pidx;
    cudaGetSymbolAddress((void**)&px, g_x);   cudaGetSymbolAddress((void**)&pt, g_t);
    cudaGetSymbolAddress((void**)&ps, g_s);   cudaGetSymbolAddress((void**)&pvt, g_vt);
    cudaGetSymbolAddress((void**)&pxh, g_xh); cudaGetSymbolAddress((void**)&pxl, g_xl);
    cudaGetSymbolAddress((void**)&pqh, g_qh); cudaGetSymbolAddress((void**)&pql, g_ql);
    cudaGetSymbolAddress((void**)&pkh, g_kh); cudaGetSymbolAddress((void**)&pkl, g_kl);
    cudaGetSymbolAddress((void**)&pvh, g_vh); cudaGetSymbolAddress((void**)&pvl, g_vl);
    cudaGetSymbolAddress((void**)&poh, g_oh); cudaGetSymbolAddress((void**)&pol, g_ol);
    cudaGetSymbolAddress((void**)&psh, g_sh); cudaGetSymbolAddress((void**)&psl, g_sl);
    cudaGetSymbolAddress((void**)&phh, g_hh);
    cudaGetSymbolAddress((void**)&pw1h, g_w1h); cudaGetSymbolAddress((void**)&pw2h, g_w2h);
    cudaGetSymbolAddress((void**)&pwqkvh, g_wqkvh); cudaGetSymbolAddress((void**)&pwqkvl, g_wqkvl);
    cudaGetSymbolAddress((void**)&pwoh, g_woh); cudaGetSymbolAddress((void**)&pwol, g_wol);
    cudaGetSymbolAddress((void**)&pvph, g_vph); cudaGetSymbolAddress((void**)&pvpl, g_vpl);
    cudaGetSymbolAddress((void**)&pdir, g_dir); cudaGetSymbolAddress((void**)&pidx, g_idx);

    const int SMEMC = 40960;
    cudaFuncSetAttribute(k_conv, cudaFuncAttributeMaxDynamicSharedMemorySize, SMEMC);

    dim3 blk256(256);
    // weight prep
    k_wprep<<<18432, blk256>>>(c1w, pw1h, 1024, 256);
    k_wprep<<<18432, blk256>>>(c2w, pw2h, 256, 1024);
    k_packqkv<<<1536, blk256>>>(wq, wk, wv, pwqkvh, pwqkvl);
    k_packsplit<<<512, blk256>>>(wo, pwoh, pwol, 8);
    // inputs
    k_vtrans<<<dim3(16, 32, 32), dim3(32, 8)>>>(value, pvt, srcL, melL);
    k_embed<<<16384, blk256>>>(tokens, embed, pos, px, pxh, pxl);

    for (int l = 0; l < 4; ++l) {
        const unsigned *wqkvh_l = pwqkvh + l * 98304, *wqkvl_l = pwqkvl + l * 98304;
        const unsigned *woh_l = pwoh + l * 32768, *wol_l = pwol + l * 32768;

        k_gemmqkv<<<dim3(6, 128), blk256>>>(pxh, pxl, wqkvh_l, wqkvl_l,
                                            bq + l * 256, bk + l * 256, bv + l * 256,
                                            pqh, pql, pkh, pkl, pvh, pvl);
        k_vpack<<<8192, blk256>>>(pvh, pvl, pvph, pvpl);
        k_scores<<<dim3(4, 4, 64), blk256>>>(pqh, pql, pkh, pkl, ps, srcL);
        k_softmax<<<4096, blk256>>>(ps, psh, psl);
        k_attnout<<<dim3(1, 4, 64), blk256>>>(psh, psl, pvph, pvpl, poh, pol, srcL);
        k_gemm_bias<<<dim3(2, 128), blk256>>>(poh, pol, woh_l, wol_l, bo + l * 256, pt);
        k_lnres<<<2048, blk256>>>(pt, px, ln1g + l * 256, ln1b + l * 256, srcL, px, pxh, pxl);

        k_conv<<<dim3(8, 128), blk256, SMEMC>>>(pxh, pw1h + (size_t)l * 2359296,
                                                c1b + l * 1024, 256, 3, 1, phh, nullptr, 1024);
        k_conv<<<dim3(2, 128), blk256, SMEMC>>>(phh, pw2h + (size_t)l * 2359296,
                                                c2b + l * 256, 1024, 5, 0, nullptr, pt, 256);
        k_lnres<<<2048, blk256>>>(pt, px, ln2g + l * 256, ln2b + l * 256, srcL, px, pxh, pxl);
    }

    k_masdp<<<32, 512>>>(pvt, srcL, melL, pdir);
    k_masbt<<<1, 32>>>(pdir, srcL, pidx);
    k_expand<<<32768, blk256>>>(px, pidx, srcL, melL, out);
}